// round 1
// baseline (speedup 1.0000x reference)
#include <cuda_runtime.h>
#include <math.h>

// Problem constants
#define BB   2
#define NN   2048
#define HIDD 2048
#define NH   16
#define NKV  4
#define DD   128
// derived
#define MQ   (BB*NN)        // 4096
#define DQ   (NH*DD)        // 2048
#define DKV  (NKV*DD)       // 512

// ---------------- device scratch (no allocations allowed) ----------------
__device__ float g_Q [(size_t)MQ * DQ];          // 4096 x 2048
__device__ float g_K [(size_t)MQ * DKV];         // 4096 x 512
__device__ float g_V [(size_t)MQ * DKV];         // 4096 x 512
__device__ float g_S [(size_t)BB * NH * NN * NN];// 2*16*2048*2048 scores
__device__ float g_AO[(size_t)MQ * DQ];          // attention out (b,n,h*d)

// ---------------- generic fp32 SGEMM, 128x128x16, 8x8 microtile ----------
#define BM 128
#define BN 128
#define BKk 16
#define TM 8
#define TN 8

template<bool TRB, bool ACC, bool CSKIP, bool KLIM>
__global__ __launch_bounds__(256)
void gemm_k(const float* __restrict__ Ag, const float* __restrict__ Bg,
            float* __restrict__ Cg,
            int K, int lda, int ldb, int ldc, int HH,
            long sAb, long sAh, long sBb, long sBh, int hshB,
            long sCb, long sCh, float alpha)
{
    const int bx = blockIdx.x, by = blockIdx.y;
    if (CSKIP && bx > by) return;   // tile entirely above causal diagonal

    const int z = blockIdx.z;
    const int b = z / HH;
    const int h = z - b * HH;

    const float* A = Ag + (long)b * sAb + (long)h * sAh;
    const float* Bp = Bg + (long)b * sBb + (long)(h >> hshB) * sBh;
    float*       C  = Cg + (long)b * sCb + (long)h * sCh;

    __shared__ __align__(16) float As[BKk][BM + 4];
    __shared__ __align__(16) float Bs[BKk][BN + 4];

    const int tid = threadIdx.x;
    const int tx = tid & 15, ty = tid >> 4;

    int kend = K;
    if (KLIM) { int ke = (by + 1) * BM; kend = ke < K ? ke : K; }

    float acc[TM][TN];
#pragma unroll
    for (int i = 0; i < TM; i++)
#pragma unroll
        for (int j = 0; j < TN; j++) acc[i][j] = 0.f;

    const int rowA0 = by * BM;

    for (int k0 = 0; k0 < kend; k0 += BKk) {
#pragma unroll
        for (int l = 0; l < 2; l++) {
            int id = tid + l * 256;
            // A tile: 128 rows x 16 cols, store transposed
            {
                int r = id >> 2, c4 = (id & 3) * 4;
                float4 av = *(const float4*)(A + (long)(rowA0 + r) * lda + (k0 + c4));
                As[c4 + 0][r] = av.x; As[c4 + 1][r] = av.y;
                As[c4 + 2][r] = av.z; As[c4 + 3][r] = av.w;
            }
            if (TRB) {
                // B is (N x K) row-major; Bs[kk][j] = B[j][kk]
                int r = id >> 2, c4 = (id & 3) * 4;
                float4 bv = *(const float4*)(Bp + (long)(bx * BN + r) * ldb + (k0 + c4));
                Bs[c4 + 0][r] = bv.x; Bs[c4 + 1][r] = bv.y;
                Bs[c4 + 2][r] = bv.z; Bs[c4 + 3][r] = bv.w;
            } else {
                int br = id >> 5, bc4 = (id & 31) * 4;
                float4 bv = *(const float4*)(Bp + (long)(k0 + br) * ldb + (bx * BN + bc4));
                *(float4*)&Bs[br][bc4] = bv;
            }
        }
        __syncthreads();

#pragma unroll
        for (int kk = 0; kk < BKk; kk++) {
            float a[TM], bb[TN];
#pragma unroll
            for (int i = 0; i < TM; i++) a[i]  = As[kk][ty * TM + i];
#pragma unroll
            for (int j = 0; j < TN; j++) bb[j] = Bs[kk][tx * TN + j];
#pragma unroll
            for (int i = 0; i < TM; i++)
#pragma unroll
                for (int j = 0; j < TN; j++)
                    acc[i][j] += a[i] * bb[j];
        }
        __syncthreads();
    }

    const int row0 = rowA0 + ty * TM;
    const int col0 = bx * BN + tx * TN;
#pragma unroll
    for (int i = 0; i < TM; i++) {
        float* cp = C + (long)(row0 + i) * ldc + col0;
#pragma unroll
        for (int q = 0; q < 2; q++) {
            float4 r;
            r.x = alpha * acc[i][q * 4 + 0];
            r.y = alpha * acc[i][q * 4 + 1];
            r.z = alpha * acc[i][q * 4 + 2];
            r.w = alpha * acc[i][q * 4 + 3];
            if (ACC) {
                float4 o = *(const float4*)(cp + q * 4);
                r.x += o.x; r.y += o.y; r.z += o.z; r.w += o.w;
            }
            *(float4*)(cp + q * 4) = r;
        }
    }
}

// ---------------- causal row softmax over g_S -----------------------------
__global__ __launch_bounds__(128)
void softmax_k(float* __restrict__ S)
{
    const int row = blockIdx.x;          // (b*H+h)*N + n
    const int n = row & (NN - 1);
    float* p = S + (size_t)row * NN;
    const int L = n + 1;
    const int tid = threadIdx.x;

    float v[16];
    int cnt = 0;
    float mx = -3.0e38f;
    for (int j = tid; j < L; j += 128) {
        float x = p[j];
        v[cnt++] = x;
        mx = fmaxf(mx, x);
    }

    __shared__ float red[128];
    red[tid] = mx; __syncthreads();
#pragma unroll
    for (int s = 64; s > 0; s >>= 1) {
        if (tid < s) red[tid] = fmaxf(red[tid], red[tid + s]);
        __syncthreads();
    }
    mx = red[0]; __syncthreads();

    float sum = 0.f;
    for (int i = 0; i < cnt; i++) { v[i] = __expf(v[i] - mx); sum += v[i]; }
    red[tid] = sum; __syncthreads();
#pragma unroll
    for (int s = 64; s > 0; s >>= 1) {
        if (tid < s) red[tid] += red[tid + s];
        __syncthreads();
    }
    const float inv = 1.f / red[0];

    const int kmax = ((n >> 7) + 1) << 7;   // end of diagonal 128-tile
    cnt = 0;
    for (int j = tid; j < kmax; j += 128)
        p[j] = (j < L) ? v[cnt++] * inv : 0.f;
}

// ---------------- GLA recurrence (state shared across GQA group) ----------
// grid (e_tile=4, kvh=4, b=2), 1024 threads.
// warp w owns output column e = e0 + w; lane l owns d in {l, l+32, l+64, l+96}.
__global__ __launch_bounds__(1024)
void fla_k(const float* __restrict__ Q, const float* __restrict__ K,
           const float* __restrict__ V, float* __restrict__ out)
{
    const int et = blockIdx.x, kvh = blockIdx.y, b = blockIdx.z;
    const int e0 = et * 32;
    const int tid = threadIdx.x;
    const int lane = tid & 31;
    const int ew   = tid >> 5;   // e_local 0..31 (= warp id)

    __shared__ __align__(16) float ks[8][128];
    __shared__ __align__(16) float gs[8][128];
    __shared__ __align__(16) float qs[4][8][128];
    __shared__ float vs[8][32];
    __shared__ float os[8][4][32];

    float s0 = 0.f, s1 = 0.f, s2 = 0.f, s3 = 0.f;
    const float CSC = 0.01f * 0.08838834764831845f;  // FLA_WEIGHT / sqrt(D)

    for (int c = 0; c < 256; c++) {
        const int n0 = c * 8;
        // stage q: 4 heads x 8 steps x 128 d = 1024 float4, one per thread
        {
            int hh = tid >> 8, t = (tid >> 5) & 7, d4 = (tid & 31) * 4;
            float4 qv = *(const float4*)(Q + (size_t)(b * NN + n0 + t) * DQ
                                           + (kvh * 4 + hh) * DD + d4);
            *(float4*)&qs[hh][t][d4] = qv;
        }
        if (tid < 256) {
            int t = tid >> 5, d4 = (tid & 31) * 4;
            float4 kv = *(const float4*)(K + (size_t)(b * NN + n0 + t) * DKV
                                           + kvh * DD + d4);
            *(float4*)&ks[t][d4] = kv;
            float4 gv;
            gv.x = 1.f / (1.f + __expf(-kv.x));
            gv.y = 1.f / (1.f + __expf(-kv.y));
            gv.z = 1.f / (1.f + __expf(-kv.z));
            gv.w = 1.f / (1.f + __expf(-kv.w));
            *(float4*)&gs[t][d4] = gv;
        } else if (tid < 512) {
            int u = tid - 256, t = u >> 5, e = u & 31;
            vs[t][e] = V[(size_t)(b * NN + n0 + t) * DKV + kvh * DD + e0 + e];
        }
        __syncthreads();

#pragma unroll
        for (int t = 0; t < 8; t++) {
            const float ve = vs[t][ew];
            const float g0 = gs[t][lane],      g1 = gs[t][lane + 32],
                        g2 = gs[t][lane + 64], g3 = gs[t][lane + 96];
            const float k0 = ks[t][lane],      k1 = ks[t][lane + 32],
                        k2 = ks[t][lane + 64], k3 = ks[t][lane + 96];
            s0 = s0 * g0 + k0 * ve;
            s1 = s1 * g1 + k1 * ve;
            s2 = s2 * g2 + k2 * ve;
            s3 = s3 * g3 + k3 * ve;
#pragma unroll
            for (int hh = 0; hh < 4; hh++) {
                float p = qs[hh][t][lane]      * s0
                        + qs[hh][t][lane + 32] * s1
                        + qs[hh][t][lane + 64] * s2
                        + qs[hh][t][lane + 96] * s3;
                p += __shfl_down_sync(0xffffffffu, p, 16);
                p += __shfl_down_sync(0xffffffffu, p, 8);
                p += __shfl_down_sync(0xffffffffu, p, 4);
                p += __shfl_down_sync(0xffffffffu, p, 2);
                p += __shfl_down_sync(0xffffffffu, p, 1);
                if (lane == 0) os[t][hh][ew] = p;
            }
        }
        __syncthreads();

        // coalesced write: out = FLA_WEIGHT * scale * fla (initializes d_out)
        {
            int t = tid >> 7, hh = (tid >> 5) & 3, e = tid & 31;
            out[(size_t)(b * NN + n0 + t) * HIDD + (kvh * 4 + hh) * DD + e0 + e]
                = CSC * os[t][hh][e];
        }
    }
}

// ---------------- launch ---------------------------------------------------
extern "C" void kernel_launch(void* const* d_in, const int* in_sizes, int n_in,
                              void* d_out, int out_size)
{
    const float* hid = (const float*)d_in[0];
    const float* Wq  = (const float*)d_in[1];
    const float* Wk  = (const float*)d_in[2];
    const float* Wv  = (const float*)d_in[3];
    const float* Wo  = (const float*)d_in[4];
    float* outp = (float*)d_out;

    float *Qp, *Kp, *Vp, *Sp, *AOp;
    cudaGetSymbolAddress((void**)&Qp,  g_Q);
    cudaGetSymbolAddress((void**)&Kp,  g_K);
    cudaGetSymbolAddress((void**)&Vp,  g_V);
    cudaGetSymbolAddress((void**)&Sp,  g_S);
    cudaGetSymbolAddress((void**)&AOp, g_AO);

    const float scale = 0.08838834764831845f; // 1/sqrt(128)

    // 1..3: projections  (C = hidden @ W)
    gemm_k<false,false,false,false><<<dim3(DQ/BN,  MQ/BM, 1), 256>>>(
        hid, Wq, Qp, HIDD, HIDD, DQ,  DQ,  1, 0,0, 0,0, 0, 0,0, 1.f);
    gemm_k<false,false,false,false><<<dim3(DKV/BN, MQ/BM, 1), 256>>>(
        hid, Wk, Kp, HIDD, HIDD, DKV, DKV, 1, 0,0, 0,0, 0, 0,0, 1.f);
    gemm_k<false,false,false,false><<<dim3(DKV/BN, MQ/BM, 1), 256>>>(
        hid, Wv, Vp, HIDD, HIDD, DKV, DKV, 1, 0,0, 0,0, 0, 0,0, 1.f);

    // 4: FLA branch -> initializes d_out with 0.01*scale*fla
    fla_k<<<dim3(4, NKV, BB), 1024>>>(Qp, Kp, Vp, outp);

    // 5: scores  S = scale * Q @ K^T  (batched over b,h; skip above-diag tiles)
    gemm_k<true,false,true,false><<<dim3(NN/BN, NN/BM, BB*NH), 256>>>(
        Qp, Kp, Sp, DD, DQ, DKV, NN, NH,
        (long)NN*DQ, (long)DD,
        (long)NN*DKV, (long)DD, 2,
        (long)NH*NN*NN, (long)NN*NN, scale);

    // 6: causal softmax
    softmax_k<<<BB*NH*NN, 128>>>(Sp);

    // 7: PV  AO = P @ V  (K-loop limited to causal range)
    gemm_k<false,false,false,true><<<dim3(1, NN/BM, BB*NH), 256>>>(
        Sp, Vp, AOp, NN, NN, DKV, DQ, NH,
        (long)NH*NN*NN, (long)NN*NN,
        (long)NN*DKV, (long)DD, 2,
        (long)NN*DQ, (long)DD, 1.f);

    // 8: output projection, accumulate onto FLA contribution in d_out
    gemm_k<false,true,false,false><<<dim3(HIDD/BN, MQ/BM, 1), 256>>>(
        AOp, Wo, outp, DQ, DQ, HIDD, HIDD, 1, 0,0, 0,0, 0, 0,0, 1.f);
}

// round 2
// speedup vs baseline: 1.5106x; 1.5106x over previous
#include <cuda_runtime.h>
#include <math.h>
#include <stdint.h>

// Problem constants
#define BB   2
#define NN   2048
#define HIDD 2048
#define NH   16
#define NKV  4
#define DD   128
// derived
#define MQ   (BB*NN)        // 4096
#define DQ   (NH*DD)        // 2048
#define DKV  (NKV*DD)       // 512

// ---------------- device scratch (no allocations allowed) ----------------
__device__ float g_Q [(size_t)MQ * DQ];          // 4096 x 2048
__device__ float g_K [(size_t)MQ * DKV];         // 4096 x 512
__device__ float g_V [(size_t)MQ * DKV];         // 4096 x 512
__device__ float g_S [(size_t)BB * NH * NN * NN];// scores
__device__ float g_AO[(size_t)MQ * DQ];          // attention out (b,n,h*d)

// ---------------- tf32 tensor-core GEMM, 128x128x16, 8 warps -------------
#define BM 128
#define BN 128
#define BKk 16
#define AKP 20      // k-major row pitch (words) for A / transposed-B tiles
#define BNP 136     // n-major row pitch (words) for B tiles

__device__ __forceinline__ uint32_t f2tf(float f) {
    uint32_t u;
    asm("cvt.rna.tf32.f32 %0, %1;" : "=r"(u) : "f"(f));
    return u;
}

__device__ __forceinline__ void mma_tf32(float* c, const uint32_t* a, const uint32_t* b) {
    asm volatile(
        "mma.sync.aligned.m16n8k8.row.col.f32.tf32.tf32.f32 "
        "{%0,%1,%2,%3}, {%4,%5,%6,%7}, {%8,%9}, {%0,%1,%2,%3};\n"
        : "+f"(c[0]), "+f"(c[1]), "+f"(c[2]), "+f"(c[3])
        : "r"(a[0]), "r"(a[1]), "r"(a[2]), "r"(a[3]),
          "r"(b[0]), "r"(b[1]));
}

template<bool TRB, bool ACC, bool CSKIP, bool KLIM>
__global__ __launch_bounds__(256)
void gemm_k(const float* __restrict__ Ag, const float* __restrict__ Bg,
            float* __restrict__ Cg,
            int K, int lda, int ldb, int ldc, int HH,
            long sAb, long sAh, long sBb, long sBh, int hshB,
            long sCb, long sCh, float alpha)
{
    const int bx = blockIdx.x, by = blockIdx.y;
    if (CSKIP && bx > by) return;   // tile entirely above causal diagonal

    const int z = blockIdx.z;
    const int b = z / HH;
    const int h = z - b * HH;

    const float* A  = Ag + (long)b * sAb + (long)h * sAh;
    const float* Bp = Bg + (long)b * sBb + (long)(h >> hshB) * sBh;
    float*       C  = Cg + (long)b * sCb + (long)h * sCh;

    __shared__ __align__(16) uint32_t As[BM * AKP];
    __shared__ __align__(16) uint32_t Bsm[TRB ? (BN * AKP) : (BKk * BNP)];

    const int tid  = threadIdx.x;
    const int lane = tid & 31;
    const int wid  = tid >> 5;
    const int wm   = wid >> 2;        // 0..1
    const int wn   = wid & 3;         // 0..3
    const int gr   = lane >> 2;       // 0..7
    const int gc   = lane & 3;        // 0..3

    int kend = K;
    if (KLIM) { int ke = (by + 1) * BM; kend = ke < K ? ke : K; }

    float acc[16][4];
#pragma unroll
    for (int i = 0; i < 16; i++)
#pragma unroll
        for (int j = 0; j < 4; j++) acc[i][j] = 0.f;

    const int rowA0 = by * BM;

    for (int k0 = 0; k0 < kend; k0 += BKk) {
#pragma unroll
        for (int l = 0; l < 2; l++) {
            int id = tid + l * 256;
            {   // A tile: 128 rows x 16 k, k-major rows
                int r = id >> 2, c4 = (id & 3) * 4;
                float4 av = *(const float4*)(A + (long)(rowA0 + r) * lda + (k0 + c4));
                uint4 at = make_uint4(f2tf(av.x), f2tf(av.y), f2tf(av.z), f2tf(av.w));
                *(uint4*)&As[r * AKP + c4] = at;
            }
            if (TRB) {
                // B is (N x K) row-major; stage as n-rows of k-contiguous tf32
                int r = id >> 2, c4 = (id & 3) * 4;
                float4 bv = *(const float4*)(Bp + (long)(bx * BN + r) * ldb + (k0 + c4));
                uint4 bt = make_uint4(f2tf(bv.x), f2tf(bv.y), f2tf(bv.z), f2tf(bv.w));
                *(uint4*)&Bsm[r * AKP + c4] = bt;
            } else {
                // B is (K x N) row-major; stage as k-rows of n-contiguous tf32
                int br = id >> 5, bc4 = (id & 31) * 4;
                float4 bv = *(const float4*)(Bp + (long)(k0 + br) * ldb + (bx * BN + bc4));
                uint4 bt = make_uint4(f2tf(bv.x), f2tf(bv.y), f2tf(bv.z), f2tf(bv.w));
                *(uint4*)&Bsm[br * BNP + bc4] = bt;
            }
        }
        __syncthreads();

#pragma unroll
        for (int ks = 0; ks < BKk; ks += 8) {
            uint32_t a[4][4], bf[4][2];
#pragma unroll
            for (int mt = 0; mt < 4; mt++) {
                int m = wm * 64 + mt * 16 + gr;
                a[mt][0] = As[m * AKP + ks + gc];
                a[mt][1] = As[(m + 8) * AKP + ks + gc];
                a[mt][2] = As[m * AKP + ks + gc + 4];
                a[mt][3] = As[(m + 8) * AKP + ks + gc + 4];
            }
#pragma unroll
            for (int nt = 0; nt < 4; nt++) {
                int n = wn * 32 + nt * 8 + gr;
                if (TRB) {
                    bf[nt][0] = Bsm[n * AKP + ks + gc];
                    bf[nt][1] = Bsm[n * AKP + ks + gc + 4];
                } else {
                    bf[nt][0] = Bsm[(ks + gc) * BNP + n];
                    bf[nt][1] = Bsm[(ks + gc + 4) * BNP + n];
                }
            }
#pragma unroll
            for (int mt = 0; mt < 4; mt++)
#pragma unroll
                for (int nt = 0; nt < 4; nt++)
                    mma_tf32(acc[mt * 4 + nt], a[mt], bf[nt]);
        }
        __syncthreads();
    }

    // epilogue
#pragma unroll
    for (int mt = 0; mt < 4; mt++) {
        int row = rowA0 + wm * 64 + mt * 16 + gr;
#pragma unroll
        for (int nt = 0; nt < 4; nt++) {
            int col = bx * BN + wn * 32 + nt * 8 + gc * 2;
            float* cp0 = C + (long)row * ldc + col;
            float* cp1 = C + (long)(row + 8) * ldc + col;
            const float* ac = acc[mt * 4 + nt];
            float2 r0 = make_float2(alpha * ac[0], alpha * ac[1]);
            float2 r1 = make_float2(alpha * ac[2], alpha * ac[3]);
            if (ACC) {
                float2 o0 = *(const float2*)cp0;
                float2 o1 = *(const float2*)cp1;
                r0.x += o0.x; r0.y += o0.y;
                r1.x += o1.x; r1.y += o1.y;
            }
            *(float2*)cp0 = r0;
            *(float2*)cp1 = r1;
        }
    }
}

// ---------------- causal row softmax over g_S -----------------------------
__global__ __launch_bounds__(128)
void softmax_k(float* __restrict__ S)
{
    const int row = blockIdx.x;          // (b*H+h)*N + n
    const int n = row & (NN - 1);
    float* p = S + (size_t)row * NN;
    const int L = n + 1;
    const int tid = threadIdx.x;

    float v[16];
    int cnt = 0;
    float mx = -3.0e38f;
    for (int j = tid; j < L; j += 128) {
        float x = p[j];
        v[cnt++] = x;
        mx = fmaxf(mx, x);
    }

    __shared__ float red[128];
    red[tid] = mx; __syncthreads();
#pragma unroll
    for (int s = 64; s > 0; s >>= 1) {
        if (tid < s) red[tid] = fmaxf(red[tid], red[tid + s]);
        __syncthreads();
    }
    mx = red[0]; __syncthreads();

    float sum = 0.f;
    for (int i = 0; i < cnt; i++) { v[i] = __expf(v[i] - mx); sum += v[i]; }
    red[tid] = sum; __syncthreads();
#pragma unroll
    for (int s = 64; s > 0; s >>= 1) {
        if (tid < s) red[tid] += red[tid + s];
        __syncthreads();
    }
    const float inv = 1.f / red[0];

    const int kmax = ((n >> 7) + 1) << 7;   // end of diagonal 128-tile
    cnt = 0;
    for (int j = tid; j < kmax; j += 128)
        p[j] = (j < L) ? v[cnt++] * inv : 0.f;
}

// ---------------- GLA recurrence (state shared across GQA group) ----------
__global__ __launch_bounds__(1024)
void fla_k(const float* __restrict__ Q, const float* __restrict__ K,
           const float* __restrict__ V, float* __restrict__ out)
{
    const int et = blockIdx.x, kvh = blockIdx.y, b = blockIdx.z;
    const int e0 = et * 32;
    const int tid = threadIdx.x;
    const int lane = tid & 31;
    const int ew   = tid >> 5;   // e_local 0..31 (= warp id)

    __shared__ __align__(16) float ks[8][128];
    __shared__ __align__(16) float gs[8][128];
    __shared__ __align__(16) float qs[4][8][128];
    __shared__ float vs[8][32];
    __shared__ float os[8][4][32];

    float s0 = 0.f, s1 = 0.f, s2 = 0.f, s3 = 0.f;
    const float CSC = 0.01f * 0.08838834764831845f;  // FLA_WEIGHT / sqrt(D)

    for (int c = 0; c < 256; c++) {
        const int n0 = c * 8;
        {
            int hh = tid >> 8, t = (tid >> 5) & 7, d4 = (tid & 31) * 4;
            float4 qv = *(const float4*)(Q + (size_t)(b * NN + n0 + t) * DQ
                                           + (kvh * 4 + hh) * DD + d4);
            *(float4*)&qs[hh][t][d4] = qv;
        }
        if (tid < 256) {
            int t = tid >> 5, d4 = (tid & 31) * 4;
            float4 kv = *(const float4*)(K + (size_t)(b * NN + n0 + t) * DKV
                                           + kvh * DD + d4);
            *(float4*)&ks[t][d4] = kv;
            float4 gv;
            gv.x = 1.f / (1.f + __expf(-kv.x));
            gv.y = 1.f / (1.f + __expf(-kv.y));
            gv.z = 1.f / (1.f + __expf(-kv.z));
            gv.w = 1.f / (1.f + __expf(-kv.w));
            *(float4*)&gs[t][d4] = gv;
        } else if (tid < 512) {
            int u = tid - 256, t = u >> 5, e = u & 31;
            vs[t][e] = V[(size_t)(b * NN + n0 + t) * DKV + kvh * DD + e0 + e];
        }
        __syncthreads();

#pragma unroll
        for (int t = 0; t < 8; t++) {
            const float ve = vs[t][ew];
            const float g0 = gs[t][lane],      g1 = gs[t][lane + 32],
                        g2 = gs[t][lane + 64], g3 = gs[t][lane + 96];
            const float k0 = ks[t][lane],      k1 = ks[t][lane + 32],
                        k2 = ks[t][lane + 64], k3 = ks[t][lane + 96];
            s0 = s0 * g0 + k0 * ve;
            s1 = s1 * g1 + k1 * ve;
            s2 = s2 * g2 + k2 * ve;
            s3 = s3 * g3 + k3 * ve;
#pragma unroll
            for (int hh = 0; hh < 4; hh++) {
                float p = qs[hh][t][lane]      * s0
                        + qs[hh][t][lane + 32] * s1
                        + qs[hh][t][lane + 64] * s2
                        + qs[hh][t][lane + 96] * s3;
                p += __shfl_down_sync(0xffffffffu, p, 16);
                p += __shfl_down_sync(0xffffffffu, p, 8);
                p += __shfl_down_sync(0xffffffffu, p, 4);
                p += __shfl_down_sync(0xffffffffu, p, 2);
                p += __shfl_down_sync(0xffffffffu, p, 1);
                if (lane == 0) os[t][hh][ew] = p;
            }
        }
        __syncthreads();

        {
            int t = tid >> 7, hh = (tid >> 5) & 3, e = tid & 31;
            out[(size_t)(b * NN + n0 + t) * HIDD + (kvh * 4 + hh) * DD + e0 + e]
                = CSC * os[t][hh][e];
        }
    }
}

// ---------------- launch ---------------------------------------------------
extern "C" void kernel_launch(void* const* d_in, const int* in_sizes, int n_in,
                              void* d_out, int out_size)
{
    const float* hid = (const float*)d_in[0];
    const float* Wq  = (const float*)d_in[1];
    const float* Wk  = (const float*)d_in[2];
    const float* Wv  = (const float*)d_in[3];
    const float* Wo  = (const float*)d_in[4];
    float* outp = (float*)d_out;

    float *Qp, *Kp, *Vp, *Sp, *AOp;
    cudaGetSymbolAddress((void**)&Qp,  g_Q);
    cudaGetSymbolAddress((void**)&Kp,  g_K);
    cudaGetSymbolAddress((void**)&Vp,  g_V);
    cudaGetSymbolAddress((void**)&Sp,  g_S);
    cudaGetSymbolAddress((void**)&AOp, g_AO);

    const float scale = 0.08838834764831845f; // 1/sqrt(128)

    // 1..3: projections  (C = hidden @ W)
    gemm_k<false,false,false,false><<<dim3(DQ/BN,  MQ/BM, 1), 256>>>(
        hid, Wq, Qp, HIDD, HIDD, DQ,  DQ,  1, 0,0, 0,0, 0, 0,0, 1.f);
    gemm_k<false,false,false,false><<<dim3(DKV/BN, MQ/BM, 1), 256>>>(
        hid, Wk, Kp, HIDD, HIDD, DKV, DKV, 1, 0,0, 0,0, 0, 0,0, 1.f);
    gemm_k<false,false,false,false><<<dim3(DKV/BN, MQ/BM, 1), 256>>>(
        hid, Wv, Vp, HIDD, HIDD, DKV, DKV, 1, 0,0, 0,0, 0, 0,0, 1.f);

    // 4: FLA branch -> initializes d_out with 0.01*scale*fla
    fla_k<<<dim3(4, NKV, BB), 1024>>>(Qp, Kp, Vp, outp);

    // 5: scores  S = scale * Q @ K^T  (batched over b,h; skip above-diag tiles)
    gemm_k<true,false,true,false><<<dim3(NN/BN, NN/BM, BB*NH), 256>>>(
        Qp, Kp, Sp, DD, DQ, DKV, NN, NH,
        (long)NN*DQ, (long)DD,
        (long)NN*DKV, (long)DD, 2,
        (long)NH*NN*NN, (long)NN*NN, scale);

    // 6: causal softmax
    softmax_k<<<BB*NH*NN, 128>>>(Sp);

    // 7: PV  AO = P @ V  (K-loop limited to causal range)
    gemm_k<false,false,false,true><<<dim3(1, NN/BM, BB*NH), 256>>>(
        Sp, Vp, AOp, NN, NN, DKV, DQ, NH,
        (long)NH*NN*NN, (long)NN*NN,
        (long)NN*DKV, (long)DD, 2,
        (long)NN*DQ, (long)DD, 1.f);

    // 8: output projection, accumulate onto FLA contribution in d_out
    gemm_k<false,true,false,false><<<dim3(HIDD/BN, MQ/BM, 1), 256>>>(
        AOp, Wo, outp, DQ, DQ, HIDD, HIDD, 1, 0,0, 0,0, 0, 0,0, 1.f);
}

// round 3
// speedup vs baseline: 1.6386x; 1.0847x over previous
#include <cuda_runtime.h>
#include <math.h>
#include <stdint.h>

// Problem constants
#define BB   2
#define NN   2048
#define HIDD 2048
#define NH   16
#define NKV  4
#define DD   128
// derived
#define MQ   (BB*NN)        // 4096
#define DQ   (NH*DD)        // 2048
#define DKV  (NKV*DD)       // 512

// ---------------- device scratch (no allocations allowed) ----------------
__device__ float g_Q [(size_t)MQ * DQ];          // 4096 x 2048
__device__ float g_K [(size_t)MQ * DKV];         // 4096 x 512
__device__ float g_V [(size_t)MQ * DKV];         // 4096 x 512
__device__ float g_AO[(size_t)MQ * DQ];          // attention out (b,n,h*d)

// ---------------- tf32 helpers -------------------------------------------
__device__ __forceinline__ uint32_t f2tf(float f) {
    uint32_t u;
    asm("cvt.rna.tf32.f32 %0, %1;" : "=r"(u) : "f"(f));
    return u;
}

__device__ __forceinline__ void mma_tf32(float* c, const uint32_t* a, const uint32_t* b) {
    asm volatile(
        "mma.sync.aligned.m16n8k8.row.col.f32.tf32.tf32.f32 "
        "{%0,%1,%2,%3}, {%4,%5,%6,%7}, {%8,%9}, {%0,%1,%2,%3};\n"
        : "+f"(c[0]), "+f"(c[1]), "+f"(c[2]), "+f"(c[3])
        : "r"(a[0]), "r"(a[1]), "r"(a[2]), "r"(a[3]),
          "r"(b[0]), "r"(b[1]));
}

// ---------------- tf32 tensor-core GEMM, 128x128x16, 8 warps -------------
#define BM 128
#define BN 128
#define BKk 16
#define AKP 20      // k-major row pitch (words)
#define BNP 136     // n-major row pitch (words)

template<bool ACC>
__global__ __launch_bounds__(256)
void gemm_k(const float* __restrict__ Ag, const float* __restrict__ Bg,
            float* __restrict__ Cg, int K, int lda, int ldb, int ldc,
            float alpha)
{
    const int bx = blockIdx.x, by = blockIdx.y;

    __shared__ __align__(16) uint32_t As[BM * AKP];
    __shared__ __align__(16) uint32_t Bsm[BKk * BNP];

    const int tid  = threadIdx.x;
    const int lane = tid & 31;
    const int wid  = tid >> 5;
    const int wm   = wid >> 2;        // 0..1
    const int wn   = wid & 3;         // 0..3
    const int gr   = lane >> 2;       // 0..7
    const int gc   = lane & 3;        // 0..3

    float acc[16][4];
#pragma unroll
    for (int i = 0; i < 16; i++)
#pragma unroll
        for (int j = 0; j < 4; j++) acc[i][j] = 0.f;

    const int rowA0 = by * BM;

    for (int k0 = 0; k0 < K; k0 += BKk) {
#pragma unroll
        for (int l = 0; l < 2; l++) {
            int id = tid + l * 256;
            {   // A tile: 128 rows x 16 k
                int r = id >> 2, c4 = (id & 3) * 4;
                float4 av = *(const float4*)(Ag + (long)(rowA0 + r) * lda + (k0 + c4));
                uint4 at = make_uint4(f2tf(av.x), f2tf(av.y), f2tf(av.z), f2tf(av.w));
                *(uint4*)&As[r * AKP + c4] = at;
            }
            {   // B tile: 16 k x 128 n
                int br = id >> 5, bc4 = (id & 31) * 4;
                float4 bv = *(const float4*)(Bg + (long)(k0 + br) * ldb + (bx * BN + bc4));
                uint4 bt = make_uint4(f2tf(bv.x), f2tf(bv.y), f2tf(bv.z), f2tf(bv.w));
                *(uint4*)&Bsm[br * BNP + bc4] = bt;
            }
        }
        __syncthreads();

#pragma unroll
        for (int ks = 0; ks < BKk; ks += 8) {
            uint32_t a[4][4], bf[4][2];
#pragma unroll
            for (int mt = 0; mt < 4; mt++) {
                int m = wm * 64 + mt * 16 + gr;
                a[mt][0] = As[m * AKP + ks + gc];
                a[mt][1] = As[(m + 8) * AKP + ks + gc];
                a[mt][2] = As[m * AKP + ks + gc + 4];
                a[mt][3] = As[(m + 8) * AKP + ks + gc + 4];
            }
#pragma unroll
            for (int nt = 0; nt < 4; nt++) {
                int n = wn * 32 + nt * 8 + gr;
                bf[nt][0] = Bsm[(ks + gc) * BNP + n];
                bf[nt][1] = Bsm[(ks + gc + 4) * BNP + n];
            }
#pragma unroll
            for (int mt = 0; mt < 4; mt++)
#pragma unroll
                for (int nt = 0; nt < 4; nt++)
                    mma_tf32(acc[mt * 4 + nt], a[mt], bf[nt]);
        }
        __syncthreads();
    }

#pragma unroll
    for (int mt = 0; mt < 4; mt++) {
        int row = rowA0 + wm * 64 + mt * 16 + gr;
#pragma unroll
        for (int nt = 0; nt < 4; nt++) {
            int col = bx * BN + wn * 32 + nt * 8 + gc * 2;
            float* cp0 = Cg + (long)row * ldc + col;
            float* cp1 = Cg + (long)(row + 8) * ldc + col;
            const float* ac = acc[mt * 4 + nt];
            float2 r0 = make_float2(alpha * ac[0], alpha * ac[1]);
            float2 r1 = make_float2(alpha * ac[2], alpha * ac[3]);
            if (ACC) {
                float2 o0 = *(const float2*)cp0;
                float2 o1 = *(const float2*)cp1;
                r0.x += o0.x; r0.y += o0.y;
                r1.x += o1.x; r1.y += o1.y;
            }
            *(float2*)cp0 = r0;
            *(float2*)cp1 = r1;
        }
    }
}

// ---------------- fused flash attention (tf32 MMA, online softmax) --------
#define FQT 128
#define FKT 64
#define QP  132
#define KP  132
#define VP  136
#define PP  68

struct FlashSmem {
    uint32_t Qs[FQT * QP];
    uint32_t Ks[FKT * KP];
    uint32_t Vs[FKT * VP];
    uint32_t Ps[FQT * PP];
    float red_m[4][FQT];
    float red_l[4][FQT];
    float sm_m[FQT];
    float sm_l[FQT];
};

__global__ __launch_bounds__(256, 1)
void flash_k(const float* __restrict__ Q, const float* __restrict__ K,
             const float* __restrict__ V, float* __restrict__ AO)
{
    extern __shared__ char smbuf[];
    FlashSmem* sm = (FlashSmem*)smbuf;

    const int bh = blockIdx.x;          // 0..31
    const int b  = bh >> 4, h = bh & 15;
    const int kvh = h >> 2;
    const int qi = 15 - blockIdx.y;     // big tiles first

    const int tid  = threadIdx.x;
    const int lane = tid & 31;
    const int wid  = tid >> 5;
    const int wm   = wid >> 2;          // 0..1
    const int wn   = wid & 3;           // 0..3
    const int gr   = lane >> 2;         // 0..7
    const int gc   = lane & 3;          // 0..3

    // stage Q (fold scale * log2e)
    const float SC = 0.08838834764831845f * 1.4426950408889634f;
#pragma unroll
    for (int it = 0; it < 16; it++) {
        int id = tid + it * 256;
        int r = id >> 5, d4 = (id & 31) * 4;
        float4 qv = *(const float4*)(Q + (size_t)(b * NN + qi * 128 + r) * DQ + h * DD + d4);
        uint4 qt = make_uint4(f2tf(qv.x * SC), f2tf(qv.y * SC),
                              f2tf(qv.z * SC), f2tf(qv.w * SC));
        *(uint4*)&sm->Qs[r * QP + d4] = qt;
    }
    if (tid < FQT) { sm->sm_m[tid] = -1e30f; sm->sm_l[tid] = 0.f; }

    float acc_o[16][4];
#pragma unroll
    for (int i = 0; i < 16; i++)
#pragma unroll
        for (int j = 0; j < 4; j++) acc_o[i][j] = 0.f;

    const int nkv = 2 * qi + 2;
    for (int j = 0; j < nkv; j++) {
        __syncthreads();    // prior PV / P reads done; Q staged (first iter)
        // stage K (n-major, k contiguous) and V (k-major, n contiguous)
#pragma unroll
        for (int it = 0; it < 8; it++) {
            int id = tid + it * 256;
            int r = id >> 5, d4 = (id & 31) * 4;
            size_t goff = (size_t)(b * NN + j * FKT + r) * DKV + kvh * DD + d4;
            float4 kv = *(const float4*)(K + goff);
            uint4 kt = make_uint4(f2tf(kv.x), f2tf(kv.y), f2tf(kv.z), f2tf(kv.w));
            *(uint4*)&sm->Ks[r * KP + d4] = kt;
            float4 vv = *(const float4*)(V + goff);
            uint4 vt = make_uint4(f2tf(vv.x), f2tf(vv.y), f2tf(vv.z), f2tf(vv.w));
            *(uint4*)&sm->Vs[r * VP + d4] = vt;
        }
        __syncthreads();

        // S = Qs @ Ks^T  (warp tile 64x16)
        float acc_s[8][4];
#pragma unroll
        for (int i = 0; i < 8; i++)
#pragma unroll
            for (int c = 0; c < 4; c++) acc_s[i][c] = 0.f;

#pragma unroll
        for (int ks = 0; ks < DD; ks += 8) {
            uint32_t a[4][4], bfr[2][2];
#pragma unroll
            for (int mt = 0; mt < 4; mt++) {
                int m = wm * 64 + mt * 16 + gr;
                a[mt][0] = sm->Qs[m * QP + ks + gc];
                a[mt][1] = sm->Qs[(m + 8) * QP + ks + gc];
                a[mt][2] = sm->Qs[m * QP + ks + gc + 4];
                a[mt][3] = sm->Qs[(m + 8) * QP + ks + gc + 4];
            }
#pragma unroll
            for (int nt = 0; nt < 2; nt++) {
                int n = wn * 16 + nt * 8 + gr;
                bfr[nt][0] = sm->Ks[n * KP + ks + gc];
                bfr[nt][1] = sm->Ks[n * KP + ks + gc + 4];
            }
#pragma unroll
            for (int mt = 0; mt < 4; mt++)
#pragma unroll
                for (int nt = 0; nt < 2; nt++)
                    mma_tf32(acc_s[mt * 2 + nt], a[mt], bfr[nt]);
        }

        // causal mask (only meaningful for the diagonal tiles)
        if ((j + 1) * FKT - 1 > qi * 128) {
#pragma unroll
            for (int mt = 0; mt < 4; mt++)
#pragma unroll
                for (int nt = 0; nt < 2; nt++)
#pragma unroll
                    for (int c = 0; c < 4; c++) {
                        int rowg = qi * 128 + wm * 64 + mt * 16 + gr + (c >> 1) * 8;
                        int colg = j * FKT + wn * 16 + nt * 8 + 2 * gc + (c & 1);
                        if (colg > rowg) acc_s[mt * 2 + nt][c] = -1e30f;
                    }
        }

        // row-max partials
#pragma unroll
        for (int mt = 0; mt < 4; mt++)
#pragma unroll
            for (int hh = 0; hh < 2; hh++) {
                float rmax = fmaxf(fmaxf(acc_s[mt * 2 + 0][hh * 2], acc_s[mt * 2 + 0][hh * 2 + 1]),
                                   fmaxf(acc_s[mt * 2 + 1][hh * 2], acc_s[mt * 2 + 1][hh * 2 + 1]));
                rmax = fmaxf(rmax, __shfl_xor_sync(0xffffffffu, rmax, 1));
                rmax = fmaxf(rmax, __shfl_xor_sync(0xffffffffu, rmax, 2));
                if (gc == 0)
                    sm->red_m[wn][wm * 64 + mt * 16 + gr + hh * 8] = rmax;
            }
        __syncthreads();

        // softmax phase: p = exp2(s - m_new), rescale acc_o, stage P
#pragma unroll
        for (int mt = 0; mt < 4; mt++)
#pragma unroll
            for (int hh = 0; hh < 2; hh++) {
                int rl = wm * 64 + mt * 16 + gr + hh * 8;
                float m_old = sm->sm_m[rl];
                float m_new = fmaxf(fmaxf(sm->red_m[0][rl], sm->red_m[1][rl]),
                                    fmaxf(sm->red_m[2][rl], sm->red_m[3][rl]));
                m_new = fmaxf(m_old, m_new);
                float alpha = exp2f(m_old - m_new);
#pragma unroll
                for (int nt = 0; nt < 4; nt++) {
                    acc_o[mt * 4 + nt][hh * 2]     *= alpha;
                    acc_o[mt * 4 + nt][hh * 2 + 1] *= alpha;
                }
                float psum = 0.f;
#pragma unroll
                for (int nt = 0; nt < 2; nt++) {
                    float p0 = exp2f(acc_s[mt * 2 + nt][hh * 2]     - m_new);
                    float p1 = exp2f(acc_s[mt * 2 + nt][hh * 2 + 1] - m_new);
                    psum += p0 + p1;
                    uint2 pt = make_uint2(f2tf(p0), f2tf(p1));
                    *(uint2*)&sm->Ps[rl * PP + wn * 16 + nt * 8 + 2 * gc] = pt;
                }
                psum += __shfl_xor_sync(0xffffffffu, psum, 1);
                psum += __shfl_xor_sync(0xffffffffu, psum, 2);
                if (gc == 0) sm->red_l[wn][rl] = psum;
            }
        __syncthreads();

        // stats update (one thread per row)
        if (tid < FQT) {
            int rl = tid;
            float m_old = sm->sm_m[rl];
            float m_new = fmaxf(fmaxf(sm->red_m[0][rl], sm->red_m[1][rl]),
                                fmaxf(sm->red_m[2][rl], sm->red_m[3][rl]));
            m_new = fmaxf(m_old, m_new);
            float alpha = exp2f(m_old - m_new);
            sm->sm_l[rl] = sm->sm_l[rl] * alpha
                         + sm->red_l[0][rl] + sm->red_l[1][rl]
                         + sm->red_l[2][rl] + sm->red_l[3][rl];
            sm->sm_m[rl] = m_new;
        }

        // PV: acc_o += Ps @ Vs  (warp tile 64x32, k = 64)
#pragma unroll
        for (int ks = 0; ks < FKT; ks += 8) {
            uint32_t pa[4][4], vb[4][2];
#pragma unroll
            for (int mt = 0; mt < 4; mt++) {
                int m = wm * 64 + mt * 16 + gr;
                pa[mt][0] = sm->Ps[m * PP + ks + gc];
                pa[mt][1] = sm->Ps[(m + 8) * PP + ks + gc];
                pa[mt][2] = sm->Ps[m * PP + ks + gc + 4];
                pa[mt][3] = sm->Ps[(m + 8) * PP + ks + gc + 4];
            }
#pragma unroll
            for (int nt = 0; nt < 4; nt++) {
                int n = wn * 32 + nt * 8 + gr;
                vb[nt][0] = sm->Vs[(ks + gc) * VP + n];
                vb[nt][1] = sm->Vs[(ks + gc + 4) * VP + n];
            }
#pragma unroll
            for (int mt = 0; mt < 4; mt++)
#pragma unroll
                for (int nt = 0; nt < 4; nt++)
                    mma_tf32(acc_o[mt * 4 + nt], pa[mt], vb[nt]);
        }
    }

    __syncthreads();   // sm_l final

    // epilogue: O = acc_o / l
#pragma unroll
    for (int mt = 0; mt < 4; mt++)
#pragma unroll
        for (int hh = 0; hh < 2; hh++) {
            int rl = wm * 64 + mt * 16 + gr + hh * 8;
            float inv = 1.f / sm->sm_l[rl];
            int gq = qi * 128 + rl;
#pragma unroll
            for (int nt = 0; nt < 4; nt++) {
                int col = wn * 32 + nt * 8 + 2 * gc;
                float2 r = make_float2(acc_o[mt * 4 + nt][hh * 2] * inv,
                                       acc_o[mt * 4 + nt][hh * 2 + 1] * inv);
                *(float2*)(AO + (size_t)(b * NN + gq) * DQ + h * DD + col) = r;
            }
        }
}

// ---------------- GLA recurrence (unchanged) ------------------------------
__global__ __launch_bounds__(1024)
void fla_k(const float* __restrict__ Q, const float* __restrict__ K,
           const float* __restrict__ V, float* __restrict__ out)
{
    const int et = blockIdx.x, kvh = blockIdx.y, b = blockIdx.z;
    const int e0 = et * 32;
    const int tid = threadIdx.x;
    const int lane = tid & 31;
    const int ew   = tid >> 5;

    __shared__ __align__(16) float ks[8][128];
    __shared__ __align__(16) float gs[8][128];
    __shared__ __align__(16) float qs[4][8][128];
    __shared__ float vs[8][32];
    __shared__ float os[8][4][32];

    float s0 = 0.f, s1 = 0.f, s2 = 0.f, s3 = 0.f;
    const float CSC = 0.01f * 0.08838834764831845f;

    for (int c = 0; c < 256; c++) {
        const int n0 = c * 8;
        {
            int hh = tid >> 8, t = (tid >> 5) & 7, d4 = (tid & 31) * 4;
            float4 qv = *(const float4*)(Q + (size_t)(b * NN + n0 + t) * DQ
                                           + (kvh * 4 + hh) * DD + d4);
            *(float4*)&qs[hh][t][d4] = qv;
        }
        if (tid < 256) {
            int t = tid >> 5, d4 = (tid & 31) * 4;
            float4 kv = *(const float4*)(K + (size_t)(b * NN + n0 + t) * DKV
                                           + kvh * DD + d4);
            *(float4*)&ks[t][d4] = kv;
            float4 gv;
            gv.x = 1.f / (1.f + __expf(-kv.x));
            gv.y = 1.f / (1.f + __expf(-kv.y));
            gv.z = 1.f / (1.f + __expf(-kv.z));
            gv.w = 1.f / (1.f + __expf(-kv.w));
            *(float4*)&gs[t][d4] = gv;
        } else if (tid < 512) {
            int u = tid - 256, t = u >> 5, e = u & 31;
            vs[t][e] = V[(size_t)(b * NN + n0 + t) * DKV + kvh * DD + e0 + e];
        }
        __syncthreads();

#pragma unroll
        for (int t = 0; t < 8; t++) {
            const float ve = vs[t][ew];
            const float g0 = gs[t][lane],      g1 = gs[t][lane + 32],
                        g2 = gs[t][lane + 64], g3 = gs[t][lane + 96];
            const float k0 = ks[t][lane],      k1 = ks[t][lane + 32],
                        k2 = ks[t][lane + 64], k3 = ks[t][lane + 96];
            s0 = s0 * g0 + k0 * ve;
            s1 = s1 * g1 + k1 * ve;
            s2 = s2 * g2 + k2 * ve;
            s3 = s3 * g3 + k3 * ve;
#pragma unroll
            for (int hh = 0; hh < 4; hh++) {
                float p = qs[hh][t][lane]      * s0
                        + qs[hh][t][lane + 32] * s1
                        + qs[hh][t][lane + 64] * s2
                        + qs[hh][t][lane + 96] * s3;
                p += __shfl_down_sync(0xffffffffu, p, 16);
                p += __shfl_down_sync(0xffffffffu, p, 8);
                p += __shfl_down_sync(0xffffffffu, p, 4);
                p += __shfl_down_sync(0xffffffffu, p, 2);
                p += __shfl_down_sync(0xffffffffu, p, 1);
                if (lane == 0) os[t][hh][ew] = p;
            }
        }
        __syncthreads();

        {
            int t = tid >> 7, hh = (tid >> 5) & 3, e = tid & 31;
            out[(size_t)(b * NN + n0 + t) * HIDD + (kvh * 4 + hh) * DD + e0 + e]
                = CSC * os[t][hh][e];
        }
    }
}

// ---------------- launch ---------------------------------------------------
extern "C" void kernel_launch(void* const* d_in, const int* in_sizes, int n_in,
                              void* d_out, int out_size)
{
    const float* hid = (const float*)d_in[0];
    const float* Wq  = (const float*)d_in[1];
    const float* Wk  = (const float*)d_in[2];
    const float* Wv  = (const float*)d_in[3];
    const float* Wo  = (const float*)d_in[4];
    float* outp = (float*)d_out;

    float *Qp, *Kp, *Vp, *AOp;
    cudaGetSymbolAddress((void**)&Qp,  g_Q);
    cudaGetSymbolAddress((void**)&Kp,  g_K);
    cudaGetSymbolAddress((void**)&Vp,  g_V);
    cudaGetSymbolAddress((void**)&AOp, g_AO);

    cudaFuncSetAttribute(flash_k, cudaFuncAttributeMaxDynamicSharedMemorySize,
                         (int)sizeof(FlashSmem));

    // 1..3: projections  (C = hidden @ W)
    gemm_k<false><<<dim3(DQ/BN,  MQ/BM), 256>>>(hid, Wq, Qp, HIDD, HIDD, DQ,  DQ,  1.f);
    gemm_k<false><<<dim3(DKV/BN, MQ/BM), 256>>>(hid, Wk, Kp, HIDD, HIDD, DKV, DKV, 1.f);
    gemm_k<false><<<dim3(DKV/BN, MQ/BM), 256>>>(hid, Wv, Vp, HIDD, HIDD, DKV, DKV, 1.f);

    // 4: FLA branch -> initializes d_out with 0.01*scale*fla
    fla_k<<<dim3(4, NKV, BB), 1024>>>(Qp, Kp, Vp, outp);

    // 5: fused causal flash attention -> g_AO
    flash_k<<<dim3(BB*NH, NN/128), 256, sizeof(FlashSmem)>>>(Qp, Kp, Vp, AOp);

    // 6: output projection, accumulate onto FLA contribution in d_out
    gemm_k<true><<<dim3(HIDD/BN, MQ/BM), 256>>>(AOp, Wo, outp, DQ, DQ, HIDD, HIDD, 1.f);
}

// round 4
// speedup vs baseline: 1.7129x; 1.0454x over previous
#include <cuda_runtime.h>
#include <math.h>
#include <stdint.h>

// Problem constants
#define BB   2
#define NN   2048
#define HIDD 2048
#define NH   16
#define NKV  4
#define DD   128
// derived
#define MQ   (BB*NN)        // 4096
#define DQ   (NH*DD)        // 2048
#define DKV  (NKV*DD)       // 512

// ---------------- device scratch (no allocations allowed) ----------------
__device__ float g_Q [(size_t)MQ * DQ];          // 4096 x 2048
__device__ float g_K [(size_t)MQ * DKV];         // 4096 x 512
__device__ float g_V [(size_t)MQ * DKV];         // 4096 x 512
__device__ float g_AO[(size_t)MQ * DQ];          // attention out (b,n,h*d)

// ---------------- tf32 / cp.async helpers --------------------------------
__device__ __forceinline__ uint32_t f2tf(float f) {
    uint32_t u;
    asm("cvt.rna.tf32.f32 %0, %1;" : "=r"(u) : "f"(f));
    return u;
}

__device__ __forceinline__ void mma_tf32(float* c, const uint32_t* a, const uint32_t* b) {
    asm volatile(
        "mma.sync.aligned.m16n8k8.row.col.f32.tf32.tf32.f32 "
        "{%0,%1,%2,%3}, {%4,%5,%6,%7}, {%8,%9}, {%0,%1,%2,%3};\n"
        : "+f"(c[0]), "+f"(c[1]), "+f"(c[2]), "+f"(c[3])
        : "r"(a[0]), "r"(a[1]), "r"(a[2]), "r"(a[3]),
          "r"(b[0]), "r"(b[1]));
}

__device__ __forceinline__ void cp16(void* smem, const void* gmem) {
    uint32_t s = (uint32_t)__cvta_generic_to_shared(smem);
    asm volatile("cp.async.cg.shared.global [%0], [%1], 16;\n" :: "r"(s), "l"(gmem));
}
__device__ __forceinline__ void cp_commit() {
    asm volatile("cp.async.commit_group;\n");
}
template<int N>
__device__ __forceinline__ void cp_wait() {
    asm volatile("cp.async.wait_group %0;\n" :: "n"(N));
}

// ---------------- tf32 GEMM, 128x128x16, 4-stage cp.async ----------------
#define BM 128
#define BN 128
#define BKk 16
#define AKP 20      // A k-major row pitch (words)
#define BNP 136     // B n-major row pitch (words)
#define GSTG 4
#define A_STG (BM*AKP)
#define B_STG (BKk*BNP)
#define GEMM_SMEM ((GSTG*(A_STG+B_STG))*4)

template<bool ACC>
__global__ __launch_bounds__(256)
void gemm_k(const float* __restrict__ Ag, const float* __restrict__ Bg,
            float* __restrict__ Cg, int K, int lda, int ldb, int ldc,
            float alpha)
{
    extern __shared__ float smf[];
    float* Asb = smf;                      // [GSTG][A_STG]
    float* Bsb = smf + GSTG * A_STG;       // [GSTG][B_STG]

    const int bx = blockIdx.x, by = blockIdx.y;
    const int tid  = threadIdx.x;
    const int lane = tid & 31;
    const int wid  = tid >> 5;
    const int wm   = wid >> 2;        // 0..1
    const int wn   = wid & 3;         // 0..3
    const int gr   = lane >> 2;       // 0..7
    const int gc   = lane & 3;        // 0..3

    const int rowA0 = by * BM;
    const int niter = K / BKk;

    // per-thread copy coordinates (2 chunks each for A and B)
    const int ar0 = tid >> 2,            ac0 = (tid & 3) * 4;
    const int ar1 = (tid + 256) >> 2,    ac1 = ((tid + 256) & 3) * 4;
    const int br0 = tid >> 5,            bc0 = (tid & 31) * 4;
    const int br1 = (tid + 256) >> 5,    bc1 = ((tid + 256) & 31) * 4;

    // prologue: stages 0..GSTG-2
#pragma unroll
    for (int s = 0; s < GSTG - 1; s++) {
        int k0 = s * BKk;
        float* As = Asb + s * A_STG;
        float* Bs = Bsb + s * B_STG;
        cp16(&As[ar0 * AKP + ac0], Ag + (long)(rowA0 + ar0) * lda + k0 + ac0);
        cp16(&As[ar1 * AKP + ac1], Ag + (long)(rowA0 + ar1) * lda + k0 + ac1);
        cp16(&Bs[br0 * BNP + bc0], Bg + (long)(k0 + br0) * ldb + bx * BN + bc0);
        cp16(&Bs[br1 * BNP + bc1], Bg + (long)(k0 + br1) * ldb + bx * BN + bc1);
        cp_commit();
    }

    float acc[16][4];
#pragma unroll
    for (int i = 0; i < 16; i++)
#pragma unroll
        for (int j = 0; j < 4; j++) acc[i][j] = 0.f;

    for (int i = 0; i < niter; i++) {
        cp_wait<GSTG - 2>();
        __syncthreads();

        // issue stage i+GSTG-1 (overwrites stage consumed at iter i-1)
        if (i + GSTG - 1 < niter) {
            int st = (i + GSTG - 1) % GSTG;
            int k0 = (i + GSTG - 1) * BKk;
            float* As = Asb + st * A_STG;
            float* Bs = Bsb + st * B_STG;
            cp16(&As[ar0 * AKP + ac0], Ag + (long)(rowA0 + ar0) * lda + k0 + ac0);
            cp16(&As[ar1 * AKP + ac1], Ag + (long)(rowA0 + ar1) * lda + k0 + ac1);
            cp16(&Bs[br0 * BNP + bc0], Bg + (long)(k0 + br0) * ldb + bx * BN + bc0);
            cp16(&Bs[br1 * BNP + bc1], Bg + (long)(k0 + br1) * ldb + bx * BN + bc1);
        }
        cp_commit();

        const float* As = Asb + (i % GSTG) * A_STG;
        const float* Bs = Bsb + (i % GSTG) * B_STG;

#pragma unroll
        for (int ks = 0; ks < BKk; ks += 8) {
            uint32_t a[4][4], bf[4][2];
#pragma unroll
            for (int mt = 0; mt < 4; mt++) {
                int m = wm * 64 + mt * 16 + gr;
                a[mt][0] = f2tf(As[m * AKP + ks + gc]);
                a[mt][1] = f2tf(As[(m + 8) * AKP + ks + gc]);
                a[mt][2] = f2tf(As[m * AKP + ks + gc + 4]);
                a[mt][3] = f2tf(As[(m + 8) * AKP + ks + gc + 4]);
            }
#pragma unroll
            for (int nt = 0; nt < 4; nt++) {
                int n = wn * 32 + nt * 8 + gr;
                bf[nt][0] = f2tf(Bs[(ks + gc) * BNP + n]);
                bf[nt][1] = f2tf(Bs[(ks + gc + 4) * BNP + n]);
            }
#pragma unroll
            for (int mt = 0; mt < 4; mt++)
#pragma unroll
                for (int nt = 0; nt < 4; nt++)
                    mma_tf32(acc[mt * 4 + nt], a[mt], bf[nt]);
        }
    }

    // epilogue
#pragma unroll
    for (int mt = 0; mt < 4; mt++) {
        int row = rowA0 + wm * 64 + mt * 16 + gr;
#pragma unroll
        for (int nt = 0; nt < 4; nt++) {
            int col = bx * BN + wn * 32 + nt * 8 + gc * 2;
            float* cp0 = Cg + (long)row * ldc + col;
            float* cp1 = Cg + (long)(row + 8) * ldc + col;
            const float* ac = acc[mt * 4 + nt];
            float2 r0 = make_float2(alpha * ac[0], alpha * ac[1]);
            float2 r1 = make_float2(alpha * ac[2], alpha * ac[3]);
            if (ACC) {
                float2 o0 = *(const float2*)cp0;
                float2 o1 = *(const float2*)cp1;
                r0.x += o0.x; r0.y += o0.y;
                r1.x += o1.x; r1.y += o1.y;
            }
            *(float2*)cp0 = r0;
            *(float2*)cp1 = r1;
        }
    }
}

// ---------------- fused flash attention (tf32 MMA, online softmax) --------
#define FQT 128
#define FKT 64
#define QP  132
#define KP  132
#define VP  136
#define PP  68

struct FlashSmem {
    uint32_t Qs[FQT * QP];
    uint32_t Ks[FKT * KP];
    uint32_t Vs[FKT * VP];
    uint32_t Ps[FQT * PP];
    float red_m[4][FQT];
    float red_l[4][FQT];
    float sm_m[FQT];
    float sm_l[FQT];
};

__global__ __launch_bounds__(256, 1)
void flash_k(const float* __restrict__ Q, const float* __restrict__ K,
             const float* __restrict__ V, float* __restrict__ AO)
{
    extern __shared__ char smbuf[];
    FlashSmem* sm = (FlashSmem*)smbuf;

    const int bh = blockIdx.x;          // 0..31
    const int b  = bh >> 4, h = bh & 15;
    const int kvh = h >> 2;
    const int qi = 15 - blockIdx.y;     // big tiles first

    const int tid  = threadIdx.x;
    const int lane = tid & 31;
    const int wid  = tid >> 5;
    const int wm   = wid >> 2;
    const int wn   = wid & 3;
    const int gr   = lane >> 2;
    const int gc   = lane & 3;

    const float SC = 0.08838834764831845f * 1.4426950408889634f;
#pragma unroll
    for (int it = 0; it < 16; it++) {
        int id = tid + it * 256;
        int r = id >> 5, d4 = (id & 31) * 4;
        float4 qv = *(const float4*)(Q + (size_t)(b * NN + qi * 128 + r) * DQ + h * DD + d4);
        uint4 qt = make_uint4(f2tf(qv.x * SC), f2tf(qv.y * SC),
                              f2tf(qv.z * SC), f2tf(qv.w * SC));
        *(uint4*)&sm->Qs[r * QP + d4] = qt;
    }
    if (tid < FQT) { sm->sm_m[tid] = -1e30f; sm->sm_l[tid] = 0.f; }

    float acc_o[16][4];
#pragma unroll
    for (int i = 0; i < 16; i++)
#pragma unroll
        for (int j = 0; j < 4; j++) acc_o[i][j] = 0.f;

    const int nkv = 2 * qi + 2;
    for (int j = 0; j < nkv; j++) {
        __syncthreads();
#pragma unroll
        for (int it = 0; it < 8; it++) {
            int id = tid + it * 256;
            int r = id >> 5, d4 = (id & 31) * 4;
            size_t goff = (size_t)(b * NN + j * FKT + r) * DKV + kvh * DD + d4;
            float4 kv = *(const float4*)(K + goff);
            uint4 kt = make_uint4(f2tf(kv.x), f2tf(kv.y), f2tf(kv.z), f2tf(kv.w));
            *(uint4*)&sm->Ks[r * KP + d4] = kt;
            float4 vv = *(const float4*)(V + goff);
            uint4 vt = make_uint4(f2tf(vv.x), f2tf(vv.y), f2tf(vv.z), f2tf(vv.w));
            *(uint4*)&sm->Vs[r * VP + d4] = vt;
        }
        __syncthreads();

        float acc_s[8][4];
#pragma unroll
        for (int i = 0; i < 8; i++)
#pragma unroll
            for (int c = 0; c < 4; c++) acc_s[i][c] = 0.f;

#pragma unroll
        for (int ks = 0; ks < DD; ks += 8) {
            uint32_t a[4][4], bfr[2][2];
#pragma unroll
            for (int mt = 0; mt < 4; mt++) {
                int m = wm * 64 + mt * 16 + gr;
                a[mt][0] = sm->Qs[m * QP + ks + gc];
                a[mt][1] = sm->Qs[(m + 8) * QP + ks + gc];
                a[mt][2] = sm->Qs[m * QP + ks + gc + 4];
                a[mt][3] = sm->Qs[(m + 8) * QP + ks + gc + 4];
            }
#pragma unroll
            for (int nt = 0; nt < 2; nt++) {
                int n = wn * 16 + nt * 8 + gr;
                bfr[nt][0] = sm->Ks[n * KP + ks + gc];
                bfr[nt][1] = sm->Ks[n * KP + ks + gc + 4];
            }
#pragma unroll
            for (int mt = 0; mt < 4; mt++)
#pragma unroll
                for (int nt = 0; nt < 2; nt++)
                    mma_tf32(acc_s[mt * 2 + nt], a[mt], bfr[nt]);
        }

        if ((j + 1) * FKT - 1 > qi * 128) {
#pragma unroll
            for (int mt = 0; mt < 4; mt++)
#pragma unroll
                for (int nt = 0; nt < 2; nt++)
#pragma unroll
                    for (int c = 0; c < 4; c++) {
                        int rowg = qi * 128 + wm * 64 + mt * 16 + gr + (c >> 1) * 8;
                        int colg = j * FKT + wn * 16 + nt * 8 + 2 * gc + (c & 1);
                        if (colg > rowg) acc_s[mt * 2 + nt][c] = -1e30f;
                    }
        }

#pragma unroll
        for (int mt = 0; mt < 4; mt++)
#pragma unroll
            for (int hh = 0; hh < 2; hh++) {
                float rmax = fmaxf(fmaxf(acc_s[mt * 2 + 0][hh * 2], acc_s[mt * 2 + 0][hh * 2 + 1]),
                                   fmaxf(acc_s[mt * 2 + 1][hh * 2], acc_s[mt * 2 + 1][hh * 2 + 1]));
                rmax = fmaxf(rmax, __shfl_xor_sync(0xffffffffu, rmax, 1));
                rmax = fmaxf(rmax, __shfl_xor_sync(0xffffffffu, rmax, 2));
                if (gc == 0)
                    sm->red_m[wn][wm * 64 + mt * 16 + gr + hh * 8] = rmax;
            }
        __syncthreads();

#pragma unroll
        for (int mt = 0; mt < 4; mt++)
#pragma unroll
            for (int hh = 0; hh < 2; hh++) {
                int rl = wm * 64 + mt * 16 + gr + hh * 8;
                float m_old = sm->sm_m[rl];
                float m_new = fmaxf(fmaxf(sm->red_m[0][rl], sm->red_m[1][rl]),
                                    fmaxf(sm->red_m[2][rl], sm->red_m[3][rl]));
                m_new = fmaxf(m_old, m_new);
                float alpha = exp2f(m_old - m_new);
#pragma unroll
                for (int nt = 0; nt < 4; nt++) {
                    acc_o[mt * 4 + nt][hh * 2]     *= alpha;
                    acc_o[mt * 4 + nt][hh * 2 + 1] *= alpha;
                }
                float psum = 0.f;
#pragma unroll
                for (int nt = 0; nt < 2; nt++) {
                    float p0 = exp2f(acc_s[mt * 2 + nt][hh * 2]     - m_new);
                    float p1 = exp2f(acc_s[mt * 2 + nt][hh * 2 + 1] - m_new);
                    psum += p0 + p1;
                    uint2 pt = make_uint2(f2tf(p0), f2tf(p1));
                    *(uint2*)&sm->Ps[rl * PP + wn * 16 + nt * 8 + 2 * gc] = pt;
                }
                psum += __shfl_xor_sync(0xffffffffu, psum, 1);
                psum += __shfl_xor_sync(0xffffffffu, psum, 2);
                if (gc == 0) sm->red_l[wn][rl] = psum;
            }
        __syncthreads();

        if (tid < FQT) {
            int rl = tid;
            float m_old = sm->sm_m[rl];
            float m_new = fmaxf(fmaxf(sm->red_m[0][rl], sm->red_m[1][rl]),
                                fmaxf(sm->red_m[2][rl], sm->red_m[3][rl]));
            m_new = fmaxf(m_old, m_new);
            float alpha = exp2f(m_old - m_new);
            sm->sm_l[rl] = sm->sm_l[rl] * alpha
                         + sm->red_l[0][rl] + sm->red_l[1][rl]
                         + sm->red_l[2][rl] + sm->red_l[3][rl];
            sm->sm_m[rl] = m_new;
        }

#pragma unroll
        for (int ks = 0; ks < FKT; ks += 8) {
            uint32_t pa[4][4], vb[4][2];
#pragma unroll
            for (int mt = 0; mt < 4; mt++) {
                int m = wm * 64 + mt * 16 + gr;
                pa[mt][0] = sm->Ps[m * PP + ks + gc];
                pa[mt][1] = sm->Ps[(m + 8) * PP + ks + gc];
                pa[mt][2] = sm->Ps[m * PP + ks + gc + 4];
                pa[mt][3] = sm->Ps[(m + 8) * PP + ks + gc + 4];
            }
#pragma unroll
            for (int nt = 0; nt < 4; nt++) {
                int n = wn * 32 + nt * 8 + gr;
                vb[nt][0] = sm->Vs[(ks + gc) * VP + n];
                vb[nt][1] = sm->Vs[(ks + gc + 4) * VP + n];
            }
#pragma unroll
            for (int mt = 0; mt < 4; mt++)
#pragma unroll
                for (int nt = 0; nt < 4; nt++)
                    mma_tf32(acc_o[mt * 4 + nt], pa[mt], vb[nt]);
        }
    }

    __syncthreads();

#pragma unroll
    for (int mt = 0; mt < 4; mt++)
#pragma unroll
        for (int hh = 0; hh < 2; hh++) {
            int rl = wm * 64 + mt * 16 + gr + hh * 8;
            float inv = 1.f / sm->sm_l[rl];
            int gq = qi * 128 + rl;
#pragma unroll
            for (int nt = 0; nt < 4; nt++) {
                int col = wn * 32 + nt * 8 + 2 * gc;
                float2 r = make_float2(acc_o[mt * 4 + nt][hh * 2] * inv,
                                       acc_o[mt * 4 + nt][hh * 2 + 1] * inv);
                *(float2*)(AO + (size_t)(b * NN + gq) * DQ + h * DD + col) = r;
            }
        }
}

// ---------------- GLA recurrence (unchanged) ------------------------------
__global__ __launch_bounds__(1024)
void fla_k(const float* __restrict__ Q, const float* __restrict__ K,
           const float* __restrict__ V, float* __restrict__ out)
{
    const int et = blockIdx.x, kvh = blockIdx.y, b = blockIdx.z;
    const int e0 = et * 32;
    const int tid = threadIdx.x;
    const int lane = tid & 31;
    const int ew   = tid >> 5;

    __shared__ __align__(16) float ks[8][128];
    __shared__ __align__(16) float gs[8][128];
    __shared__ __align__(16) float qs[4][8][128];
    __shared__ float vs[8][32];
    __shared__ float os[8][4][32];

    float s0 = 0.f, s1 = 0.f, s2 = 0.f, s3 = 0.f;
    const float CSC = 0.01f * 0.08838834764831845f;

    for (int c = 0; c < 256; c++) {
        const int n0 = c * 8;
        {
            int hh = tid >> 8, t = (tid >> 5) & 7, d4 = (tid & 31) * 4;
            float4 qv = *(const float4*)(Q + (size_t)(b * NN + n0 + t) * DQ
                                           + (kvh * 4 + hh) * DD + d4);
            *(float4*)&qs[hh][t][d4] = qv;
        }
        if (tid < 256) {
            int t = tid >> 5, d4 = (tid & 31) * 4;
            float4 kv = *(const float4*)(K + (size_t)(b * NN + n0 + t) * DKV
                                           + kvh * DD + d4);
            *(float4*)&ks[t][d4] = kv;
            float4 gv;
            gv.x = 1.f / (1.f + __expf(-kv.x));
            gv.y = 1.f / (1.f + __expf(-kv.y));
            gv.z = 1.f / (1.f + __expf(-kv.z));
            gv.w = 1.f / (1.f + __expf(-kv.w));
            *(float4*)&gs[t][d4] = gv;
        } else if (tid < 512) {
            int u = tid - 256, t = u >> 5, e = u & 31;
            vs[t][e] = V[(size_t)(b * NN + n0 + t) * DKV + kvh * DD + e0 + e];
        }
        __syncthreads();

#pragma unroll
        for (int t = 0; t < 8; t++) {
            const float ve = vs[t][ew];
            const float g0 = gs[t][lane],      g1 = gs[t][lane + 32],
                        g2 = gs[t][lane + 64], g3 = gs[t][lane + 96];
            const float k0 = ks[t][lane],      k1 = ks[t][lane + 32],
                        k2 = ks[t][lane + 64], k3 = ks[t][lane + 96];
            s0 = s0 * g0 + k0 * ve;
            s1 = s1 * g1 + k1 * ve;
            s2 = s2 * g2 + k2 * ve;
            s3 = s3 * g3 + k3 * ve;
#pragma unroll
            for (int hh = 0; hh < 4; hh++) {
                float p = qs[hh][t][lane]      * s0
                        + qs[hh][t][lane + 32] * s1
                        + qs[hh][t][lane + 64] * s2
                        + qs[hh][t][lane + 96] * s3;
                p += __shfl_down_sync(0xffffffffu, p, 16);
                p += __shfl_down_sync(0xffffffffu, p, 8);
                p += __shfl_down_sync(0xffffffffu, p, 4);
                p += __shfl_down_sync(0xffffffffu, p, 2);
                p += __shfl_down_sync(0xffffffffu, p, 1);
                if (lane == 0) os[t][hh][ew] = p;
            }
        }
        __syncthreads();

        {
            int t = tid >> 7, hh = (tid >> 5) & 3, e = tid & 31;
            out[(size_t)(b * NN + n0 + t) * HIDD + (kvh * 4 + hh) * DD + e0 + e]
                = CSC * os[t][hh][e];
        }
    }
}

// ---------------- launch ---------------------------------------------------
extern "C" void kernel_launch(void* const* d_in, const int* in_sizes, int n_in,
                              void* d_out, int out_size)
{
    const float* hid = (const float*)d_in[0];
    const float* Wq  = (const float*)d_in[1];
    const float* Wk  = (const float*)d_in[2];
    const float* Wv  = (const float*)d_in[3];
    const float* Wo  = (const float*)d_in[4];
    float* outp = (float*)d_out;

    float *Qp, *Kp, *Vp, *AOp;
    cudaGetSymbolAddress((void**)&Qp,  g_Q);
    cudaGetSymbolAddress((void**)&Kp,  g_K);
    cudaGetSymbolAddress((void**)&Vp,  g_V);
    cudaGetSymbolAddress((void**)&AOp, g_AO);

    cudaFuncSetAttribute(gemm_k<false>, cudaFuncAttributeMaxDynamicSharedMemorySize, GEMM_SMEM);
    cudaFuncSetAttribute(gemm_k<true>,  cudaFuncAttributeMaxDynamicSharedMemorySize, GEMM_SMEM);
    cudaFuncSetAttribute(flash_k, cudaFuncAttributeMaxDynamicSharedMemorySize,
                         (int)sizeof(FlashSmem));

    // 1..3: projections  (C = hidden @ W)
    gemm_k<false><<<dim3(DQ/BN,  MQ/BM), 256, GEMM_SMEM>>>(hid, Wq, Qp, HIDD, HIDD, DQ,  DQ,  1.f);
    gemm_k<false><<<dim3(DKV/BN, MQ/BM), 256, GEMM_SMEM>>>(hid, Wk, Kp, HIDD, HIDD, DKV, DKV, 1.f);
    gemm_k<false><<<dim3(DKV/BN, MQ/BM), 256, GEMM_SMEM>>>(hid, Wv, Vp, HIDD, HIDD, DKV, DKV, 1.f);

    // 4: FLA branch -> initializes d_out with 0.01*scale*fla
    fla_k<<<dim3(4, NKV, BB), 1024>>>(Qp, Kp, Vp, outp);

    // 5: fused causal flash attention -> g_AO
    flash_k<<<dim3(BB*NH, NN/128), 256, sizeof(FlashSmem)>>>(Qp, Kp, Vp, AOp);

    // 6: output projection, accumulate onto FLA contribution in d_out
    gemm_k<true><<<dim3(HIDD/BN, MQ/BM), 256, GEMM_SMEM>>>(AOp, Wo, outp, DQ, DQ, HIDD, HIDD, 1.f);
}

// round 6
// speedup vs baseline: 1.7299x; 1.0099x over previous
#include <cuda_runtime.h>
#include <math.h>
#include <stdint.h>

// Problem constants
#define BB   2
#define NN   2048
#define HIDD 2048
#define NH   16
#define NKV  4
#define DD   128
#define MQ   (BB*NN)        // 4096
#define DQ   (NH*DD)        // 2048
#define DKV  (NKV*DD)       // 512

// ---------------- device scratch ------------------------------------------
__device__ float g_Q [(size_t)MQ * DQ];
__device__ float g_K [(size_t)MQ * DKV];
__device__ float g_V [(size_t)MQ * DKV];
__device__ float g_AO[(size_t)MQ * DQ];

// ---------------- tf32 / cp.async helpers --------------------------------
__device__ __forceinline__ uint32_t f2tf(float f) {
    uint32_t u;
    asm("cvt.rna.tf32.f32 %0, %1;" : "=r"(u) : "f"(f));
    return u;
}

__device__ __forceinline__ void mma_tf32(float* c, const uint32_t* a, const uint32_t* b) {
    asm volatile(
        "mma.sync.aligned.m16n8k8.row.col.f32.tf32.tf32.f32 "
        "{%0,%1,%2,%3}, {%4,%5,%6,%7}, {%8,%9}, {%0,%1,%2,%3};\n"
        : "+f"(c[0]), "+f"(c[1]), "+f"(c[2]), "+f"(c[3])
        : "r"(a[0]), "r"(a[1]), "r"(a[2]), "r"(a[3]),
          "r"(b[0]), "r"(b[1]));
}

__device__ __forceinline__ void cp16(void* smem, const void* gmem) {
    uint32_t s = (uint32_t)__cvta_generic_to_shared(smem);
    asm volatile("cp.async.cg.shared.global [%0], [%1], 16;\n" :: "r"(s), "l"(gmem));
}
__device__ __forceinline__ void cp_commit() {
    asm volatile("cp.async.commit_group;\n");
}
template<int N8>
__device__ __forceinline__ void cp_wait() {
    asm volatile("cp.async.wait_group %0;\n" :: "n"(N8));
}

// ---------------- tf32 GEMM, 128x128x16, 4-stage cp.async (R4) -----------
#define BM 128
#define BN 128
#define BKk 16
#define AKP 20
#define BNP 136
#define GSTG 4
#define A_STG (BM*AKP)
#define B_STG (BKk*BNP)
#define GEMM_SMEM ((GSTG*(A_STG+B_STG))*4)

template<bool ACC>
__global__ __launch_bounds__(256)
void gemm_k(const float* __restrict__ Ag, const float* __restrict__ Bg,
            float* __restrict__ Cg, int K, int lda, int ldb, int ldc,
            float alpha)
{
    extern __shared__ float smf[];
    float* Asb = smf;
    float* Bsb = smf + GSTG * A_STG;

    const int bx = blockIdx.x, by = blockIdx.y;
    const int tid  = threadIdx.x;
    const int lane = tid & 31;
    const int wid  = tid >> 5;
    const int wm   = wid >> 2;
    const int wn   = wid & 3;
    const int gr   = lane >> 2;
    const int gc   = lane & 3;

    const int rowA0 = by * BM;
    const int niter = K / BKk;

    const int ar0 = tid >> 2,            ac0 = (tid & 3) * 4;
    const int ar1 = (tid + 256) >> 2,    ac1 = ((tid + 256) & 3) * 4;
    const int br0 = tid >> 5,            bc0 = (tid & 31) * 4;
    const int br1 = (tid + 256) >> 5,    bc1 = ((tid + 256) & 31) * 4;

#pragma unroll
    for (int s = 0; s < GSTG - 1; s++) {
        int k0 = s * BKk;
        float* As = Asb + s * A_STG;
        float* Bs = Bsb + s * B_STG;
        cp16(&As[ar0 * AKP + ac0], Ag + (long)(rowA0 + ar0) * lda + k0 + ac0);
        cp16(&As[ar1 * AKP + ac1], Ag + (long)(rowA0 + ar1) * lda + k0 + ac1);
        cp16(&Bs[br0 * BNP + bc0], Bg + (long)(k0 + br0) * ldb + bx * BN + bc0);
        cp16(&Bs[br1 * BNP + bc1], Bg + (long)(k0 + br1) * ldb + bx * BN + bc1);
        cp_commit();
    }

    float acc[16][4];
#pragma unroll
    for (int i = 0; i < 16; i++)
#pragma unroll
        for (int j = 0; j < 4; j++) acc[i][j] = 0.f;

    for (int i = 0; i < niter; i++) {
        cp_wait<GSTG - 2>();
        __syncthreads();

        if (i + GSTG - 1 < niter) {
            int st = (i + GSTG - 1) % GSTG;
            int k0 = (i + GSTG - 1) * BKk;
            float* As = Asb + st * A_STG;
            float* Bs = Bsb + st * B_STG;
            cp16(&As[ar0 * AKP + ac0], Ag + (long)(rowA0 + ar0) * lda + k0 + ac0);
            cp16(&As[ar1 * AKP + ac1], Ag + (long)(rowA0 + ar1) * lda + k0 + ac1);
            cp16(&Bs[br0 * BNP + bc0], Bg + (long)(k0 + br0) * ldb + bx * BN + bc0);
            cp16(&Bs[br1 * BNP + bc1], Bg + (long)(k0 + br1) * ldb + bx * BN + bc1);
        }
        cp_commit();

        const float* As = Asb + (i % GSTG) * A_STG;
        const float* Bs = Bsb + (i % GSTG) * B_STG;

#pragma unroll
        for (int ks = 0; ks < BKk; ks += 8) {
            uint32_t a[4][4], bf[4][2];
#pragma unroll
            for (int mt = 0; mt < 4; mt++) {
                int m = wm * 64 + mt * 16 + gr;
                a[mt][0] = f2tf(As[m * AKP + ks + gc]);
                a[mt][1] = f2tf(As[(m + 8) * AKP + ks + gc]);
                a[mt][2] = f2tf(As[m * AKP + ks + gc + 4]);
                a[mt][3] = f2tf(As[(m + 8) * AKP + ks + gc + 4]);
            }
#pragma unroll
            for (int nt = 0; nt < 4; nt++) {
                int n = wn * 32 + nt * 8 + gr;
                bf[nt][0] = f2tf(Bs[(ks + gc) * BNP + n]);
                bf[nt][1] = f2tf(Bs[(ks + gc + 4) * BNP + n]);
            }
#pragma unroll
            for (int mt = 0; mt < 4; mt++)
#pragma unroll
                for (int nt = 0; nt < 4; nt++)
                    mma_tf32(acc[mt * 4 + nt], a[mt], bf[nt]);
        }
    }

#pragma unroll
    for (int mt = 0; mt < 4; mt++) {
        int row = rowA0 + wm * 64 + mt * 16 + gr;
#pragma unroll
        for (int nt = 0; nt < 4; nt++) {
            int col = bx * BN + wn * 32 + nt * 8 + gc * 2;
            float* cp0 = Cg + (long)row * ldc + col;
            float* cp1 = Cg + (long)(row + 8) * ldc + col;
            const float* ac = acc[mt * 4 + nt];
            float2 r0 = make_float2(alpha * ac[0], alpha * ac[1]);
            float2 r1 = make_float2(alpha * ac[2], alpha * ac[3]);
            if (ACC) {
                float2 o0 = *(const float2*)cp0;
                float2 o1 = *(const float2*)cp1;
                r0.x += o0.x; r0.y += o0.y;
                r1.x += o1.x; r1.y += o1.y;
            }
            *(float2*)cp0 = r0;
            *(float2*)cp1 = r1;
        }
    }
}

// ---------------- flash attention: 2-stage cp.async K/V, P aliases K -----
#define FQT 128
#define FKT 64
#define QP  132      // Q pitch (tf32 words)
#define KPW 132      // K read pitch within stage (words)
#define VPW 136      // V pitch (words)
#define PPW 68       // P pitch (words) within K stage region
#define STGW (64*136)   // stage region: 34816 B = max(K 33792, P 34816, V 34816)

struct FlashSmem {
    uint32_t Qs[FQT * QP];
    float    Kb[2][STGW];     // raw K (pitch 132); aliased by P (pitch 68) after S
    float    Vb[2][STGW];     // raw V (pitch 136)
    float red_m[4][FQT];
    float red_l[4][FQT];
    float sm_m[FQT];
    float sm_l[FQT];
};

__device__ __forceinline__ void flash_prefetch(FlashSmem* sm, int s,
        const float* __restrict__ K, const float* __restrict__ V,
        int b, int kvh, int j, int tid)
{
#pragma unroll
    for (int it = 0; it < 8; it++) {
        int c = tid + it * 256;
        int r = c >> 5, seg = c & 31;         // 64 rows x 32 16B-chunks
        size_t goff = (size_t)(b * NN + j * FKT + r) * DKV + kvh * DD + seg * 4;
        cp16(&sm->Kb[s][r * KPW + seg * 4], K + goff);
        cp16(&sm->Vb[s][r * VPW + seg * 4], V + goff);
    }
}

__global__ __launch_bounds__(256, 1)
void flash_k(const float* __restrict__ Q, const float* __restrict__ K,
             const float* __restrict__ V, float* __restrict__ AO)
{
    extern __shared__ char smbuf[];
    FlashSmem* sm = (FlashSmem*)smbuf;

    const int bh = blockIdx.x;
    const int b  = bh >> 4, h = bh & 15;
    const int kvh = h >> 2;
    const int qi = 15 - blockIdx.y;     // big tiles first

    const int tid  = threadIdx.x;
    const int lane = tid & 31;
    const int wid  = tid >> 5;
    const int wm   = wid >> 2;
    const int wn   = wid & 3;
    const int gr   = lane >> 2;
    const int gc   = lane & 3;

    const int nkv = 2 * qi + 2;

    // prefetch j=0
    flash_prefetch(sm, 0, K, V, b, kvh, 0, tid);
    cp_commit();

    // stage Q (fold scale * log2e), tf32
    const float SC = 0.08838834764831845f * 1.4426950408889634f;
#pragma unroll
    for (int it = 0; it < 16; it++) {
        int id = tid + it * 256;
        int r = id >> 5, d4 = (id & 31) * 4;
        float4 qv = *(const float4*)(Q + (size_t)(b * NN + qi * 128 + r) * DQ + h * DD + d4);
        uint4 qt = make_uint4(f2tf(qv.x * SC), f2tf(qv.y * SC),
                              f2tf(qv.z * SC), f2tf(qv.w * SC));
        *(uint4*)&sm->Qs[r * QP + d4] = qt;
    }
    if (tid < FQT) { sm->sm_m[tid] = -1e30f; sm->sm_l[tid] = 0.f; }

    float acc_o[16][4];
#pragma unroll
    for (int i = 0; i < 16; i++)
#pragma unroll
        for (int j = 0; j < 4; j++) acc_o[i][j] = 0.f;

    for (int j = 0; j < nkv; j++) {
        const int s = j & 1;
        __syncthreads();                 // prior iter's P/V reads done; Q staged (j=0)

        if (j + 1 < nkv)
            flash_prefetch(sm, s ^ 1, K, V, b, kvh, j + 1, tid);
        cp_commit();
        cp_wait<1>();                    // stage j arrived; j+1 still in flight
        __syncthreads();

        const float* Kr = sm->Kb[s];
        const float* Vr = sm->Vb[s];
        uint32_t* Ps = (uint32_t*)sm->Kb[s];   // P overlays K after S-GEMM

        // S = Qs @ K^T
        float acc_s[8][4];
#pragma unroll
        for (int i = 0; i < 8; i++)
#pragma unroll
            for (int c = 0; c < 4; c++) acc_s[i][c] = 0.f;

#pragma unroll
        for (int ks = 0; ks < DD; ks += 8) {
            uint32_t a[4][4], bfr[2][2];
#pragma unroll
            for (int mt = 0; mt < 4; mt++) {
                int m = wm * 64 + mt * 16 + gr;
                a[mt][0] = sm->Qs[m * QP + ks + gc];
                a[mt][1] = sm->Qs[(m + 8) * QP + ks + gc];
                a[mt][2] = sm->Qs[m * QP + ks + gc + 4];
                a[mt][3] = sm->Qs[(m + 8) * QP + ks + gc + 4];
            }
#pragma unroll
            for (int nt = 0; nt < 2; nt++) {
                int n = wn * 16 + nt * 8 + gr;
                bfr[nt][0] = f2tf(Kr[n * KPW + ks + gc]);
                bfr[nt][1] = f2tf(Kr[n * KPW + ks + gc + 4]);
            }
#pragma unroll
            for (int mt = 0; mt < 4; mt++)
#pragma unroll
                for (int nt = 0; nt < 2; nt++)
                    mma_tf32(acc_s[mt * 2 + nt], a[mt], bfr[nt]);
        }

        // causal mask on diagonal tiles
        if ((j + 1) * FKT - 1 > qi * 128) {
#pragma unroll
            for (int mt = 0; mt < 4; mt++)
#pragma unroll
                for (int nt = 0; nt < 2; nt++)
#pragma unroll
                    for (int c = 0; c < 4; c++) {
                        int rowg = qi * 128 + wm * 64 + mt * 16 + gr + (c >> 1) * 8;
                        int colg = j * FKT + wn * 16 + nt * 8 + 2 * gc + (c & 1);
                        if (colg > rowg) acc_s[mt * 2 + nt][c] = -1e30f;
                    }
        }

        // row-max partials
#pragma unroll
        for (int mt = 0; mt < 4; mt++)
#pragma unroll
            for (int hh = 0; hh < 2; hh++) {
                float rmax = fmaxf(fmaxf(acc_s[mt * 2 + 0][hh * 2], acc_s[mt * 2 + 0][hh * 2 + 1]),
                                   fmaxf(acc_s[mt * 2 + 1][hh * 2], acc_s[mt * 2 + 1][hh * 2 + 1]));
                rmax = fmaxf(rmax, __shfl_xor_sync(0xffffffffu, rmax, 1));
                rmax = fmaxf(rmax, __shfl_xor_sync(0xffffffffu, rmax, 2));
                if (gc == 0)
                    sm->red_m[wn][wm * 64 + mt * 16 + gr + hh * 8] = rmax;
            }
        __syncthreads();     // all K reads done; safe to overlay P

        // softmax: p = exp2(s - m_new), rescale acc_o, stage P into Kb[s]
#pragma unroll
        for (int mt = 0; mt < 4; mt++)
#pragma unroll
            for (int hh = 0; hh < 2; hh++) {
                int rl = wm * 64 + mt * 16 + gr + hh * 8;
                float m_old = sm->sm_m[rl];
                float m_new = fmaxf(fmaxf(sm->red_m[0][rl], sm->red_m[1][rl]),
                                    fmaxf(sm->red_m[2][rl], sm->red_m[3][rl]));
                m_new = fmaxf(m_old, m_new);
                float alpha = exp2f(m_old - m_new);
#pragma unroll
                for (int nt = 0; nt < 4; nt++) {
                    acc_o[mt * 4 + nt][hh * 2]     *= alpha;
                    acc_o[mt * 4 + nt][hh * 2 + 1] *= alpha;
                }
                float psum = 0.f;
#pragma unroll
                for (int nt = 0; nt < 2; nt++) {
                    float p0 = exp2f(acc_s[mt * 2 + nt][hh * 2]     - m_new);
                    float p1 = exp2f(acc_s[mt * 2 + nt][hh * 2 + 1] - m_new);
                    psum += p0 + p1;
                    uint2 pt = make_uint2(f2tf(p0), f2tf(p1));
                    *(uint2*)&Ps[rl * PPW + wn * 16 + nt * 8 + 2 * gc] = pt;
                }
                psum += __shfl_xor_sync(0xffffffffu, psum, 1);
                psum += __shfl_xor_sync(0xffffffffu, psum, 2);
                if (gc == 0) sm->red_l[wn][rl] = psum;
            }
        __syncthreads();

        // stats update
        if (tid < FQT) {
            int rl = tid;
            float m_old = sm->sm_m[rl];
            float m_new = fmaxf(fmaxf(sm->red_m[0][rl], sm->red_m[1][rl]),
                                fmaxf(sm->red_m[2][rl], sm->red_m[3][rl]));
            m_new = fmaxf(m_old, m_new);
            float alpha = exp2f(m_old - m_new);
            sm->sm_l[rl] = sm->sm_l[rl] * alpha
                         + sm->red_l[0][rl] + sm->red_l[1][rl]
                         + sm->red_l[2][rl] + sm->red_l[3][rl];
            sm->sm_m[rl] = m_new;
        }

        // PV: acc_o += P @ V
#pragma unroll
        for (int ks = 0; ks < FKT; ks += 8) {
            uint32_t pa[4][4], vb[4][2];
#pragma unroll
            for (int mt = 0; mt < 4; mt++) {
                int m = wm * 64 + mt * 16 + gr;
                pa[mt][0] = Ps[m * PPW + ks + gc];
                pa[mt][1] = Ps[(m + 8) * PPW + ks + gc];
                pa[mt][2] = Ps[m * PPW + ks + gc + 4];
                pa[mt][3] = Ps[(m + 8) * PPW + ks + gc + 4];
            }
#pragma unroll
            for (int nt = 0; nt < 4; nt++) {
                int n = wn * 32 + nt * 8 + gr;
                vb[nt][0] = f2tf(Vr[(ks + gc) * VPW + n]);
                vb[nt][1] = f2tf(Vr[(ks + gc + 4) * VPW + n]);
            }
#pragma unroll
            for (int mt = 0; mt < 4; mt++)
#pragma unroll
                for (int nt = 0; nt < 4; nt++)
                    mma_tf32(acc_o[mt * 4 + nt], pa[mt], vb[nt]);
        }
    }

    __syncthreads();

    // epilogue: O = acc_o / l
#pragma unroll
    for (int mt = 0; mt < 4; mt++)
#pragma unroll
        for (int hh = 0; hh < 2; hh++) {
            int rl = wm * 64 + mt * 16 + gr + hh * 8;
            float inv = 1.f / sm->sm_l[rl];
            int gq = qi * 128 + rl;
#pragma unroll
            for (int nt = 0; nt < 4; nt++) {
                int col = wn * 32 + nt * 8 + 2 * gc;
                float2 r = make_float2(acc_o[mt * 4 + nt][hh * 2] * inv,
                                       acc_o[mt * 4 + nt][hh * 2 + 1] * inv);
                *(float2*)(AO + (size_t)(b * NN + gq) * DQ + h * DD + col) = r;
            }
        }
}

// ---------------- GLA recurrence (unchanged) ------------------------------
__global__ __launch_bounds__(1024)
void fla_k(const float* __restrict__ Q, const float* __restrict__ K,
           const float* __restrict__ V, float* __restrict__ out)
{
    const int et = blockIdx.x, kvh = blockIdx.y, b = blockIdx.z;
    const int e0 = et * 32;
    const int tid = threadIdx.x;
    const int lane = tid & 31;
    const int ew   = tid >> 5;

    __shared__ __align__(16) float ks[8][128];
    __shared__ __align__(16) float gs[8][128];
    __shared__ __align__(16) float qs[4][8][128];
    __shared__ float vs[8][32];
    __shared__ float os[8][4][32];

    float s0 = 0.f, s1 = 0.f, s2 = 0.f, s3 = 0.f;
    const float CSC = 0.01f * 0.08838834764831845f;

    for (int c = 0; c < 256; c++) {
        const int n0 = c * 8;
        {
            int hh = tid >> 8, t = (tid >> 5) & 7, d4 = (tid & 31) * 4;
            float4 qv = *(const float4*)(Q + (size_t)(b * NN + n0 + t) * DQ
                                           + (kvh * 4 + hh) * DD + d4);
            *(float4*)&qs[hh][t][d4] = qv;
        }
        if (tid < 256) {
            int t = tid >> 5, d4 = (tid & 31) * 4;
            float4 kv = *(const float4*)(K + (size_t)(b * NN + n0 + t) * DKV
                                           + kvh * DD + d4);
            *(float4*)&ks[t][d4] = kv;
            float4 gv;
            gv.x = 1.f / (1.f + __expf(-kv.x));
            gv.y = 1.f / (1.f + __expf(-kv.y));
            gv.z = 1.f / (1.f + __expf(-kv.z));
            gv.w = 1.f / (1.f + __expf(-kv.w));
            *(float4*)&gs[t][d4] = gv;
        } else if (tid < 512) {
            int u = tid - 256, t = u >> 5, e = u & 31;
            vs[t][e] = V[(size_t)(b * NN + n0 + t) * DKV + kvh * DD + e0 + e];
        }
        __syncthreads();

#pragma unroll
        for (int t = 0; t < 8; t++) {
            const float ve = vs[t][ew];
            const float g0 = gs[t][lane],      g1 = gs[t][lane + 32],
                        g2 = gs[t][lane + 64], g3 = gs[t][lane + 96];
            const float k0 = ks[t][lane],      k1 = ks[t][lane + 32],
                        k2 = ks[t][lane + 64], k3 = ks[t][lane + 96];
            s0 = s0 * g0 + k0 * ve;
            s1 = s1 * g1 + k1 * ve;
            s2 = s2 * g2 + k2 * ve;
            s3 = s3 * g3 + k3 * ve;
#pragma unroll
            for (int hh = 0; hh < 4; hh++) {
                float p = qs[hh][t][lane]      * s0
                        + qs[hh][t][lane + 32] * s1
                        + qs[hh][t][lane + 64] * s2
                        + qs[hh][t][lane + 96] * s3;
                p += __shfl_down_sync(0xffffffffu, p, 16);
                p += __shfl_down_sync(0xffffffffu, p, 8);
                p += __shfl_down_sync(0xffffffffu, p, 4);
                p += __shfl_down_sync(0xffffffffu, p, 2);
                p += __shfl_down_sync(0xffffffffu, p, 1);
                if (lane == 0) os[t][hh][ew] = p;
            }
        }
        __syncthreads();

        {
            int t = tid >> 7, hh = (tid >> 5) & 3, e = tid & 31;
            out[(size_t)(b * NN + n0 + t) * HIDD + (kvh * 4 + hh) * DD + e0 + e]
                = CSC * os[t][hh][e];
        }
    }
}

// ---------------- launch ---------------------------------------------------
extern "C" void kernel_launch(void* const* d_in, const int* in_sizes, int n_in,
                              void* d_out, int out_size)
{
    const float* hid = (const float*)d_in[0];
    const float* Wq  = (const float*)d_in[1];
    const float* Wk  = (const float*)d_in[2];
    const float* Wv  = (const float*)d_in[3];
    const float* Wo  = (const float*)d_in[4];
    float* outp = (float*)d_out;

    float *Qp, *Kp, *Vp, *AOp;
    cudaGetSymbolAddress((void**)&Qp,  g_Q);
    cudaGetSymbolAddress((void**)&Kp,  g_K);
    cudaGetSymbolAddress((void**)&Vp,  g_V);
    cudaGetSymbolAddress((void**)&AOp, g_AO);

    cudaFuncSetAttribute(gemm_k<false>, cudaFuncAttributeMaxDynamicSharedMemorySize, GEMM_SMEM);
    cudaFuncSetAttribute(gemm_k<true>,  cudaFuncAttributeMaxDynamicSharedMemorySize, GEMM_SMEM);
    cudaFuncSetAttribute(flash_k, cudaFuncAttributeMaxDynamicSharedMemorySize,
                         (int)sizeof(FlashSmem));

    // projections
    gemm_k<false><<<dim3(DQ/BN,  MQ/BM), 256, GEMM_SMEM>>>(hid, Wq, Qp, HIDD, HIDD, DQ,  DQ,  1.f);
    gemm_k<false><<<dim3(DKV/BN, MQ/BM), 256, GEMM_SMEM>>>(hid, Wk, Kp, HIDD, HIDD, DKV, DKV, 1.f);
    gemm_k<false><<<dim3(DKV/BN, MQ/BM), 256, GEMM_SMEM>>>(hid, Wv, Vp, HIDD, HIDD, DKV, DKV, 1.f);

    // FLA branch -> initializes d_out with 0.01*scale*fla
    fla_k<<<dim3(4, NKV, BB), 1024>>>(Qp, Kp, Vp, outp);

    // fused causal flash attention (pipelined K/V) -> g_AO
    flash_k<<<dim3(BB*NH, NN/128), 256, sizeof(FlashSmem)>>>(Qp, Kp, Vp, AOp);

    // output projection, accumulate onto FLA contribution in d_out
    gemm_k<true><<<dim3(HIDD/BN, MQ/BM), 256, GEMM_SMEM>>>(AOp, Wo, outp, DQ, DQ, HIDD, HIDD, 1.f);
}

// round 7
// speedup vs baseline: 2.0647x; 1.1935x over previous
#include <cuda_runtime.h>
#include <cuda_fp16.h>
#include <math.h>
#include <stdint.h>

// Problem constants
#define BB   2
#define NN   2048
#define HIDD 2048
#define NH   16
#define NKV  4
#define DD   128
#define MQ   (BB*NN)        // 4096
#define DQ   (NH*DD)        // 2048
#define DKV  (NKV*DD)       // 512

// ---------------- device scratch (fp16) -----------------------------------
__device__ __half g_Xh [(size_t)MQ * HIDD];
__device__ __half g_Qh [(size_t)MQ * DQ];     // pre-scaled by 1/sqrt(D)
__device__ __half g_Kh [(size_t)MQ * DKV];
__device__ __half g_Vh [(size_t)MQ * DKV];
__device__ __half g_AOh[(size_t)MQ * DQ];
__device__ __half g_WTq[(size_t)DQ  * HIDD];  // W^T [N][K] fp16
__device__ __half g_WTk[(size_t)DKV * HIDD];
__device__ __half g_WTv[(size_t)DKV * HIDD];
__device__ __half g_WTo[(size_t)HIDD * DQ];

// ---------------- helpers --------------------------------------------------
__device__ __forceinline__ void mma_h16(float* c, const uint32_t* a, const uint32_t* b) {
    asm volatile(
        "mma.sync.aligned.m16n8k16.row.col.f32.f16.f16.f32 "
        "{%0,%1,%2,%3}, {%4,%5,%6,%7}, {%8,%9}, {%0,%1,%2,%3};\n"
        : "+f"(c[0]), "+f"(c[1]), "+f"(c[2]), "+f"(c[3])
        : "r"(a[0]), "r"(a[1]), "r"(a[2]), "r"(a[3]),
          "r"(b[0]), "r"(b[1]));
}
__device__ __forceinline__ void cp16(void* smem, const void* gmem) {
    uint32_t s = (uint32_t)__cvta_generic_to_shared(smem);
    asm volatile("cp.async.cg.shared.global [%0], [%1], 16;\n" :: "r"(s), "l"(gmem));
}
__device__ __forceinline__ void cp_commit() { asm volatile("cp.async.commit_group;\n"); }
template<int N8>
__device__ __forceinline__ void cp_wait() { asm volatile("cp.async.wait_group %0;\n" :: "n"(N8)); }

__device__ __forceinline__ uint32_t h2u(__half2 h) { return *reinterpret_cast<uint32_t*>(&h); }

// ---------------- prepasses ------------------------------------------------
__global__ __launch_bounds__(256)
void convh_k(const float4* __restrict__ in, uint2* __restrict__ out)
{
    int i = blockIdx.x * 256 + threadIdx.x;
    float4 v = in[i];
    uint2 o;
    o.x = h2u(__floats2half2_rn(v.x, v.y));
    o.y = h2u(__floats2half2_rn(v.z, v.w));
    out[i] = o;
}

// W [K][N] fp32 -> WT [N][K] fp16
__global__ __launch_bounds__(256)
void transh_k(const float* __restrict__ W, __half* __restrict__ WT, int K, int N)
{
    __shared__ float t[32][33];
    int k0 = blockIdx.y * 32, n0 = blockIdx.x * 32;
    int tx = threadIdx.x & 31, ty = threadIdx.x >> 5;
#pragma unroll
    for (int i = 0; i < 4; i++)
        t[ty + 8 * i][tx] = W[(long)(k0 + ty + 8 * i) * N + n0 + tx];
    __syncthreads();
#pragma unroll
    for (int i = 0; i < 4; i++)
        WT[(long)(n0 + ty + 8 * i) * K + k0 + tx] = __float2half_rn(t[tx][ty + 8 * i]);
}

// ---------------- fp16 GEMM, 128x128x32, 4-stage cp.async ------------------
// C[M,N] = alpha * A[M,K] @ Bt[N,K]^T  (A,Bt k-major fp16; lda=ldb=K, ldc=N)
#define HP   20               // row pitch in 32-bit words (40 halfs)
#define HSTGW (128*HP)        // stage size per operand (words)
#define GEMM_SMEMH (4*2*HSTGW*4)

template<bool ACC, bool OUTH>
__global__ __launch_bounds__(256)
void gemm_h(const __half* __restrict__ Ag, const __half* __restrict__ Bt,
            void* __restrict__ Cg, int Kdim, int N, float alpha)
{
    extern __shared__ uint32_t smw[];
    uint32_t* Asb = smw;
    uint32_t* Bsb = smw + 4 * HSTGW;

    const int bx = blockIdx.x, by = blockIdx.y;
    const int tid  = threadIdx.x;
    const int lane = tid & 31;
    const int wid  = tid >> 5;
    const int wm   = wid >> 2;
    const int wn   = wid & 3;
    const int gr   = lane >> 2;
    const int gc   = lane & 3;

    const int rowA0 = by * 128;
    const int colB0 = bx * 128;
    const int niter = Kdim / 32;

    // 2 chunks per operand per thread (512 chunks = 128 rows x 4)
    const int r0 = tid >> 2,         s0 = (tid & 3);
    const int r1 = (tid + 256) >> 2, s1 = ((tid + 256) & 3);

#pragma unroll
    for (int s = 0; s < 3; s++) {
        int k0 = s * 32;
        uint32_t* As = Asb + s * HSTGW;
        uint32_t* Bs = Bsb + s * HSTGW;
        cp16(&As[r0 * HP + s0 * 4], Ag + (size_t)(rowA0 + r0) * Kdim + k0 + s0 * 8);
        cp16(&As[r1 * HP + s1 * 4], Ag + (size_t)(rowA0 + r1) * Kdim + k0 + s1 * 8);
        cp16(&Bs[r0 * HP + s0 * 4], Bt + (size_t)(colB0 + r0) * Kdim + k0 + s0 * 8);
        cp16(&Bs[r1 * HP + s1 * 4], Bt + (size_t)(colB0 + r1) * Kdim + k0 + s1 * 8);
        cp_commit();
    }

    float acc[16][4];
#pragma unroll
    for (int i = 0; i < 16; i++)
#pragma unroll
        for (int j = 0; j < 4; j++) acc[i][j] = 0.f;

    for (int i = 0; i < niter; i++) {
        cp_wait<2>();
        __syncthreads();

        if (i + 3 < niter) {
            int st = (i + 3) & 3;
            int k0 = (i + 3) * 32;
            uint32_t* As = Asb + st * HSTGW;
            uint32_t* Bs = Bsb + st * HSTGW;
            cp16(&As[r0 * HP + s0 * 4], Ag + (size_t)(rowA0 + r0) * Kdim + k0 + s0 * 8);
            cp16(&As[r1 * HP + s1 * 4], Ag + (size_t)(rowA0 + r1) * Kdim + k0 + s1 * 8);
            cp16(&Bs[r0 * HP + s0 * 4], Bt + (size_t)(colB0 + r0) * Kdim + k0 + s0 * 8);
            cp16(&Bs[r1 * HP + s1 * 4], Bt + (size_t)(colB0 + r1) * Kdim + k0 + s1 * 8);
        }
        cp_commit();

        const uint32_t* As = Asb + (i & 3) * HSTGW;
        const uint32_t* Bs = Bsb + (i & 3) * HSTGW;

#pragma unroll
        for (int ks = 0; ks < 2; ks++) {
            const int k2 = ks * 8;
            uint32_t a[4][4], bf[4][2];
#pragma unroll
            for (int mt = 0; mt < 4; mt++) {
                int m = wm * 64 + mt * 16 + gr;
                a[mt][0] = As[m * HP + k2 + gc];
                a[mt][1] = As[(m + 8) * HP + k2 + gc];
                a[mt][2] = As[m * HP + k2 + gc + 4];
                a[mt][3] = As[(m + 8) * HP + k2 + gc + 4];
            }
#pragma unroll
            for (int nt = 0; nt < 4; nt++) {
                int n = wn * 32 + nt * 8 + gr;
                bf[nt][0] = Bs[n * HP + k2 + gc];
                bf[nt][1] = Bs[n * HP + k2 + gc + 4];
            }
#pragma unroll
            for (int mt = 0; mt < 4; mt++)
#pragma unroll
                for (int nt = 0; nt < 4; nt++)
                    mma_h16(acc[mt * 4 + nt], a[mt], bf[nt]);
        }
    }

#pragma unroll
    for (int mt = 0; mt < 4; mt++) {
        int row = rowA0 + wm * 64 + mt * 16 + gr;
#pragma unroll
        for (int nt = 0; nt < 4; nt++) {
            int col = colB0 + wn * 32 + nt * 8 + gc * 2;
            const float* ac = acc[mt * 4 + nt];
            if (OUTH) {
                __half* C = (__half*)Cg;
                *(uint32_t*)(C + (size_t)row * N + col) =
                    h2u(__floats2half2_rn(alpha * ac[0], alpha * ac[1]));
                *(uint32_t*)(C + (size_t)(row + 8) * N + col) =
                    h2u(__floats2half2_rn(alpha * ac[2], alpha * ac[3]));
            } else {
                float* C = (float*)Cg;
                float* cp0 = C + (size_t)row * N + col;
                float* cp1 = C + (size_t)(row + 8) * N + col;
                float2 rv0 = make_float2(alpha * ac[0], alpha * ac[1]);
                float2 rv1 = make_float2(alpha * ac[2], alpha * ac[3]);
                if (ACC) {
                    float2 o0 = *(const float2*)cp0;
                    float2 o1 = *(const float2*)cp1;
                    rv0.x += o0.x; rv0.y += o0.y;
                    rv1.x += o1.x; rv1.y += o1.y;
                }
                *(float2*)cp0 = rv0;
                *(float2*)cp1 = rv1;
            }
        }
    }
}

// ---------------- fp16 flash attention ------------------------------------
#define QPW 68     // Q/K/V row pitch (words = half2)
#define PPW2 36    // P row pitch (words)

struct FlashSmemH {
    uint32_t Qs[128 * QPW];
    uint32_t Kb[2][64 * QPW];
    uint32_t Vb[2][64 * QPW];
    uint32_t Ps[128 * PPW2];
    float red_m[4][128];
    float red_l[4][128];
    float sm_m[128];
    float sm_l[128];
};

__device__ __forceinline__ void flash_pfkv(FlashSmemH* sm, int s,
        const __half* __restrict__ K, const __half* __restrict__ V,
        int b, int kvh, int j, int tid)
{
#pragma unroll
    for (int it = 0; it < 4; it++) {
        int id = tid + it * 256;
        int r = id >> 4, seg = id & 15;
        size_t goff = (size_t)(b * NN + j * 64 + r) * DKV + kvh * DD + seg * 8;
        cp16(&sm->Kb[s][r * QPW + seg * 4], K + goff);
        cp16(&sm->Vb[s][r * QPW + seg * 4], V + goff);
    }
}

__global__ __launch_bounds__(256, 1)
void flash_h(const __half* __restrict__ Q, const __half* __restrict__ K,
             const __half* __restrict__ V, __half* __restrict__ AO)
{
    extern __shared__ char smbuf[];
    FlashSmemH* sm = (FlashSmemH*)smbuf;

    const int bh = blockIdx.x;
    const int b  = bh >> 4, h = bh & 15;
    const int kvh = h >> 2;
    const int qi = 15 - blockIdx.y;

    const int tid  = threadIdx.x;
    const int lane = tid & 31;
    const int wid  = tid >> 5;
    const int wm   = wid >> 2;
    const int wn   = wid & 3;
    const int gr   = lane >> 2;
    const int gc   = lane & 3;

    const int nkv = 2 * qi + 2;
    const float LOG2E = 1.4426950408889634f;

    // prologue: stage Q + K0/V0 (one cp.async group)
#pragma unroll
    for (int it = 0; it < 8; it++) {
        int id = tid + it * 256;
        int r = id >> 4, seg = id & 15;
        cp16(&sm->Qs[r * QPW + seg * 4],
             Q + (size_t)(b * NN + qi * 128 + r) * DQ + h * DD + seg * 8);
    }
    flash_pfkv(sm, 0, K, V, b, kvh, 0, tid);
    cp_commit();

    if (tid < 128) { sm->sm_m[tid] = -1e30f; sm->sm_l[tid] = 0.f; }

    float acc_o[16][4];
#pragma unroll
    for (int i = 0; i < 16; i++)
#pragma unroll
        for (int j = 0; j < 4; j++) acc_o[i][j] = 0.f;

    for (int j = 0; j < nkv; j++) {
        const int s = j & 1;
        __syncthreads();
        if (j + 1 < nkv)
            flash_pfkv(sm, s ^ 1, K, V, b, kvh, j + 1, tid);
        cp_commit();
        cp_wait<1>();
        __syncthreads();

        const uint32_t* Ks = sm->Kb[s];

        // S = Q @ K^T  (Q pre-scaled by 1/sqrt(D))
        float acc_s[8][4];
#pragma unroll
        for (int i = 0; i < 8; i++)
#pragma unroll
            for (int c = 0; c < 4; c++) acc_s[i][c] = 0.f;

#pragma unroll
        for (int ks = 0; ks < 8; ks++) {
            const int k2 = ks * 8;
            uint32_t a[4][4], bfr[2][2];
#pragma unroll
            for (int mt = 0; mt < 4; mt++) {
                int m = wm * 64 + mt * 16 + gr;
                a[mt][0] = sm->Qs[m * QPW + k2 + gc];
                a[mt][1] = sm->Qs[(m + 8) * QPW + k2 + gc];
                a[mt][2] = sm->Qs[m * QPW + k2 + gc + 4];
                a[mt][3] = sm->Qs[(m + 8) * QPW + k2 + gc + 4];
            }
#pragma unroll
            for (int nt = 0; nt < 2; nt++) {
                int n = wn * 16 + nt * 8 + gr;
                bfr[nt][0] = Ks[n * QPW + k2 + gc];
                bfr[nt][1] = Ks[n * QPW + k2 + gc + 4];
            }
#pragma unroll
            for (int mt = 0; mt < 4; mt++)
#pragma unroll
                for (int nt = 0; nt < 2; nt++)
                    mma_h16(acc_s[mt * 2 + nt], a[mt], bfr[nt]);
        }

        // causal mask (diagonal tiles)
        if ((j + 1) * 64 - 1 > qi * 128) {
#pragma unroll
            for (int mt = 0; mt < 4; mt++)
#pragma unroll
                for (int nt = 0; nt < 2; nt++)
#pragma unroll
                    for (int c = 0; c < 4; c++) {
                        int rowg = qi * 128 + wm * 64 + mt * 16 + gr + (c >> 1) * 8;
                        int colg = j * 64 + wn * 16 + nt * 8 + 2 * gc + (c & 1);
                        if (colg > rowg) acc_s[mt * 2 + nt][c] = -1e30f;
                    }
        }

        // row-max partials
#pragma unroll
        for (int mt = 0; mt < 4; mt++)
#pragma unroll
            for (int hh = 0; hh < 2; hh++) {
                float rmax = fmaxf(fmaxf(acc_s[mt * 2 + 0][hh * 2], acc_s[mt * 2 + 0][hh * 2 + 1]),
                                   fmaxf(acc_s[mt * 2 + 1][hh * 2], acc_s[mt * 2 + 1][hh * 2 + 1]));
                rmax = fmaxf(rmax, __shfl_xor_sync(0xffffffffu, rmax, 1));
                rmax = fmaxf(rmax, __shfl_xor_sync(0xffffffffu, rmax, 2));
                if (gc == 0)
                    sm->red_m[wn][wm * 64 + mt * 16 + gr + hh * 8] = rmax;
            }
        __syncthreads();

        // softmax: p = exp2((s - m)*log2e), rescale acc_o, store P fp16
#pragma unroll
        for (int mt = 0; mt < 4; mt++)
#pragma unroll
            for (int hh = 0; hh < 2; hh++) {
                int rl = wm * 64 + mt * 16 + gr + hh * 8;
                float m_old = sm->sm_m[rl];
                float m_new = fmaxf(fmaxf(sm->red_m[0][rl], sm->red_m[1][rl]),
                                    fmaxf(sm->red_m[2][rl], sm->red_m[3][rl]));
                m_new = fmaxf(m_old, m_new);
                float alpha = exp2f((m_old - m_new) * LOG2E);
#pragma unroll
                for (int nt = 0; nt < 4; nt++) {
                    acc_o[mt * 4 + nt][hh * 2]     *= alpha;
                    acc_o[mt * 4 + nt][hh * 2 + 1] *= alpha;
                }
                float psum = 0.f;
#pragma unroll
                for (int nt = 0; nt < 2; nt++) {
                    float p0 = exp2f((acc_s[mt * 2 + nt][hh * 2]     - m_new) * LOG2E);
                    float p1 = exp2f((acc_s[mt * 2 + nt][hh * 2 + 1] - m_new) * LOG2E);
                    psum += p0 + p1;
                    sm->Ps[rl * PPW2 + wn * 8 + nt * 4 + gc] = h2u(__floats2half2_rn(p0, p1));
                }
                psum += __shfl_xor_sync(0xffffffffu, psum, 1);
                psum += __shfl_xor_sync(0xffffffffu, psum, 2);
                if (gc == 0) sm->red_l[wn][rl] = psum;
            }
        __syncthreads();

        if (tid < 128) {
            int rl = tid;
            float m_old = sm->sm_m[rl];
            float m_new = fmaxf(fmaxf(sm->red_m[0][rl], sm->red_m[1][rl]),
                                fmaxf(sm->red_m[2][rl], sm->red_m[3][rl]));
            m_new = fmaxf(m_old, m_new);
            float alpha = exp2f((m_old - m_new) * LOG2E);
            sm->sm_l[rl] = sm->sm_l[rl] * alpha
                         + sm->red_l[0][rl] + sm->red_l[1][rl]
                         + sm->red_l[2][rl] + sm->red_l[3][rl];
            sm->sm_m[rl] = m_new;
        }

        // PV: acc_o += P @ V   (V via ldmatrix.x4.trans)
        uint32_t vbase = (uint32_t)__cvta_generic_to_shared(&sm->Vb[s][0]);
        const int mrow = lane >> 3, rr = lane & 7;
#pragma unroll
        for (int ks = 0; ks < 4; ks++) {
            const int k2 = ks * 8;
            uint32_t pa[4][4];
#pragma unroll
            for (int mt = 0; mt < 4; mt++) {
                int m = wm * 64 + mt * 16 + gr;
                pa[mt][0] = sm->Ps[m * PPW2 + k2 + gc];
                pa[mt][1] = sm->Ps[(m + 8) * PPW2 + k2 + gc];
                pa[mt][2] = sm->Ps[m * PPW2 + k2 + gc + 4];
                pa[mt][3] = sm->Ps[(m + 8) * PPW2 + k2 + gc + 4];
            }
#pragma unroll
            for (int np = 0; np < 2; np++) {
                int n0 = wn * 32 + np * 16;
                int token = ks * 16 + (mrow & 1) * 8 + rr;
                int d     = n0 + (mrow >> 1) * 8;
                uint32_t addr = vbase + (uint32_t)(token * QPW + (d >> 1)) * 4;
                uint32_t v0, v1, v2, v3;
                asm volatile(
                    "ldmatrix.sync.aligned.m8n8.x4.trans.shared.b16 {%0,%1,%2,%3}, [%4];"
                    : "=r"(v0), "=r"(v1), "=r"(v2), "=r"(v3) : "r"(addr));
                uint32_t b0[2] = {v0, v1}, b1[2] = {v2, v3};
#pragma unroll
                for (int mt = 0; mt < 4; mt++) {
                    mma_h16(acc_o[mt * 4 + np * 2 + 0], pa[mt], b0);
                    mma_h16(acc_o[mt * 4 + np * 2 + 1], pa[mt], b1);
                }
            }
        }
    }

    __syncthreads();

    // epilogue: AO = fp16(acc_o / l)
#pragma unroll
    for (int mt = 0; mt < 4; mt++)
#pragma unroll
        for (int hh = 0; hh < 2; hh++) {
            int rl = wm * 64 + mt * 16 + gr + hh * 8;
            float inv = 1.f / sm->sm_l[rl];
            int gq = qi * 128 + rl;
#pragma unroll
            for (int nt = 0; nt < 4; nt++) {
                int col = wn * 32 + nt * 8 + 2 * gc;
                *(uint32_t*)(AO + (size_t)(b * NN + gq) * DQ + h * DD + col) =
                    h2u(__floats2half2_rn(acc_o[mt * 4 + nt][hh * 2] * inv,
                                          acc_o[mt * 4 + nt][hh * 2 + 1] * inv));
            }
        }
}

// ---------------- GLA recurrence (fp16 inputs) ----------------------------
__global__ __launch_bounds__(1024)
void fla_k(const __half* __restrict__ Q, const __half* __restrict__ K,
           const __half* __restrict__ V, float* __restrict__ out)
{
    const int et = blockIdx.x, kvh = blockIdx.y, b = blockIdx.z;
    const int e0 = et * 32;
    const int tid = threadIdx.x;
    const int lane = tid & 31;
    const int ew   = tid >> 5;

    __shared__ __align__(16) float ks[8][128];
    __shared__ __align__(16) float gs[8][128];
    __shared__ __align__(16) float qs[4][8][128];
    __shared__ float vs[8][32];
    __shared__ float os[8][4][32];

    float s0 = 0.f, s1 = 0.f, s2 = 0.f, s3 = 0.f;
    const float CSC = 0.01f;   // Q is pre-scaled by 1/sqrt(D)

    for (int c = 0; c < 256; c++) {
        const int n0 = c * 8;
        {
            int hh = tid >> 8, t = (tid >> 5) & 7, d4 = (tid & 31) * 4;
            uint2 raw = *(const uint2*)(Q + (size_t)(b * NN + n0 + t) * DQ
                                          + (kvh * 4 + hh) * DD + d4);
            float2 f01 = __half22float2(*reinterpret_cast<__half2*>(&raw.x));
            float2 f23 = __half22float2(*reinterpret_cast<__half2*>(&raw.y));
            qs[hh][t][d4 + 0] = f01.x; qs[hh][t][d4 + 1] = f01.y;
            qs[hh][t][d4 + 2] = f23.x; qs[hh][t][d4 + 3] = f23.y;
        }
        if (tid < 256) {
            int t = tid >> 5, d4 = (tid & 31) * 4;
            uint2 raw = *(const uint2*)(K + (size_t)(b * NN + n0 + t) * DKV
                                          + kvh * DD + d4);
            float2 f01 = __half22float2(*reinterpret_cast<__half2*>(&raw.x));
            float2 f23 = __half22float2(*reinterpret_cast<__half2*>(&raw.y));
            ks[t][d4 + 0] = f01.x; ks[t][d4 + 1] = f01.y;
            ks[t][d4 + 2] = f23.x; ks[t][d4 + 3] = f23.y;
            gs[t][d4 + 0] = 1.f / (1.f + __expf(-f01.x));
            gs[t][d4 + 1] = 1.f / (1.f + __expf(-f01.y));
            gs[t][d4 + 2] = 1.f / (1.f + __expf(-f23.x));
            gs[t][d4 + 3] = 1.f / (1.f + __expf(-f23.y));
        } else if (tid < 512) {
            int u = tid - 256, t = u >> 5, e = u & 31;
            vs[t][e] = __half2float(V[(size_t)(b * NN + n0 + t) * DKV + kvh * DD + e0 + e]);
        }
        __syncthreads();

#pragma unroll
        for (int t = 0; t < 8; t++) {
            const float ve = vs[t][ew];
            const float g0 = gs[t][lane],      g1 = gs[t][lane + 32],
                        g2 = gs[t][lane + 64], g3 = gs[t][lane + 96];
            const float k0 = ks[t][lane],      k1 = ks[t][lane + 32],
                        k2 = ks[t][lane + 64], k3 = ks[t][lane + 96];
            s0 = s0 * g0 + k0 * ve;
            s1 = s1 * g1 + k1 * ve;
            s2 = s2 * g2 + k2 * ve;
            s3 = s3 * g3 + k3 * ve;
#pragma unroll
            for (int hh = 0; hh < 4; hh++) {
                float p = qs[hh][t][lane]      * s0
                        + qs[hh][t][lane + 32] * s1
                        + qs[hh][t][lane + 64] * s2
                        + qs[hh][t][lane + 96] * s3;
                p += __shfl_down_sync(0xffffffffu, p, 16);
                p += __shfl_down_sync(0xffffffffu, p, 8);
                p += __shfl_down_sync(0xffffffffu, p, 4);
                p += __shfl_down_sync(0xffffffffu, p, 2);
                p += __shfl_down_sync(0xffffffffu, p, 1);
                if (lane == 0) os[t][hh][ew] = p;
            }
        }
        __syncthreads();

        {
            int t = tid >> 7, hh = (tid >> 5) & 3, e = tid & 31;
            out[(size_t)(b * NN + n0 + t) * HIDD + (kvh * 4 + hh) * DD + e0 + e]
                = CSC * os[t][hh][e];
        }
    }
}

// ---------------- launch ---------------------------------------------------
extern "C" void kernel_launch(void* const* d_in, const int* in_sizes, int n_in,
                              void* d_out, int out_size)
{
    const float* hid = (const float*)d_in[0];
    const float* Wq  = (const float*)d_in[1];
    const float* Wk  = (const float*)d_in[2];
    const float* Wv  = (const float*)d_in[3];
    const float* Wo  = (const float*)d_in[4];
    float* outp = (float*)d_out;

    __half *Xh, *Qh, *Kh, *Vh, *AOh, *WTq, *WTk, *WTv, *WTo;
    cudaGetSymbolAddress((void**)&Xh,  g_Xh);
    cudaGetSymbolAddress((void**)&Qh,  g_Qh);
    cudaGetSymbolAddress((void**)&Kh,  g_Kh);
    cudaGetSymbolAddress((void**)&Vh,  g_Vh);
    cudaGetSymbolAddress((void**)&AOh, g_AOh);
    cudaGetSymbolAddress((void**)&WTq, g_WTq);
    cudaGetSymbolAddress((void**)&WTk, g_WTk);
    cudaGetSymbolAddress((void**)&WTv, g_WTv);
    cudaGetSymbolAddress((void**)&WTo, g_WTo);

    cudaFuncSetAttribute((const void*)gemm_h<false,true>,  cudaFuncAttributeMaxDynamicSharedMemorySize, GEMM_SMEMH);
    cudaFuncSetAttribute((const void*)gemm_h<true,false>,  cudaFuncAttributeMaxDynamicSharedMemorySize, GEMM_SMEMH);
    cudaFuncSetAttribute((const void*)flash_h, cudaFuncAttributeMaxDynamicSharedMemorySize,
                         (int)sizeof(FlashSmemH));

    const float scale = 0.08838834764831845f;

    // prepasses
    convh_k<<<(MQ * HIDD) / 4 / 256, 256>>>((const float4*)hid, (uint2*)Xh);
    transh_k<<<dim3(DQ / 32,  HIDD / 32), 256>>>(Wq, WTq, HIDD, DQ);
    transh_k<<<dim3(DKV / 32, HIDD / 32), 256>>>(Wk, WTk, HIDD, DKV);
    transh_k<<<dim3(DKV / 32, HIDD / 32), 256>>>(Wv, WTv, HIDD, DKV);
    transh_k<<<dim3(HIDD / 32, DQ / 32),  256>>>(Wo, WTo, DQ, HIDD);

    // projections (fp16 out; Q pre-scaled by 1/sqrt(D))
    gemm_h<false,true><<<dim3(DQ / 128,  MQ / 128), 256, GEMM_SMEMH>>>(Xh, WTq, Qh, HIDD, DQ,  scale);
    gemm_h<false,true><<<dim3(DKV / 128, MQ / 128), 256, GEMM_SMEMH>>>(Xh, WTk, Kh, HIDD, DKV, 1.f);
    gemm_h<false,true><<<dim3(DKV / 128, MQ / 128), 256, GEMM_SMEMH>>>(Xh, WTv, Vh, HIDD, DKV, 1.f);

    // FLA branch -> initializes d_out with 0.01 * (q_scaled . S)
    fla_k<<<dim3(4, NKV, BB), 1024>>>(Qh, Kh, Vh, outp);

    // fused causal flash attention -> AO (fp16)
    flash_h<<<dim3(BB * NH, NN / 128), 256, sizeof(FlashSmemH)>>>(Qh, Kh, Vh, AOh);

    // output projection, accumulate onto FLA contribution in d_out
    gemm_h<true,false><<<dim3(HIDD / 128, MQ / 128), 256, GEMM_SMEMH>>>(AOh, WTo, outp, DQ, HIDD, 1.f);
}

// round 8
// speedup vs baseline: 2.0849x; 1.0098x over previous
#include <cuda_runtime.h>
#include <cuda_fp16.h>
#include <math.h>
#include <stdint.h>

// Problem constants
#define BB   2
#define NN   2048
#define HIDD 2048
#define NH   16
#define NKV  4
#define DD   128
#define MQ   (BB*NN)        // 4096
#define DQ   (NH*DD)        // 2048
#define DKV  (NKV*DD)       // 512
#define NQKV (DQ + 2*DKV)   // 3072 fused projection width

// ---------------- device scratch (fp16) -----------------------------------
__device__ __half g_Xh  [(size_t)MQ * HIDD];
__device__ __half g_QKV [(size_t)MQ * NQKV];    // [4096][3072]: Q | K | V
__device__ __half g_AOh [(size_t)MQ * DQ];
__device__ __half g_WTa [(size_t)NQKV * HIDD];  // fused W^T [3072][2048]
__device__ __half g_WTo [(size_t)HIDD * DQ];

// ---------------- helpers --------------------------------------------------
__device__ __forceinline__ void mma_h16(float* c, const uint32_t* a, const uint32_t* b) {
    asm volatile(
        "mma.sync.aligned.m16n8k16.row.col.f32.f16.f16.f32 "
        "{%0,%1,%2,%3}, {%4,%5,%6,%7}, {%8,%9}, {%0,%1,%2,%3};\n"
        : "+f"(c[0]), "+f"(c[1]), "+f"(c[2]), "+f"(c[3])
        : "r"(a[0]), "r"(a[1]), "r"(a[2]), "r"(a[3]),
          "r"(b[0]), "r"(b[1]));
}
__device__ __forceinline__ void ldsm4(uint32_t& r0, uint32_t& r1, uint32_t& r2,
                                      uint32_t& r3, uint32_t addr) {
    asm volatile("ldmatrix.sync.aligned.m8n8.x4.shared.b16 {%0,%1,%2,%3}, [%4];"
                 : "=r"(r0), "=r"(r1), "=r"(r2), "=r"(r3) : "r"(addr));
}
__device__ __forceinline__ void cp16(void* smem, const void* gmem) {
    uint32_t s = (uint32_t)__cvta_generic_to_shared(smem);
    asm volatile("cp.async.cg.shared.global [%0], [%1], 16;\n" :: "r"(s), "l"(gmem));
}
__device__ __forceinline__ void cp_commit() { asm volatile("cp.async.commit_group;\n"); }
template<int N8>
__device__ __forceinline__ void cp_wait() { asm volatile("cp.async.wait_group %0;\n" :: "n"(N8)); }
__device__ __forceinline__ uint32_t h2u(__half2 h) { return *reinterpret_cast<uint32_t*>(&h); }

// ---------------- prepasses ------------------------------------------------
__global__ __launch_bounds__(256)
void convh_k(const float4* __restrict__ in, uint2* __restrict__ out)
{
    int i = blockIdx.x * 256 + threadIdx.x;
    float4 v = in[i];
    uint2 o;
    o.x = h2u(__floats2half2_rn(v.x, v.y));
    o.y = h2u(__floats2half2_rn(v.z, v.w));
    out[i] = o;
}

// W [K][N] fp32 -> WT [N][K] fp16, scaled by alpha
__global__ __launch_bounds__(256)
void transh_k(const float* __restrict__ W, __half* __restrict__ WT, int K, int N,
              float alpha)
{
    __shared__ float t[32][33];
    int k0 = blockIdx.y * 32, n0 = blockIdx.x * 32;
    int tx = threadIdx.x & 31, ty = threadIdx.x >> 5;
#pragma unroll
    for (int i = 0; i < 4; i++)
        t[ty + 8 * i][tx] = W[(long)(k0 + ty + 8 * i) * N + n0 + tx];
    __syncthreads();
#pragma unroll
    for (int i = 0; i < 4; i++)
        WT[(long)(n0 + ty + 8 * i) * K + k0 + tx] = __float2half_rn(alpha * t[tx][ty + 8 * i]);
}

// ---------------- fp16 GEMM, 128x128x32, 4-stage cp.async, ldmatrix -------
#define HP    20
#define HSTGW (128*HP)
#define GEMM_SMEMH (4*2*HSTGW*4)

template<bool ACC, bool OUTH>
__global__ __launch_bounds__(256)
void gemm_h(const __half* __restrict__ Ag, const __half* __restrict__ Bt,
            void* __restrict__ Cg, int Kdim, int N, float alpha)
{
    extern __shared__ uint32_t smw[];
    uint32_t* Asb = smw;
    uint32_t* Bsb = smw + 4 * HSTGW;
    const uint32_t abase = (uint32_t)__cvta_generic_to_shared(Asb);
    const uint32_t bbase = (uint32_t)__cvta_generic_to_shared(Bsb);

    const int bx = blockIdx.x, by = blockIdx.y;
    const int tid  = threadIdx.x;
    const int lane = tid & 31;
    const int wid  = tid >> 5;
    const int wm   = wid >> 2;
    const int wn   = wid & 3;
    const int gr   = lane >> 2;
    const int gc   = lane & 3;

    const int rowA0 = by * 128;
    const int colB0 = bx * 128;
    const int niter = Kdim / 32;

    const int lrow  = lane & 15;
    const int lcolw = (lane >> 4) * 4;
    const uint32_t aoff = (uint32_t)(((wm * 64 + lrow) * HP + lcolw) * 4);
    const uint32_t boff = (uint32_t)(((wn * 32 + lrow) * HP + lcolw) * 4);

    const int r0 = tid >> 2,         s0 = (tid & 3);
    const int r1 = (tid + 256) >> 2, s1 = ((tid + 256) & 3);

#pragma unroll
    for (int s = 0; s < 3; s++) {
        int k0 = s * 32;
        uint32_t* As = Asb + s * HSTGW;
        uint32_t* Bs = Bsb + s * HSTGW;
        cp16(&As[r0 * HP + s0 * 4], Ag + (size_t)(rowA0 + r0) * Kdim + k0 + s0 * 8);
        cp16(&As[r1 * HP + s1 * 4], Ag + (size_t)(rowA0 + r1) * Kdim + k0 + s1 * 8);
        cp16(&Bs[r0 * HP + s0 * 4], Bt + (size_t)(colB0 + r0) * Kdim + k0 + s0 * 8);
        cp16(&Bs[r1 * HP + s1 * 4], Bt + (size_t)(colB0 + r1) * Kdim + k0 + s1 * 8);
        cp_commit();
    }

    float acc[16][4];
#pragma unroll
    for (int i = 0; i < 16; i++)
#pragma unroll
        for (int j = 0; j < 4; j++) acc[i][j] = 0.f;

    for (int i = 0; i < niter; i++) {
        cp_wait<2>();
        __syncthreads();

        if (i + 3 < niter) {
            int st = (i + 3) & 3;
            int k0 = (i + 3) * 32;
            uint32_t* As = Asb + st * HSTGW;
            uint32_t* Bs = Bsb + st * HSTGW;
            cp16(&As[r0 * HP + s0 * 4], Ag + (size_t)(rowA0 + r0) * Kdim + k0 + s0 * 8);
            cp16(&As[r1 * HP + s1 * 4], Ag + (size_t)(rowA0 + r1) * Kdim + k0 + s1 * 8);
            cp16(&Bs[r0 * HP + s0 * 4], Bt + (size_t)(colB0 + r0) * Kdim + k0 + s0 * 8);
            cp16(&Bs[r1 * HP + s1 * 4], Bt + (size_t)(colB0 + r1) * Kdim + k0 + s1 * 8);
        }
        cp_commit();

        const uint32_t ast = abase + (uint32_t)((i & 3) * HSTGW * 4);
        const uint32_t bst = bbase + (uint32_t)((i & 3) * HSTGW * 4);

#pragma unroll
        for (int ks = 0; ks < 2; ks++) {
            const int k2 = ks * 8;
            uint32_t a[4][4], bf[4][2];
#pragma unroll
            for (int mt = 0; mt < 4; mt++)
                ldsm4(a[mt][0], a[mt][1], a[mt][2], a[mt][3],
                      ast + aoff + (uint32_t)((mt * 16 * HP + k2) * 4));
#pragma unroll
            for (int p = 0; p < 2; p++) {
                uint32_t q0, q1, q2, q3;
                ldsm4(q0, q1, q2, q3, bst + boff + (uint32_t)((p * 16 * HP + k2) * 4));
                bf[2 * p][0] = q0;     bf[2 * p][1] = q2;
                bf[2 * p + 1][0] = q1; bf[2 * p + 1][1] = q3;
            }
#pragma unroll
            for (int mt = 0; mt < 4; mt++)
#pragma unroll
                for (int nt = 0; nt < 4; nt++)
                    mma_h16(acc[mt * 4 + nt], a[mt], bf[nt]);
        }
    }

#pragma unroll
    for (int mt = 0; mt < 4; mt++) {
        int row = rowA0 + wm * 64 + mt * 16 + gr;
#pragma unroll
        for (int nt = 0; nt < 4; nt++) {
            int col = colB0 + wn * 32 + nt * 8 + gc * 2;
            const float* ac = acc[mt * 4 + nt];
            if (OUTH) {
                __half* C = (__half*)Cg;
                *(uint32_t*)(C + (size_t)row * N + col) =
                    h2u(__floats2half2_rn(alpha * ac[0], alpha * ac[1]));
                *(uint32_t*)(C + (size_t)(row + 8) * N + col) =
                    h2u(__floats2half2_rn(alpha * ac[2], alpha * ac[3]));
            } else {
                float* C = (float*)Cg;
                float* cp0 = C + (size_t)row * N + col;
                float* cp1 = C + (size_t)(row + 8) * N + col;
                float2 rv0 = make_float2(alpha * ac[0], alpha * ac[1]);
                float2 rv1 = make_float2(alpha * ac[2], alpha * ac[3]);
                if (ACC) {
                    float2 o0 = *(const float2*)cp0;
                    float2 o1 = *(const float2*)cp1;
                    rv0.x += o0.x; rv0.y += o0.y;
                    rv1.x += o1.x; rv1.y += o1.y;
                }
                *(float2*)cp0 = rv0;
                *(float2*)cp1 = rv1;
            }
        }
    }
}

// ---------------- fp16 flash attention (ldmatrix fragments) ----------------
#define QPW 68
#define PPW2 36

struct FlashSmemH {
    uint32_t Qs[128 * QPW];
    uint32_t Kb[2][64 * QPW];
    uint32_t Vb[2][64 * QPW];
    uint32_t Ps[128 * PPW2];
    float red_m[4][128];
    float red_l[4][128];
    float sm_m[128];
    float sm_l[128];
};

__device__ __forceinline__ void flash_pfkv(FlashSmemH* sm, int s,
        const __half* __restrict__ K, const __half* __restrict__ V,
        int b, int j, int tid)
{
#pragma unroll
    for (int it = 0; it < 4; it++) {
        int id = tid + it * 256;
        int r = id >> 4, seg = id & 15;
        size_t goff = (size_t)(b * NN + j * 64 + r) * NQKV + seg * 8;
        cp16(&sm->Kb[s][r * QPW + seg * 4], K + goff);
        cp16(&sm->Vb[s][r * QPW + seg * 4], V + goff);
    }
}

__global__ __launch_bounds__(256, 1)
void flash_h(const __half* __restrict__ Q, const __half* __restrict__ K,
             const __half* __restrict__ V, __half* __restrict__ AO)
{
    extern __shared__ char smbuf[];
    FlashSmemH* sm = (FlashSmemH*)smbuf;

    const int bh = blockIdx.x;
    const int b  = bh >> 4, h = bh & 15;
    const int kvh = h >> 2;
    const int qi = 15 - blockIdx.y;

    const int tid  = threadIdx.x;
    const int lane = tid & 31;
    const int wid  = tid >> 5;
    const int wm   = wid >> 2;
    const int wn   = wid & 3;
    const int gr   = lane >> 2;
    const int gc   = lane & 3;

    const int nkv = 2 * qi + 2;
    const float LOG2E = 1.4426950408889634f;

    const __half* Kh = K + (size_t)kvh * DD;
    const __half* Vh = V + (size_t)kvh * DD;

    const int lrow  = lane & 15;
    const int lcolw = (lane >> 4) * 4;
    const uint32_t qfbase = (uint32_t)__cvta_generic_to_shared(sm->Qs)
                          + (uint32_t)(((wm * 64 + lrow) * QPW + lcolw) * 4);
    const uint32_t pfbase = (uint32_t)__cvta_generic_to_shared(sm->Ps)
                          + (uint32_t)(((wm * 64 + lrow) * PPW2 + lcolw) * 4);
    const uint32_t kfoff  = (uint32_t)(((wn * 16 + lrow) * QPW + lcolw) * 4);

    // prologue: stage Q + K0/V0
#pragma unroll
    for (int it = 0; it < 8; it++) {
        int id = tid + it * 256;
        int r = id >> 4, seg = id & 15;
        cp16(&sm->Qs[r * QPW + seg * 4],
             Q + (size_t)(b * NN + qi * 128 + r) * NQKV + h * DD + seg * 8);
    }
    flash_pfkv(sm, 0, Kh, Vh, b, 0, tid);
    cp_commit();

    if (tid < 128) { sm->sm_m[tid] = -1e30f; sm->sm_l[tid] = 0.f; }

    float acc_o[16][4];
#pragma unroll
    for (int i = 0; i < 16; i++)
#pragma unroll
        for (int j = 0; j < 4; j++) acc_o[i][j] = 0.f;

    for (int j = 0; j < nkv; j++) {
        const int s = j & 1;
        __syncthreads();
        if (j + 1 < nkv)
            flash_pfkv(sm, s ^ 1, Kh, Vh, b, j + 1, tid);
        cp_commit();
        cp_wait<1>();
        __syncthreads();

        const uint32_t kst = (uint32_t)__cvta_generic_to_shared(sm->Kb[s]) + kfoff;

        // S = Q @ K^T
        float acc_s[8][4];
#pragma unroll
        for (int i = 0; i < 8; i++)
#pragma unroll
            for (int c = 0; c < 4; c++) acc_s[i][c] = 0.f;

#pragma unroll
        for (int ks = 0; ks < 8; ks++) {
            const int k2 = ks * 8;
            uint32_t a[4][4], bfr[2][2];
#pragma unroll
            for (int mt = 0; mt < 4; mt++)
                ldsm4(a[mt][0], a[mt][1], a[mt][2], a[mt][3],
                      qfbase + (uint32_t)((mt * 16 * QPW + k2) * 4));
            {
                uint32_t q0, q1, q2, q3;
                ldsm4(q0, q1, q2, q3, kst + (uint32_t)(k2 * 4));
                bfr[0][0] = q0; bfr[0][1] = q2;
                bfr[1][0] = q1; bfr[1][1] = q3;
            }
#pragma unroll
            for (int mt = 0; mt < 4; mt++)
#pragma unroll
                for (int nt = 0; nt < 2; nt++)
                    mma_h16(acc_s[mt * 2 + nt], a[mt], bfr[nt]);
        }

        // causal mask (diagonal tiles)
        if ((j + 1) * 64 - 1 > qi * 128) {
#pragma unroll
            for (int mt = 0; mt < 4; mt++)
#pragma unroll
                for (int nt = 0; nt < 2; nt++)
#pragma unroll
                    for (int c = 0; c < 4; c++) {
                        int rowg = qi * 128 + wm * 64 + mt * 16 + gr + (c >> 1) * 8;
                        int colg = j * 64 + wn * 16 + nt * 8 + 2 * gc + (c & 1);
                        if (colg > rowg) acc_s[mt * 2 + nt][c] = -1e30f;
                    }
        }

        // row-max partials
#pragma unroll
        for (int mt = 0; mt < 4; mt++)
#pragma unroll
            for (int hh = 0; hh < 2; hh++) {
                float rmax = fmaxf(fmaxf(acc_s[mt * 2 + 0][hh * 2], acc_s[mt * 2 + 0][hh * 2 + 1]),
                                   fmaxf(acc_s[mt * 2 + 1][hh * 2], acc_s[mt * 2 + 1][hh * 2 + 1]));
                rmax = fmaxf(rmax, __shfl_xor_sync(0xffffffffu, rmax, 1));
                rmax = fmaxf(rmax, __shfl_xor_sync(0xffffffffu, rmax, 2));
                if (gc == 0)
                    sm->red_m[wn][wm * 64 + mt * 16 + gr + hh * 8] = rmax;
            }
        __syncthreads();

        // softmax
#pragma unroll
        for (int mt = 0; mt < 4; mt++)
#pragma unroll
            for (int hh = 0; hh < 2; hh++) {
                int rl = wm * 64 + mt * 16 + gr + hh * 8;
                float m_old = sm->sm_m[rl];
                float m_new = fmaxf(fmaxf(sm->red_m[0][rl], sm->red_m[1][rl]),
                                    fmaxf(sm->red_m[2][rl], sm->red_m[3][rl]));
                m_new = fmaxf(m_old, m_new);
                float alpha = exp2f((m_old - m_new) * LOG2E);
#pragma unroll
                for (int nt = 0; nt < 4; nt++) {
                    acc_o[mt * 4 + nt][hh * 2]     *= alpha;
                    acc_o[mt * 4 + nt][hh * 2 + 1] *= alpha;
                }
                float psum = 0.f;
#pragma unroll
                for (int nt = 0; nt < 2; nt++) {
                    float p0 = exp2f((acc_s[mt * 2 + nt][hh * 2]     - m_new) * LOG2E);
                    float p1 = exp2f((acc_s[mt * 2 + nt][hh * 2 + 1] - m_new) * LOG2E);
                    psum += p0 + p1;
                    sm->Ps[rl * PPW2 + wn * 8 + nt * 4 + gc] = h2u(__floats2half2_rn(p0, p1));
                }
                psum += __shfl_xor_sync(0xffffffffu, psum, 1);
                psum += __shfl_xor_sync(0xffffffffu, psum, 2);
                if (gc == 0) sm->red_l[wn][rl] = psum;
            }
        __syncthreads();

        if (tid < 128) {
            int rl = tid;
            float m_old = sm->sm_m[rl];
            float m_new = fmaxf(fmaxf(sm->red_m[0][rl], sm->red_m[1][rl]),
                                fmaxf(sm->red_m[2][rl], sm->red_m[3][rl]));
            m_new = fmaxf(m_old, m_new);
            float alpha = exp2f((m_old - m_new) * LOG2E);
            sm->sm_l[rl] = sm->sm_l[rl] * alpha
                         + sm->red_l[0][rl] + sm->red_l[1][rl]
                         + sm->red_l[2][rl] + sm->red_l[3][rl];
            sm->sm_m[rl] = m_new;
        }

        // PV: acc_o += P @ V   (P via ldmatrix, V via ldmatrix.trans)
        uint32_t vbase = (uint32_t)__cvta_generic_to_shared(&sm->Vb[s][0]);
        const int mrow = lane >> 3, rr = lane & 7;
#pragma unroll
        for (int ks = 0; ks < 4; ks++) {
            const int k2 = ks * 8;
            uint32_t pa[4][4];
#pragma unroll
            for (int mt = 0; mt < 4; mt++)
                ldsm4(pa[mt][0], pa[mt][1], pa[mt][2], pa[mt][3],
                      pfbase + (uint32_t)((mt * 16 * PPW2 + k2) * 4));
#pragma unroll
            for (int np = 0; np < 2; np++) {
                int n0 = wn * 32 + np * 16;
                int token = ks * 16 + (mrow & 1) * 8 + rr;
                int d     = n0 + (mrow >> 1) * 8;
                uint32_t addr = vbase + (uint32_t)(token * QPW + (d >> 1)) * 4;
                uint32_t v0, v1, v2, v3;
                asm volatile(
                    "ldmatrix.sync.aligned.m8n8.x4.trans.shared.b16 {%0,%1,%2,%3}, [%4];"
                    : "=r"(v0), "=r"(v1), "=r"(v2), "=r"(v3) : "r"(addr));
                uint32_t b0[2] = {v0, v1}, b1[2] = {v2, v3};
#pragma unroll
                for (int mt = 0; mt < 4; mt++) {
                    mma_h16(acc_o[mt * 4 + np * 2 + 0], pa[mt], b0);
                    mma_h16(acc_o[mt * 4 + np * 2 + 1], pa[mt], b1);
                }
            }
        }
    }

    __syncthreads();

    // epilogue
#pragma unroll
    for (int mt = 0; mt < 4; mt++)
#pragma unroll
        for (int hh = 0; hh < 2; hh++) {
            int rl = wm * 64 + mt * 16 + gr + hh * 8;
            float inv = 1.f / sm->sm_l[rl];
            int gq = qi * 128 + rl;
#pragma unroll
            for (int nt = 0; nt < 4; nt++) {
                int col = wn * 32 + nt * 8 + 2 * gc;
                *(uint32_t*)(AO + (size_t)(b * NN + gq) * DQ + h * DD + col) =
                    h2u(__floats2half2_rn(acc_o[mt * 4 + nt][hh * 2] * inv,
                                          acc_o[mt * 4 + nt][hh * 2 + 1] * inv));
            }
        }
}

// ---------------- GLA recurrence (fp16 inputs, fused buffer) --------------
__global__ __launch_bounds__(1024)
void fla_k(const __half* __restrict__ Q, const __half* __restrict__ K,
           const __half* __restrict__ V, float* __restrict__ out)
{
    const int et = blockIdx.x, kvh = blockIdx.y, b = blockIdx.z;
    const int e0 = et * 32;
    const int tid = threadIdx.x;
    const int lane = tid & 31;
    const int ew   = tid >> 5;

    __shared__ __align__(16) float ks[8][128];
    __shared__ __align__(16) float gs[8][128];
    __shared__ __align__(16) float qs[4][8][128];
    __shared__ float vs[8][32];
    __shared__ float os[8][4][32];

    float s0 = 0.f, s1 = 0.f, s2 = 0.f, s3 = 0.f;
    const float CSC = 0.01f;   // Q pre-scaled by 1/sqrt(D)

    for (int c = 0; c < 256; c++) {
        const int n0 = c * 8;
        {
            int hh = tid >> 8, t = (tid >> 5) & 7, d4 = (tid & 31) * 4;
            uint2 raw = *(const uint2*)(Q + (size_t)(b * NN + n0 + t) * NQKV
                                          + (kvh * 4 + hh) * DD + d4);
            float2 f01 = __half22float2(*reinterpret_cast<__half2*>(&raw.x));
            float2 f23 = __half22float2(*reinterpret_cast<__half2*>(&raw.y));
            qs[hh][t][d4 + 0] = f01.x; qs[hh][t][d4 + 1] = f01.y;
            qs[hh][t][d4 + 2] = f23.x; qs[hh][t][d4 + 3] = f23.y;
        }
        if (tid < 256) {
            int t = tid >> 5, d4 = (tid & 31) * 4;
            uint2 raw = *(const uint2*)(K + (size_t)(b * NN + n0 + t) * NQKV
                                          + kvh * DD + d4);
            float2 f01 = __half22float2(*reinterpret_cast<__half2*>(&raw.x));
            float2 f23 = __half22float2(*reinterpret_cast<__half2*>(&raw.y));
            ks[t][d4 + 0] = f01.x; ks[t][d4 + 1] = f01.y;
            ks[t][d4 + 2] = f23.x; ks[t][d4 + 3] = f23.y;
            gs[t][d4 + 0] = 1.f / (1.f + __expf(-f01.x));
            gs[t][d4 + 1] = 1.f / (1.f + __expf(-f01.y));
            gs[t][d4 + 2] = 1.f / (1.f + __expf(-f23.x));
            gs[t][d4 + 3] = 1.f / (1.f + __expf(-f23.y));
        } else if (tid < 512) {
            int u = tid - 256, t = u >> 5, e = u & 31;
            vs[t][e] = __half2float(V[(size_t)(b * NN + n0 + t) * NQKV + kvh * DD + e0 + e]);
        }
        __syncthreads();

#pragma unroll
        for (int t = 0; t < 8; t++) {
            const float ve = vs[t][ew];
            const float g0 = gs[t][lane],      g1 = gs[t][lane + 32],
                        g2 = gs[t][lane + 64], g3 = gs[t][lane + 96];
            const float k0 = ks[t][lane],      k1 = ks[t][lane + 32],
                        k2 = ks[t][lane + 64], k3 = ks[t][lane + 96];
            s0 = s0 * g0 + k0 * ve;
            s1 = s1 * g1 + k1 * ve;
            s2 = s2 * g2 + k2 * ve;
            s3 = s3 * g3 + k3 * ve;
#pragma unroll
            for (int hh = 0; hh < 4; hh++) {
                float p = qs[hh][t][lane]      * s0
                        + qs[hh][t][lane + 32] * s1
                        + qs[hh][t][lane + 64] * s2
                        + qs[hh][t][lane + 96] * s3;
                p += __shfl_down_sync(0xffffffffu, p, 16);
                p += __shfl_down_sync(0xffffffffu, p, 8);
                p += __shfl_down_sync(0xffffffffu, p, 4);
                p += __shfl_down_sync(0xffffffffu, p, 2);
                p += __shfl_down_sync(0xffffffffu, p, 1);
                if (lane == 0) os[t][hh][ew] = p;
            }
        }
        __syncthreads();

        {
            int t = tid >> 7, hh = (tid >> 5) & 3, e = tid & 31;
            out[(size_t)(b * NN + n0 + t) * HIDD + (kvh * 4 + hh) * DD + e0 + e]
                = CSC * os[t][hh][e];
        }
    }
}

// ---------------- launch ---------------------------------------------------
extern "C" void kernel_launch(void* const* d_in, const int* in_sizes, int n_in,
                              void* d_out, int out_size)
{
    const float* hid = (const float*)d_in[0];
    const float* Wq  = (const float*)d_in[1];
    const float* Wk  = (const float*)d_in[2];
    const float* Wv  = (const float*)d_in[3];
    const float* Wo  = (const float*)d_in[4];
    float* outp = (float*)d_out;

    __half *Xh, *QKV, *AOh, *WTa, *WTo;
    cudaGetSymbolAddress((void**)&Xh,  g_Xh);
    cudaGetSymbolAddress((void**)&QKV, g_QKV);
    cudaGetSymbolAddress((void**)&AOh, g_AOh);
    cudaGetSymbolAddress((void**)&WTa, g_WTa);
    cudaGetSymbolAddress((void**)&WTo, g_WTo);

    cudaFuncSetAttribute((const void*)gemm_h<false,true>, cudaFuncAttributeMaxDynamicSharedMemorySize, GEMM_SMEMH);
    cudaFuncSetAttribute((const void*)gemm_h<true,false>, cudaFuncAttributeMaxDynamicSharedMemorySize, GEMM_SMEMH);
    cudaFuncSetAttribute((const void*)flash_h, cudaFuncAttributeMaxDynamicSharedMemorySize,
                         (int)sizeof(FlashSmemH));

    const float scale = 0.08838834764831845f;

    // prepasses: fp16 hidden; fused transposed weights (Q region pre-scaled)
    convh_k<<<(MQ * HIDD) / 4 / 256, 256>>>((const float4*)hid, (uint2*)Xh);
    transh_k<<<dim3(DQ / 32,  HIDD / 32), 256>>>(Wq, WTa,                        HIDD, DQ,  scale);
    transh_k<<<dim3(DKV / 32, HIDD / 32), 256>>>(Wk, WTa + (size_t)DQ * HIDD,    HIDD, DKV, 1.f);
    transh_k<<<dim3(DKV / 32, HIDD / 32), 256>>>(Wv, WTa + (size_t)(DQ + DKV) * HIDD, HIDD, DKV, 1.f);
    transh_k<<<dim3(HIDD / 32, DQ / 32),  256>>>(Wo, WTo, DQ, HIDD, 1.f);

    // fused QKV projection: [4096][3072] = Xh @ WTa^T
    gemm_h<false,true><<<dim3(NQKV / 128, MQ / 128), 256, GEMM_SMEMH>>>(
        Xh, WTa, QKV, HIDD, NQKV, 1.f);

    const __half* Qh = QKV;
    const __half* Kh = QKV + DQ;
    const __half* Vh = QKV + DQ + DKV;

    // FLA branch -> initializes d_out with 0.01 * (q_scaled . S)
    fla_k<<<dim3(4, NKV, BB), 1024>>>(Qh, Kh, Vh, outp);

    // fused causal flash attention -> AO (fp16)
    flash_h<<<dim3(BB * NH, NN / 128), 256, sizeof(FlashSmemH)>>>(Qh, Kh, Vh, AOh);

    // output projection, accumulate onto FLA contribution in d_out
    gemm_h<true,false><<<dim3(HIDD / 128, MQ / 128), 256, GEMM_SMEMH>>>(
        AOh, WTo, outp, DQ, HIDD, 1.f);
}

// round 9
// speedup vs baseline: 3.4713x; 1.6650x over previous
#include <cuda_runtime.h>
#include <cuda_fp16.h>
#include <math.h>
#include <stdint.h>

// Problem constants
#define BB   2
#define NN   2048
#define HIDD 2048
#define NH   16
#define NKV  4
#define DD   128
#define MQ   (BB*NN)        // 4096
#define DQ   (NH*DD)        // 2048
#define DKV  (NKV*DD)       // 512
#define NQKV (DQ + 2*DKV)   // 3072

// ---------------- device scratch (fp16) -----------------------------------
__device__ __half g_Xh  [(size_t)MQ * HIDD];
__device__ __half g_QKV [(size_t)MQ * NQKV];
__device__ __half g_AOh [(size_t)MQ * DQ];
__device__ __half g_WTa [(size_t)NQKV * HIDD];
__device__ __half g_WTo [(size_t)HIDD * DQ];

// ---------------- helpers --------------------------------------------------
__device__ __forceinline__ void mma_h16(float* c, const uint32_t* a, const uint32_t* b) {
    asm volatile(
        "mma.sync.aligned.m16n8k16.row.col.f32.f16.f16.f32 "
        "{%0,%1,%2,%3}, {%4,%5,%6,%7}, {%8,%9}, {%0,%1,%2,%3};\n"
        : "+f"(c[0]), "+f"(c[1]), "+f"(c[2]), "+f"(c[3])
        : "r"(a[0]), "r"(a[1]), "r"(a[2]), "r"(a[3]),
          "r"(b[0]), "r"(b[1]));
}
__device__ __forceinline__ void ldsm4(uint32_t& r0, uint32_t& r1, uint32_t& r2,
                                      uint32_t& r3, uint32_t addr) {
    asm volatile("ldmatrix.sync.aligned.m8n8.x4.shared.b16 {%0,%1,%2,%3}, [%4];"
                 : "=r"(r0), "=r"(r1), "=r"(r2), "=r"(r3) : "r"(addr));
}
__device__ __forceinline__ void cp16(void* smem, const void* gmem) {
    uint32_t s = (uint32_t)__cvta_generic_to_shared(smem);
    asm volatile("cp.async.cg.shared.global [%0], [%1], 16;\n" :: "r"(s), "l"(gmem));
}
__device__ __forceinline__ void cp_commit() { asm volatile("cp.async.commit_group;\n"); }
template<int N8>
__device__ __forceinline__ void cp_wait() { asm volatile("cp.async.wait_group %0;\n" :: "n"(N8)); }
__device__ __forceinline__ uint32_t h2u(__half2 h) { return *reinterpret_cast<uint32_t*>(&h); }

// ---------------- prepasses ------------------------------------------------
__global__ __launch_bounds__(256)
void convh_k(const float4* __restrict__ in, uint2* __restrict__ out)
{
    int i = blockIdx.x * 256 + threadIdx.x;
    float4 v = in[i];
    uint2 o;
    o.x = h2u(__floats2half2_rn(v.x, v.y));
    o.y = h2u(__floats2half2_rn(v.z, v.w));
    out[i] = o;
}

__global__ __launch_bounds__(256)
void transh_k(const float* __restrict__ W, __half* __restrict__ WT, int K, int N,
              float alpha)
{
    __shared__ float t[32][33];
    int k0 = blockIdx.y * 32, n0 = blockIdx.x * 32;
    int tx = threadIdx.x & 31, ty = threadIdx.x >> 5;
#pragma unroll
    for (int i = 0; i < 4; i++)
        t[ty + 8 * i][tx] = W[(long)(k0 + ty + 8 * i) * N + n0 + tx];
    __syncthreads();
#pragma unroll
    for (int i = 0; i < 4; i++)
        WT[(long)(n0 + ty + 8 * i) * K + k0 + tx] = __float2half_rn(alpha * t[tx][ty + 8 * i]);
}

// ---------------- fp16 GEMM, 128x128x32, 4-stage cp.async, ldmatrix -------
#define HP    20
#define HSTGW (128*HP)
#define GEMM_SMEMH (4*2*HSTGW*4)

template<bool ACC, bool OUTH>
__global__ __launch_bounds__(256)
void gemm_h(const __half* __restrict__ Ag, const __half* __restrict__ Bt,
            void* __restrict__ Cg, int Kdim, int N, float alpha)
{
    extern __shared__ uint32_t smw[];
    uint32_t* Asb = smw;
    uint32_t* Bsb = smw + 4 * HSTGW;
    const uint32_t abase = (uint32_t)__cvta_generic_to_shared(Asb);
    const uint32_t bbase = (uint32_t)__cvta_generic_to_shared(Bsb);

    const int bx = blockIdx.x, by = blockIdx.y;
    const int tid  = threadIdx.x;
    const int lane = tid & 31;
    const int wid  = tid >> 5;
    const int wm   = wid >> 2;
    const int wn   = wid & 3;
    const int gr   = lane >> 2;
    const int gc   = lane & 3;

    const int rowA0 = by * 128;
    const int colB0 = bx * 128;
    const int niter = Kdim / 32;

    const int lrow  = lane & 15;
    const int lcolw = (lane >> 4) * 4;
    const uint32_t aoff = (uint32_t)(((wm * 64 + lrow) * HP + lcolw) * 4);
    const uint32_t boff = (uint32_t)(((wn * 32 + lrow) * HP + lcolw) * 4);

    const int r0 = tid >> 2,         s0 = (tid & 3);
    const int r1 = (tid + 256) >> 2, s1 = ((tid + 256) & 3);

#pragma unroll
    for (int s = 0; s < 3; s++) {
        int k0 = s * 32;
        uint32_t* As = Asb + s * HSTGW;
        uint32_t* Bs = Bsb + s * HSTGW;
        cp16(&As[r0 * HP + s0 * 4], Ag + (size_t)(rowA0 + r0) * Kdim + k0 + s0 * 8);
        cp16(&As[r1 * HP + s1 * 4], Ag + (size_t)(rowA0 + r1) * Kdim + k0 + s1 * 8);
        cp16(&Bs[r0 * HP + s0 * 4], Bt + (size_t)(colB0 + r0) * Kdim + k0 + s0 * 8);
        cp16(&Bs[r1 * HP + s1 * 4], Bt + (size_t)(colB0 + r1) * Kdim + k0 + s1 * 8);
        cp_commit();
    }

    float acc[16][4];
#pragma unroll
    for (int i = 0; i < 16; i++)
#pragma unroll
        for (int j = 0; j < 4; j++) acc[i][j] = 0.f;

    for (int i = 0; i < niter; i++) {
        cp_wait<2>();
        __syncthreads();

        if (i + 3 < niter) {
            int st = (i + 3) & 3;
            int k0 = (i + 3) * 32;
            uint32_t* As = Asb + st * HSTGW;
            uint32_t* Bs = Bsb + st * HSTGW;
            cp16(&As[r0 * HP + s0 * 4], Ag + (size_t)(rowA0 + r0) * Kdim + k0 + s0 * 8);
            cp16(&As[r1 * HP + s1 * 4], Ag + (size_t)(rowA0 + r1) * Kdim + k0 + s1 * 8);
            cp16(&Bs[r0 * HP + s0 * 4], Bt + (size_t)(colB0 + r0) * Kdim + k0 + s0 * 8);
            cp16(&Bs[r1 * HP + s1 * 4], Bt + (size_t)(colB0 + r1) * Kdim + k0 + s1 * 8);
        }
        cp_commit();

        const uint32_t ast = abase + (uint32_t)((i & 3) * HSTGW * 4);
        const uint32_t bst = bbase + (uint32_t)((i & 3) * HSTGW * 4);

#pragma unroll
        for (int ks = 0; ks < 2; ks++) {
            const int k2 = ks * 8;
            uint32_t a[4][4], bf[4][2];
#pragma unroll
            for (int mt = 0; mt < 4; mt++)
                ldsm4(a[mt][0], a[mt][1], a[mt][2], a[mt][3],
                      ast + aoff + (uint32_t)((mt * 16 * HP + k2) * 4));
#pragma unroll
            for (int p = 0; p < 2; p++) {
                uint32_t q0, q1, q2, q3;
                ldsm4(q0, q1, q2, q3, bst + boff + (uint32_t)((p * 16 * HP + k2) * 4));
                bf[2 * p][0] = q0;     bf[2 * p][1] = q2;
                bf[2 * p + 1][0] = q1; bf[2 * p + 1][1] = q3;
            }
#pragma unroll
            for (int mt = 0; mt < 4; mt++)
#pragma unroll
                for (int nt = 0; nt < 4; nt++)
                    mma_h16(acc[mt * 4 + nt], a[mt], bf[nt]);
        }
    }

#pragma unroll
    for (int mt = 0; mt < 4; mt++) {
        int row = rowA0 + wm * 64 + mt * 16 + gr;
#pragma unroll
        for (int nt = 0; nt < 4; nt++) {
            int col = colB0 + wn * 32 + nt * 8 + gc * 2;
            const float* ac = acc[mt * 4 + nt];
            if (OUTH) {
                __half* C = (__half*)Cg;
                *(uint32_t*)(C + (size_t)row * N + col) =
                    h2u(__floats2half2_rn(alpha * ac[0], alpha * ac[1]));
                *(uint32_t*)(C + (size_t)(row + 8) * N + col) =
                    h2u(__floats2half2_rn(alpha * ac[2], alpha * ac[3]));
            } else {
                float* C = (float*)Cg;
                float* cp0 = C + (size_t)row * N + col;
                float* cp1 = C + (size_t)(row + 8) * N + col;
                float2 rv0 = make_float2(alpha * ac[0], alpha * ac[1]);
                float2 rv1 = make_float2(alpha * ac[2], alpha * ac[3]);
                if (ACC) {
                    float2 o0 = *(const float2*)cp0;
                    float2 o1 = *(const float2*)cp1;
                    rv0.x += o0.x; rv0.y += o0.y;
                    rv1.x += o1.x; rv1.y += o1.y;
                }
                *(float2*)cp0 = rv0;
                *(float2*)cp1 = rv1;
            }
        }
    }
}

// ---------------- fused flash + FLA kernel --------------------------------
// grid 640: blocks [0,128) = FLA (b,kvh,e-tile of 8); [128,640) = flash.
#define QPW 68
#define PPW2 36
#define NFLA 128

struct FlashSmemH {
    uint32_t Qs[128 * QPW];
    uint32_t Kb[2][64 * QPW];
    uint32_t Vb[2][64 * QPW];
    uint32_t Ps[128 * PPW2];
    float red_m[4][128];
    float red_l[4][128];
    float sm_m[128];
    float sm_l[128];
};

struct FlaSmem {
    float ks[8][128];
    float gs[8][128];
    float qs[4][8][128];
    float vs[8][8];
    float os[8][4][8];
};

__device__ __forceinline__ void flash_pfkv(FlashSmemH* sm, int s,
        const __half* __restrict__ K, const __half* __restrict__ V,
        int b, int j, int tid)
{
#pragma unroll
    for (int it = 0; it < 4; it++) {
        int id = tid + it * 256;
        int r = id >> 4, seg = id & 15;
        size_t goff = (size_t)(b * NN + j * 64 + r) * NQKV + seg * 8;
        cp16(&sm->Kb[s][r * QPW + seg * 4], K + goff);
        cp16(&sm->Vb[s][r * QPW + seg * 4], V + goff);
    }
}

__device__ void fla_part(char* smbuf, const __half* Q, const __half* K,
                         const __half* V, float* out, int bid)
{
    FlaSmem* sm = (FlaSmem*)smbuf;
    const int et  = bid & 15;          // e-tile of 8
    const int kvh = (bid >> 4) & 3;
    const int b   = bid >> 6;
    const int e0  = et * 8;
    const int tid = threadIdx.x;
    const int lane = tid & 31;
    const int w    = tid >> 5;         // e_local 0..7

    float s0 = 0.f, s1 = 0.f, s2 = 0.f, s3 = 0.f;
    const float CSC = 0.01f;           // Q pre-scaled by 1/sqrt(D)

    for (int c = 0; c < 256; c++) {
        const int n0 = c * 8;
        // stage q: 1024 float4 -> 4 per thread
#pragma unroll
        for (int i = 0; i < 4; i++) {
            int id = tid + i * 256;
            int hh = id >> 8, t = (id >> 5) & 7, d4 = (id & 31) * 4;
            uint2 raw = *(const uint2*)(Q + (size_t)(b * NN + n0 + t) * NQKV
                                          + (kvh * 4 + hh) * DD + d4);
            float2 f01 = __half22float2(*reinterpret_cast<__half2*>(&raw.x));
            float2 f23 = __half22float2(*reinterpret_cast<__half2*>(&raw.y));
            sm->qs[hh][t][d4 + 0] = f01.x; sm->qs[hh][t][d4 + 1] = f01.y;
            sm->qs[hh][t][d4 + 2] = f23.x; sm->qs[hh][t][d4 + 3] = f23.y;
        }
        {   // stage k + gate: 256 float4
            int t = tid >> 5, d4 = (tid & 31) * 4;
            uint2 raw = *(const uint2*)(K + (size_t)(b * NN + n0 + t) * NQKV
                                          + kvh * DD + d4);
            float2 f01 = __half22float2(*reinterpret_cast<__half2*>(&raw.x));
            float2 f23 = __half22float2(*reinterpret_cast<__half2*>(&raw.y));
            sm->ks[t][d4 + 0] = f01.x; sm->ks[t][d4 + 1] = f01.y;
            sm->ks[t][d4 + 2] = f23.x; sm->ks[t][d4 + 3] = f23.y;
            sm->gs[t][d4 + 0] = 1.f / (1.f + __expf(-f01.x));
            sm->gs[t][d4 + 1] = 1.f / (1.f + __expf(-f01.y));
            sm->gs[t][d4 + 2] = 1.f / (1.f + __expf(-f23.x));
            sm->gs[t][d4 + 3] = 1.f / (1.f + __expf(-f23.y));
        }
        if (tid < 64) {
            int t = tid >> 3, e = tid & 7;
            sm->vs[t][e] = __half2float(V[(size_t)(b * NN + n0 + t) * NQKV
                                          + kvh * DD + e0 + e]);
        }
        __syncthreads();

#pragma unroll
        for (int t = 0; t < 8; t++) {
            const float ve = sm->vs[t][w];
            const float g0 = sm->gs[t][lane],      g1 = sm->gs[t][lane + 32],
                        g2 = sm->gs[t][lane + 64], g3 = sm->gs[t][lane + 96];
            const float k0 = sm->ks[t][lane],      k1 = sm->ks[t][lane + 32],
                        k2 = sm->ks[t][lane + 64], k3 = sm->ks[t][lane + 96];
            s0 = s0 * g0 + k0 * ve;
            s1 = s1 * g1 + k1 * ve;
            s2 = s2 * g2 + k2 * ve;
            s3 = s3 * g3 + k3 * ve;
#pragma unroll
            for (int hh = 0; hh < 4; hh++) {
                float p = sm->qs[hh][t][lane]      * s0
                        + sm->qs[hh][t][lane + 32] * s1
                        + sm->qs[hh][t][lane + 64] * s2
                        + sm->qs[hh][t][lane + 96] * s3;
                p += __shfl_down_sync(0xffffffffu, p, 16);
                p += __shfl_down_sync(0xffffffffu, p, 8);
                p += __shfl_down_sync(0xffffffffu, p, 4);
                p += __shfl_down_sync(0xffffffffu, p, 2);
                p += __shfl_down_sync(0xffffffffu, p, 1);
                if (lane == 0) sm->os[t][hh][w] = p;
            }
        }
        __syncthreads();

        {   // write out: 256 values
            int t = tid >> 5, hh = (tid >> 3) & 3, e = tid & 7;
            out[(size_t)(b * NN + n0 + t) * HIDD + (kvh * 4 + hh) * DD + e0 + e]
                = CSC * sm->os[t][hh][e];
        }
        __syncthreads();
    }
}

__device__ void flash_part(char* smbuf, const __half* Q, const __half* K,
                           const __half* V, __half* AO, int bid2)
{
    FlashSmemH* sm = (FlashSmemH*)smbuf;

    const int bh = bid2 & 31;
    const int b  = bh >> 4, h = bh & 15;
    const int kvh = h >> 2;
    const int qi = 15 - (bid2 >> 5);    // big tiles first

    const int tid  = threadIdx.x;
    const int lane = tid & 31;
    const int wid  = tid >> 5;
    const int wm   = wid >> 2;
    const int wn   = wid & 3;
    const int gr   = lane >> 2;
    const int gc   = lane & 3;

    const int nkv = 2 * qi + 2;
    const float LOG2E = 1.4426950408889634f;

    const __half* Kh = K + (size_t)kvh * DD;
    const __half* Vh = V + (size_t)kvh * DD;

    const int lrow  = lane & 15;
    const int lcolw = (lane >> 4) * 4;
    const uint32_t qfbase = (uint32_t)__cvta_generic_to_shared(sm->Qs)
                          + (uint32_t)(((wm * 64 + lrow) * QPW + lcolw) * 4);
    const uint32_t pfbase = (uint32_t)__cvta_generic_to_shared(sm->Ps)
                          + (uint32_t)(((wm * 64 + lrow) * PPW2 + lcolw) * 4);
    const uint32_t kfoff  = (uint32_t)(((wn * 16 + lrow) * QPW + lcolw) * 4);

#pragma unroll
    for (int it = 0; it < 8; it++) {
        int id = tid + it * 256;
        int r = id >> 4, seg = id & 15;
        cp16(&sm->Qs[r * QPW + seg * 4],
             Q + (size_t)(b * NN + qi * 128 + r) * NQKV + h * DD + seg * 8);
    }
    flash_pfkv(sm, 0, Kh, Vh, b, 0, tid);
    cp_commit();

    if (tid < 128) { sm->sm_m[tid] = -1e30f; sm->sm_l[tid] = 0.f; }

    float acc_o[16][4];
#pragma unroll
    for (int i = 0; i < 16; i++)
#pragma unroll
        for (int j = 0; j < 4; j++) acc_o[i][j] = 0.f;

    for (int j = 0; j < nkv; j++) {
        const int s = j & 1;
        __syncthreads();
        if (j + 1 < nkv)
            flash_pfkv(sm, s ^ 1, Kh, Vh, b, j + 1, tid);
        cp_commit();
        cp_wait<1>();
        __syncthreads();

        const uint32_t kst = (uint32_t)__cvta_generic_to_shared(sm->Kb[s]) + kfoff;

        float acc_s[8][4];
#pragma unroll
        for (int i = 0; i < 8; i++)
#pragma unroll
            for (int c = 0; c < 4; c++) acc_s[i][c] = 0.f;

#pragma unroll
        for (int ks = 0; ks < 8; ks++) {
            const int k2 = ks * 8;
            uint32_t a[4][4], bfr[2][2];
#pragma unroll
            for (int mt = 0; mt < 4; mt++)
                ldsm4(a[mt][0], a[mt][1], a[mt][2], a[mt][3],
                      qfbase + (uint32_t)((mt * 16 * QPW + k2) * 4));
            {
                uint32_t q0, q1, q2, q3;
                ldsm4(q0, q1, q2, q3, kst + (uint32_t)(k2 * 4));
                bfr[0][0] = q0; bfr[0][1] = q2;
                bfr[1][0] = q1; bfr[1][1] = q3;
            }
#pragma unroll
            for (int mt = 0; mt < 4; mt++)
#pragma unroll
                for (int nt = 0; nt < 2; nt++)
                    mma_h16(acc_s[mt * 2 + nt], a[mt], bfr[nt]);
        }

        if ((j + 1) * 64 - 1 > qi * 128) {
#pragma unroll
            for (int mt = 0; mt < 4; mt++)
#pragma unroll
                for (int nt = 0; nt < 2; nt++)
#pragma unroll
                    for (int c = 0; c < 4; c++) {
                        int rowg = qi * 128 + wm * 64 + mt * 16 + gr + (c >> 1) * 8;
                        int colg = j * 64 + wn * 16 + nt * 8 + 2 * gc + (c & 1);
                        if (colg > rowg) acc_s[mt * 2 + nt][c] = -1e30f;
                    }
        }

#pragma unroll
        for (int mt = 0; mt < 4; mt++)
#pragma unroll
            for (int hh = 0; hh < 2; hh++) {
                float rmax = fmaxf(fmaxf(acc_s[mt * 2 + 0][hh * 2], acc_s[mt * 2 + 0][hh * 2 + 1]),
                                   fmaxf(acc_s[mt * 2 + 1][hh * 2], acc_s[mt * 2 + 1][hh * 2 + 1]));
                rmax = fmaxf(rmax, __shfl_xor_sync(0xffffffffu, rmax, 1));
                rmax = fmaxf(rmax, __shfl_xor_sync(0xffffffffu, rmax, 2));
                if (gc == 0)
                    sm->red_m[wn][wm * 64 + mt * 16 + gr + hh * 8] = rmax;
            }
        __syncthreads();

#pragma unroll
        for (int mt = 0; mt < 4; mt++)
#pragma unroll
            for (int hh = 0; hh < 2; hh++) {
                int rl = wm * 64 + mt * 16 + gr + hh * 8;
                float m_old = sm->sm_m[rl];
                float m_new = fmaxf(fmaxf(sm->red_m[0][rl], sm->red_m[1][rl]),
                                    fmaxf(sm->red_m[2][rl], sm->red_m[3][rl]));
                m_new = fmaxf(m_old, m_new);
                float alpha = exp2f((m_old - m_new) * LOG2E);
#pragma unroll
                for (int nt = 0; nt < 4; nt++) {
                    acc_o[mt * 4 + nt][hh * 2]     *= alpha;
                    acc_o[mt * 4 + nt][hh * 2 + 1] *= alpha;
                }
                float psum = 0.f;
#pragma unroll
                for (int nt = 0; nt < 2; nt++) {
                    float p0 = exp2f((acc_s[mt * 2 + nt][hh * 2]     - m_new) * LOG2E);
                    float p1 = exp2f((acc_s[mt * 2 + nt][hh * 2 + 1] - m_new) * LOG2E);
                    psum += p0 + p1;
                    sm->Ps[rl * PPW2 + wn * 8 + nt * 4 + gc] = h2u(__floats2half2_rn(p0, p1));
                }
                psum += __shfl_xor_sync(0xffffffffu, psum, 1);
                psum += __shfl_xor_sync(0xffffffffu, psum, 2);
                if (gc == 0) sm->red_l[wn][rl] = psum;
            }
        __syncthreads();

        if (tid < 128) {
            int rl = tid;
            float m_old = sm->sm_m[rl];
            float m_new = fmaxf(fmaxf(sm->red_m[0][rl], sm->red_m[1][rl]),
                                fmaxf(sm->red_m[2][rl], sm->red_m[3][rl]));
            m_new = fmaxf(m_old, m_new);
            float alpha = exp2f((m_old - m_new) * LOG2E);
            sm->sm_l[rl] = sm->sm_l[rl] * alpha
                         + sm->red_l[0][rl] + sm->red_l[1][rl]
                         + sm->red_l[2][rl] + sm->red_l[3][rl];
            sm->sm_m[rl] = m_new;
        }

        uint32_t vbase = (uint32_t)__cvta_generic_to_shared(&sm->Vb[s][0]);
        const int mrow = lane >> 3, rr = lane & 7;
#pragma unroll
        for (int ks = 0; ks < 4; ks++) {
            const int k2 = ks * 8;
            uint32_t pa[4][4];
#pragma unroll
            for (int mt = 0; mt < 4; mt++)
                ldsm4(pa[mt][0], pa[mt][1], pa[mt][2], pa[mt][3],
                      pfbase + (uint32_t)((mt * 16 * PPW2 + k2) * 4));
#pragma unroll
            for (int np = 0; np < 2; np++) {
                int n0 = wn * 32 + np * 16;
                int token = ks * 16 + (mrow & 1) * 8 + rr;
                int d     = n0 + (mrow >> 1) * 8;
                uint32_t addr = vbase + (uint32_t)(token * QPW + (d >> 1)) * 4;
                uint32_t v0, v1, v2, v3;
                asm volatile(
                    "ldmatrix.sync.aligned.m8n8.x4.trans.shared.b16 {%0,%1,%2,%3}, [%4];"
                    : "=r"(v0), "=r"(v1), "=r"(v2), "=r"(v3) : "r"(addr));
                uint32_t b0[2] = {v0, v1}, b1[2] = {v2, v3};
#pragma unroll
                for (int mt = 0; mt < 4; mt++) {
                    mma_h16(acc_o[mt * 4 + np * 2 + 0], pa[mt], b0);
                    mma_h16(acc_o[mt * 4 + np * 2 + 1], pa[mt], b1);
                }
            }
        }
    }

    __syncthreads();

#pragma unroll
    for (int mt = 0; mt < 4; mt++)
#pragma unroll
        for (int hh = 0; hh < 2; hh++) {
            int rl = wm * 64 + mt * 16 + gr + hh * 8;
            float inv = 1.f / sm->sm_l[rl];
            int gq = qi * 128 + rl;
#pragma unroll
            for (int nt = 0; nt < 4; nt++) {
                int col = wn * 32 + nt * 8 + 2 * gc;
                *(uint32_t*)(AO + (size_t)(b * NN + gq) * DQ + h * DD + col) =
                    h2u(__floats2half2_rn(acc_o[mt * 4 + nt][hh * 2] * inv,
                                          acc_o[mt * 4 + nt][hh * 2 + 1] * inv));
            }
        }
}

__global__ __launch_bounds__(256, 1)
void fused_attn_k(const __half* __restrict__ Q, const __half* __restrict__ K,
                  const __half* __restrict__ V, __half* __restrict__ AO,
                  float* __restrict__ out)
{
    extern __shared__ char smbuf[];
    const int bid = blockIdx.x;
    if (bid < NFLA)
        fla_part(smbuf, Q, K, V, out, bid);
    else
        flash_part(smbuf, Q, K, V, AO, bid - NFLA);
}

// ---------------- launch ---------------------------------------------------
extern "C" void kernel_launch(void* const* d_in, const int* in_sizes, int n_in,
                              void* d_out, int out_size)
{
    const float* hid = (const float*)d_in[0];
    const float* Wq  = (const float*)d_in[1];
    const float* Wk  = (const float*)d_in[2];
    const float* Wv  = (const float*)d_in[3];
    const float* Wo  = (const float*)d_in[4];
    float* outp = (float*)d_out;

    __half *Xh, *QKV, *AOh, *WTa, *WTo;
    cudaGetSymbolAddress((void**)&Xh,  g_Xh);
    cudaGetSymbolAddress((void**)&QKV, g_QKV);
    cudaGetSymbolAddress((void**)&AOh, g_AOh);
    cudaGetSymbolAddress((void**)&WTa, g_WTa);
    cudaGetSymbolAddress((void**)&WTo, g_WTo);

    cudaFuncSetAttribute((const void*)gemm_h<false,true>, cudaFuncAttributeMaxDynamicSharedMemorySize, GEMM_SMEMH);
    cudaFuncSetAttribute((const void*)gemm_h<true,false>, cudaFuncAttributeMaxDynamicSharedMemorySize, GEMM_SMEMH);
    cudaFuncSetAttribute((const void*)fused_attn_k, cudaFuncAttributeMaxDynamicSharedMemorySize,
                         (int)sizeof(FlashSmemH));

    const float scale = 0.08838834764831845f;

    // prepasses
    convh_k<<<(MQ * HIDD) / 4 / 256, 256>>>((const float4*)hid, (uint2*)Xh);
    transh_k<<<dim3(DQ / 32,  HIDD / 32), 256>>>(Wq, WTa,                        HIDD, DQ,  scale);
    transh_k<<<dim3(DKV / 32, HIDD / 32), 256>>>(Wk, WTa + (size_t)DQ * HIDD,    HIDD, DKV, 1.f);
    transh_k<<<dim3(DKV / 32, HIDD / 32), 256>>>(Wv, WTa + (size_t)(DQ + DKV) * HIDD, HIDD, DKV, 1.f);
    transh_k<<<dim3(HIDD / 32, DQ / 32),  256>>>(Wo, WTo, DQ, HIDD, 1.f);

    // fused QKV projection
    gemm_h<false,true><<<dim3(NQKV / 128, MQ / 128), 256, GEMM_SMEMH>>>(
        Xh, WTa, QKV, HIDD, NQKV, 1.f);

    const __half* Qh = QKV;
    const __half* Kh = QKV + DQ;
    const __half* Vh = QKV + DQ + DKV;

    // fused FLA (writes d_out) + flash attention (writes AOh), one launch
    fused_attn_k<<<NFLA + BB * NH * (NN / 128), 256, sizeof(FlashSmemH)>>>(
        Qh, Kh, Vh, AOh, outp);

    // output projection, accumulate onto FLA contribution in d_out
    gemm_h<true,false><<<dim3(HIDD / 128, MQ / 128), 256, GEMM_SMEMH>>>(
        AOh, WTo, outp, DQ, HIDD, 1.f);
}

// round 10
// speedup vs baseline: 3.5174x; 1.0133x over previous
#include <cuda_runtime.h>
#include <cuda_fp16.h>
#include <math.h>
#include <stdint.h>

// Problem constants
#define BB   2
#define NN   2048
#define HIDD 2048
#define NH   16
#define NKV  4
#define DD   128
#define MQ   (BB*NN)        // 4096
#define DQ   (NH*DD)        // 2048
#define DKV  (NKV*DD)       // 512
#define NQKV (DQ + 2*DKV)   // 3072

// ---------------- device scratch ------------------------------------------
__device__ __half g_Xh  [(size_t)MQ * HIDD];
__device__ __half g_QKV [(size_t)MQ * NQKV];
__device__ __half g_AOh [(size_t)MQ * DQ];
__device__ __half g_WTa [(size_t)NQKV * HIDD];
__device__ __half g_WTo [(size_t)HIDD * DQ];
__device__ float  g_FLA [(size_t)MQ * HIDD];   // FLA contribution
__device__ int    g_cntFlash[32];              // per (b,qi) flash completion
__device__ int    g_cntFla;                    // fla blocks done

// ---------------- helpers --------------------------------------------------
__device__ __forceinline__ void mma_h16(float* c, const uint32_t* a, const uint32_t* b) {
    asm volatile(
        "mma.sync.aligned.m16n8k16.row.col.f32.f16.f16.f32 "
        "{%0,%1,%2,%3}, {%4,%5,%6,%7}, {%8,%9}, {%0,%1,%2,%3};\n"
        : "+f"(c[0]), "+f"(c[1]), "+f"(c[2]), "+f"(c[3])
        : "r"(a[0]), "r"(a[1]), "r"(a[2]), "r"(a[3]),
          "r"(b[0]), "r"(b[1]));
}
__device__ __forceinline__ void ldsm4(uint32_t& r0, uint32_t& r1, uint32_t& r2,
                                      uint32_t& r3, uint32_t addr) {
    asm volatile("ldmatrix.sync.aligned.m8n8.x4.shared.b16 {%0,%1,%2,%3}, [%4];"
                 : "=r"(r0), "=r"(r1), "=r"(r2), "=r"(r3) : "r"(addr));
}
__device__ __forceinline__ void cp16(void* smem, const void* gmem) {
    uint32_t s = (uint32_t)__cvta_generic_to_shared(smem);
    asm volatile("cp.async.cg.shared.global [%0], [%1], 16;\n" :: "r"(s), "l"(gmem));
}
__device__ __forceinline__ void cp_commit() { asm volatile("cp.async.commit_group;\n"); }
template<int N8>
__device__ __forceinline__ void cp_wait() { asm volatile("cp.async.wait_group %0;\n" :: "n"(N8)); }
__device__ __forceinline__ uint32_t h2u(__half2 h) { return *reinterpret_cast<uint32_t*>(&h); }

// ---------------- prepasses ------------------------------------------------
__global__ __launch_bounds__(64)
void reset_k()
{
    if (threadIdx.x < 32) g_cntFlash[threadIdx.x] = 0;
    if (threadIdx.x == 32) g_cntFla = 0;
}

__global__ __launch_bounds__(256)
void convh_k(const float4* __restrict__ in, uint2* __restrict__ out)
{
    int i = blockIdx.x * 256 + threadIdx.x;
    float4 v = in[i];
    uint2 o;
    o.x = h2u(__floats2half2_rn(v.x, v.y));
    o.y = h2u(__floats2half2_rn(v.z, v.w));
    out[i] = o;
}

__global__ __launch_bounds__(256)
void transh_k(const float* __restrict__ W, __half* __restrict__ WT, int K, int N,
              float alpha)
{
    __shared__ float t[32][33];
    int k0 = blockIdx.y * 32, n0 = blockIdx.x * 32;
    int tx = threadIdx.x & 31, ty = threadIdx.x >> 5;
#pragma unroll
    for (int i = 0; i < 4; i++)
        t[ty + 8 * i][tx] = W[(long)(k0 + ty + 8 * i) * N + n0 + tx];
    __syncthreads();
#pragma unroll
    for (int i = 0; i < 4; i++)
        WT[(long)(n0 + ty + 8 * i) * K + k0 + tx] = __float2half_rn(alpha * t[tx][ty + 8 * i]);
}

// ---------------- fp16 GEMM (standalone, QKV projection) -------------------
#define HP    20
#define HSTGW (128*HP)
#define GEMM_SMEMH (4*2*HSTGW*4)

__global__ __launch_bounds__(256)
void gemm_h(const __half* __restrict__ Ag, const __half* __restrict__ Bt,
            __half* __restrict__ Cg, int Kdim, int N, float alpha)
{
    extern __shared__ uint32_t smw[];
    uint32_t* Asb = smw;
    uint32_t* Bsb = smw + 4 * HSTGW;
    const uint32_t abase = (uint32_t)__cvta_generic_to_shared(Asb);
    const uint32_t bbase = (uint32_t)__cvta_generic_to_shared(Bsb);

    const int bx = blockIdx.x, by = blockIdx.y;
    const int tid  = threadIdx.x;
    const int lane = tid & 31;
    const int wid  = tid >> 5;
    const int wm   = wid >> 2;
    const int wn   = wid & 3;
    const int gr   = lane >> 2;
    const int gc   = lane & 3;

    const int rowA0 = by * 128;
    const int colB0 = bx * 128;
    const int niter = Kdim / 32;

    const int lrow  = lane & 15;
    const int lcolw = (lane >> 4) * 4;
    const uint32_t aoff = (uint32_t)(((wm * 64 + lrow) * HP + lcolw) * 4);
    const uint32_t boff = (uint32_t)(((wn * 32 + lrow) * HP + lcolw) * 4);

    const int r0 = tid >> 2,         s0 = (tid & 3);
    const int r1 = (tid + 256) >> 2, s1 = ((tid + 256) & 3);

#pragma unroll
    for (int s = 0; s < 3; s++) {
        int k0 = s * 32;
        uint32_t* As = Asb + s * HSTGW;
        uint32_t* Bs = Bsb + s * HSTGW;
        cp16(&As[r0 * HP + s0 * 4], Ag + (size_t)(rowA0 + r0) * Kdim + k0 + s0 * 8);
        cp16(&As[r1 * HP + s1 * 4], Ag + (size_t)(rowA0 + r1) * Kdim + k0 + s1 * 8);
        cp16(&Bs[r0 * HP + s0 * 4], Bt + (size_t)(colB0 + r0) * Kdim + k0 + s0 * 8);
        cp16(&Bs[r1 * HP + s1 * 4], Bt + (size_t)(colB0 + r1) * Kdim + k0 + s1 * 8);
        cp_commit();
    }

    float acc[16][4];
#pragma unroll
    for (int i = 0; i < 16; i++)
#pragma unroll
        for (int j = 0; j < 4; j++) acc[i][j] = 0.f;

    for (int i = 0; i < niter; i++) {
        cp_wait<2>();
        __syncthreads();
        if (i + 3 < niter) {
            int st = (i + 3) & 3;
            int k0 = (i + 3) * 32;
            uint32_t* As = Asb + st * HSTGW;
            uint32_t* Bs = Bsb + st * HSTGW;
            cp16(&As[r0 * HP + s0 * 4], Ag + (size_t)(rowA0 + r0) * Kdim + k0 + s0 * 8);
            cp16(&As[r1 * HP + s1 * 4], Ag + (size_t)(rowA0 + r1) * Kdim + k0 + s1 * 8);
            cp16(&Bs[r0 * HP + s0 * 4], Bt + (size_t)(colB0 + r0) * Kdim + k0 + s0 * 8);
            cp16(&Bs[r1 * HP + s1 * 4], Bt + (size_t)(colB0 + r1) * Kdim + k0 + s1 * 8);
        }
        cp_commit();

        const uint32_t ast = abase + (uint32_t)((i & 3) * HSTGW * 4);
        const uint32_t bst = bbase + (uint32_t)((i & 3) * HSTGW * 4);

#pragma unroll
        for (int ks = 0; ks < 2; ks++) {
            const int k2 = ks * 8;
            uint32_t a[4][4], bf[4][2];
#pragma unroll
            for (int mt = 0; mt < 4; mt++)
                ldsm4(a[mt][0], a[mt][1], a[mt][2], a[mt][3],
                      ast + aoff + (uint32_t)((mt * 16 * HP + k2) * 4));
#pragma unroll
            for (int p = 0; p < 2; p++) {
                uint32_t q0, q1, q2, q3;
                ldsm4(q0, q1, q2, q3, bst + boff + (uint32_t)((p * 16 * HP + k2) * 4));
                bf[2 * p][0] = q0;     bf[2 * p][1] = q2;
                bf[2 * p + 1][0] = q1; bf[2 * p + 1][1] = q3;
            }
#pragma unroll
            for (int mt = 0; mt < 4; mt++)
#pragma unroll
                for (int nt = 0; nt < 4; nt++)
                    mma_h16(acc[mt * 4 + nt], a[mt], bf[nt]);
        }
    }

#pragma unroll
    for (int mt = 0; mt < 4; mt++) {
        int row = rowA0 + wm * 64 + mt * 16 + gr;
#pragma unroll
        for (int nt = 0; nt < 4; nt++) {
            int col = colB0 + wn * 32 + nt * 8 + gc * 2;
            const float* ac = acc[mt * 4 + nt];
            *(uint32_t*)(Cg + (size_t)row * N + col) =
                h2u(__floats2half2_rn(alpha * ac[0], alpha * ac[1]));
            *(uint32_t*)(Cg + (size_t)(row + 8) * N + col) =
                h2u(__floats2half2_rn(alpha * ac[2], alpha * ac[3]));
        }
    }
}

// ---------------- fused attn + Wo kernel ----------------------------------
// grid 1152: [0,128) FLA; [128,640) flash; [640,1152) Wo (dep-spun)
#define QPW 68
#define PPW2 36
#define NFLA 128
#define NFLASH 512

struct FlashSmemH {
    uint32_t Qs[128 * QPW];
    uint32_t Kb[2][64 * QPW];
    uint32_t Vb[2][64 * QPW];
    uint32_t Ps[128 * PPW2];
    float red_m[4][128];
    float red_l[4][128];
    float sm_m[128];
    float sm_l[128];
};

struct FlaSmem {
    float ks[8][128];
    float gs[8][128];
    float qs[4][8][128];
    float vs[8][8];
    float os[8][4][8];
};

__device__ __forceinline__ void flash_pfkv(FlashSmemH* sm, int s,
        const __half* __restrict__ K, const __half* __restrict__ V,
        int b, int j, int tid)
{
#pragma unroll
    for (int it = 0; it < 4; it++) {
        int id = tid + it * 256;
        int r = id >> 4, seg = id & 15;
        size_t goff = (size_t)(b * NN + j * 64 + r) * NQKV + seg * 8;
        cp16(&sm->Kb[s][r * QPW + seg * 4], K + goff);
        cp16(&sm->Vb[s][r * QPW + seg * 4], V + goff);
    }
}

__device__ void fla_part(char* smbuf, const __half* Q, const __half* K,
                         const __half* V, int bid)
{
    FlaSmem* sm = (FlaSmem*)smbuf;
    const int et  = bid & 15;
    const int kvh = (bid >> 4) & 3;
    const int b   = bid >> 6;
    const int e0  = et * 8;
    const int tid = threadIdx.x;
    const int lane = tid & 31;
    const int w    = tid >> 5;

    float s0 = 0.f, s1 = 0.f, s2 = 0.f, s3 = 0.f;
    const float CSC = 0.01f;

    for (int c = 0; c < 256; c++) {
        const int n0 = c * 8;
#pragma unroll
        for (int i = 0; i < 4; i++) {
            int id = tid + i * 256;
            int hh = id >> 8, t = (id >> 5) & 7, d4 = (id & 31) * 4;
            uint2 raw = *(const uint2*)(Q + (size_t)(b * NN + n0 + t) * NQKV
                                          + (kvh * 4 + hh) * DD + d4);
            float2 f01 = __half22float2(*reinterpret_cast<__half2*>(&raw.x));
            float2 f23 = __half22float2(*reinterpret_cast<__half2*>(&raw.y));
            sm->qs[hh][t][d4 + 0] = f01.x; sm->qs[hh][t][d4 + 1] = f01.y;
            sm->qs[hh][t][d4 + 2] = f23.x; sm->qs[hh][t][d4 + 3] = f23.y;
        }
        {
            int t = tid >> 5, d4 = (tid & 31) * 4;
            uint2 raw = *(const uint2*)(K + (size_t)(b * NN + n0 + t) * NQKV
                                          + kvh * DD + d4);
            float2 f01 = __half22float2(*reinterpret_cast<__half2*>(&raw.x));
            float2 f23 = __half22float2(*reinterpret_cast<__half2*>(&raw.y));
            sm->ks[t][d4 + 0] = f01.x; sm->ks[t][d4 + 1] = f01.y;
            sm->ks[t][d4 + 2] = f23.x; sm->ks[t][d4 + 3] = f23.y;
            sm->gs[t][d4 + 0] = 1.f / (1.f + __expf(-f01.x));
            sm->gs[t][d4 + 1] = 1.f / (1.f + __expf(-f01.y));
            sm->gs[t][d4 + 2] = 1.f / (1.f + __expf(-f23.x));
            sm->gs[t][d4 + 3] = 1.f / (1.f + __expf(-f23.y));
        }
        if (tid < 64) {
            int t = tid >> 3, e = tid & 7;
            sm->vs[t][e] = __half2float(V[(size_t)(b * NN + n0 + t) * NQKV
                                          + kvh * DD + e0 + e]);
        }
        __syncthreads();

#pragma unroll
        for (int t = 0; t < 8; t++) {
            const float ve = sm->vs[t][w];
            const float g0 = sm->gs[t][lane],      g1 = sm->gs[t][lane + 32],
                        g2 = sm->gs[t][lane + 64], g3 = sm->gs[t][lane + 96];
            const float k0 = sm->ks[t][lane],      k1 = sm->ks[t][lane + 32],
                        k2 = sm->ks[t][lane + 64], k3 = sm->ks[t][lane + 96];
            s0 = s0 * g0 + k0 * ve;
            s1 = s1 * g1 + k1 * ve;
            s2 = s2 * g2 + k2 * ve;
            s3 = s3 * g3 + k3 * ve;
#pragma unroll
            for (int hh = 0; hh < 4; hh++) {
                float p = sm->qs[hh][t][lane]      * s0
                        + sm->qs[hh][t][lane + 32] * s1
                        + sm->qs[hh][t][lane + 64] * s2
                        + sm->qs[hh][t][lane + 96] * s3;
                p += __shfl_down_sync(0xffffffffu, p, 16);
                p += __shfl_down_sync(0xffffffffu, p, 8);
                p += __shfl_down_sync(0xffffffffu, p, 4);
                p += __shfl_down_sync(0xffffffffu, p, 2);
                p += __shfl_down_sync(0xffffffffu, p, 1);
                if (lane == 0) sm->os[t][hh][w] = p;
            }
        }
        __syncthreads();

        {
            int t = tid >> 5, hh = (tid >> 3) & 3, e = tid & 7;
            g_FLA[(size_t)(b * NN + n0 + t) * HIDD + (kvh * 4 + hh) * DD + e0 + e]
                = CSC * sm->os[t][hh][e];
        }
        __syncthreads();
    }

    if (tid == 0) { __threadfence(); atomicAdd(&g_cntFla, 1); }
}

__device__ void flash_part(char* smbuf, const __half* Q, const __half* K,
                           const __half* V, __half* AO, int bid2)
{
    FlashSmemH* sm = (FlashSmemH*)smbuf;

    const int bh = bid2 & 31;
    const int b  = bh >> 4, h = bh & 15;
    const int kvh = h >> 2;
    const int qi = 15 - (bid2 >> 5);

    const int tid  = threadIdx.x;
    const int lane = tid & 31;
    const int wid  = tid >> 5;
    const int wm   = wid >> 2;
    const int wn   = wid & 3;
    const int gr   = lane >> 2;
    const int gc   = lane & 3;

    const int nkv = 2 * qi + 2;
    const float LOG2E = 1.4426950408889634f;

    const __half* Kh = K + (size_t)kvh * DD;
    const __half* Vh = V + (size_t)kvh * DD;

    const int lrow  = lane & 15;
    const int lcolw = (lane >> 4) * 4;
    const uint32_t qfbase = (uint32_t)__cvta_generic_to_shared(sm->Qs)
                          + (uint32_t)(((wm * 64 + lrow) * QPW + lcolw) * 4);
    const uint32_t pfbase = (uint32_t)__cvta_generic_to_shared(sm->Ps)
                          + (uint32_t)(((wm * 64 + lrow) * PPW2 + lcolw) * 4);
    const uint32_t kfoff  = (uint32_t)(((wn * 16 + lrow) * QPW + lcolw) * 4);

#pragma unroll
    for (int it = 0; it < 8; it++) {
        int id = tid + it * 256;
        int r = id >> 4, seg = id & 15;
        cp16(&sm->Qs[r * QPW + seg * 4],
             Q + (size_t)(b * NN + qi * 128 + r) * NQKV + h * DD + seg * 8);
    }
    flash_pfkv(sm, 0, Kh, Vh, b, 0, tid);
    cp_commit();

    if (tid < 128) { sm->sm_m[tid] = -1e30f; sm->sm_l[tid] = 0.f; }

    float acc_o[16][4];
#pragma unroll
    for (int i = 0; i < 16; i++)
#pragma unroll
        for (int j = 0; j < 4; j++) acc_o[i][j] = 0.f;

    for (int j = 0; j < nkv; j++) {
        const int s = j & 1;
        __syncthreads();
        if (j + 1 < nkv)
            flash_pfkv(sm, s ^ 1, Kh, Vh, b, j + 1, tid);
        cp_commit();
        cp_wait<1>();
        __syncthreads();

        const uint32_t kst = (uint32_t)__cvta_generic_to_shared(sm->Kb[s]) + kfoff;

        float acc_s[8][4];
#pragma unroll
        for (int i = 0; i < 8; i++)
#pragma unroll
            for (int c = 0; c < 4; c++) acc_s[i][c] = 0.f;

#pragma unroll
        for (int ks = 0; ks < 8; ks++) {
            const int k2 = ks * 8;
            uint32_t a[4][4], bfr[2][2];
#pragma unroll
            for (int mt = 0; mt < 4; mt++)
                ldsm4(a[mt][0], a[mt][1], a[mt][2], a[mt][3],
                      qfbase + (uint32_t)((mt * 16 * QPW + k2) * 4));
            {
                uint32_t q0, q1, q2, q3;
                ldsm4(q0, q1, q2, q3, kst + (uint32_t)(k2 * 4));
                bfr[0][0] = q0; bfr[0][1] = q2;
                bfr[1][0] = q1; bfr[1][1] = q3;
            }
#pragma unroll
            for (int mt = 0; mt < 4; mt++)
#pragma unroll
                for (int nt = 0; nt < 2; nt++)
                    mma_h16(acc_s[mt * 2 + nt], a[mt], bfr[nt]);
        }

        if ((j + 1) * 64 - 1 > qi * 128) {
#pragma unroll
            for (int mt = 0; mt < 4; mt++)
#pragma unroll
                for (int nt = 0; nt < 2; nt++)
#pragma unroll
                    for (int c = 0; c < 4; c++) {
                        int rowg = qi * 128 + wm * 64 + mt * 16 + gr + (c >> 1) * 8;
                        int colg = j * 64 + wn * 16 + nt * 8 + 2 * gc + (c & 1);
                        if (colg > rowg) acc_s[mt * 2 + nt][c] = -1e30f;
                    }
        }

#pragma unroll
        for (int mt = 0; mt < 4; mt++)
#pragma unroll
            for (int hh = 0; hh < 2; hh++) {
                float rmax = fmaxf(fmaxf(acc_s[mt * 2 + 0][hh * 2], acc_s[mt * 2 + 0][hh * 2 + 1]),
                                   fmaxf(acc_s[mt * 2 + 1][hh * 2], acc_s[mt * 2 + 1][hh * 2 + 1]));
                rmax = fmaxf(rmax, __shfl_xor_sync(0xffffffffu, rmax, 1));
                rmax = fmaxf(rmax, __shfl_xor_sync(0xffffffffu, rmax, 2));
                if (gc == 0)
                    sm->red_m[wn][wm * 64 + mt * 16 + gr + hh * 8] = rmax;
            }
        __syncthreads();

#pragma unroll
        for (int mt = 0; mt < 4; mt++)
#pragma unroll
            for (int hh = 0; hh < 2; hh++) {
                int rl = wm * 64 + mt * 16 + gr + hh * 8;
                float m_old = sm->sm_m[rl];
                float m_new = fmaxf(fmaxf(sm->red_m[0][rl], sm->red_m[1][rl]),
                                    fmaxf(sm->red_m[2][rl], sm->red_m[3][rl]));
                m_new = fmaxf(m_old, m_new);
                float alpha = exp2f((m_old - m_new) * LOG2E);
#pragma unroll
                for (int nt = 0; nt < 4; nt++) {
                    acc_o[mt * 4 + nt][hh * 2]     *= alpha;
                    acc_o[mt * 4 + nt][hh * 2 + 1] *= alpha;
                }
                float psum = 0.f;
#pragma unroll
                for (int nt = 0; nt < 2; nt++) {
                    float p0 = exp2f((acc_s[mt * 2 + nt][hh * 2]     - m_new) * LOG2E);
                    float p1 = exp2f((acc_s[mt * 2 + nt][hh * 2 + 1] - m_new) * LOG2E);
                    psum += p0 + p1;
                    sm->Ps[rl * PPW2 + wn * 8 + nt * 4 + gc] = h2u(__floats2half2_rn(p0, p1));
                }
                psum += __shfl_xor_sync(0xffffffffu, psum, 1);
                psum += __shfl_xor_sync(0xffffffffu, psum, 2);
                if (gc == 0) sm->red_l[wn][rl] = psum;
            }
        __syncthreads();

        if (tid < 128) {
            int rl = tid;
            float m_old = sm->sm_m[rl];
            float m_new = fmaxf(fmaxf(sm->red_m[0][rl], sm->red_m[1][rl]),
                                fmaxf(sm->red_m[2][rl], sm->red_m[3][rl]));
            m_new = fmaxf(m_old, m_new);
            float alpha = exp2f((m_old - m_new) * LOG2E);
            sm->sm_l[rl] = sm->sm_l[rl] * alpha
                         + sm->red_l[0][rl] + sm->red_l[1][rl]
                         + sm->red_l[2][rl] + sm->red_l[3][rl];
            sm->sm_m[rl] = m_new;
        }

        uint32_t vbase = (uint32_t)__cvta_generic_to_shared(&sm->Vb[s][0]);
        const int mrow = lane >> 3, rr = lane & 7;
#pragma unroll
        for (int ks = 0; ks < 4; ks++) {
            const int k2 = ks * 8;
            uint32_t pa[4][4];
#pragma unroll
            for (int mt = 0; mt < 4; mt++)
                ldsm4(pa[mt][0], pa[mt][1], pa[mt][2], pa[mt][3],
                      pfbase + (uint32_t)((mt * 16 * PPW2 + k2) * 4));
#pragma unroll
            for (int np = 0; np < 2; np++) {
                int n0 = wn * 32 + np * 16;
                int token = ks * 16 + (mrow & 1) * 8 + rr;
                int d     = n0 + (mrow >> 1) * 8;
                uint32_t addr = vbase + (uint32_t)(token * QPW + (d >> 1)) * 4;
                uint32_t v0, v1, v2, v3;
                asm volatile(
                    "ldmatrix.sync.aligned.m8n8.x4.trans.shared.b16 {%0,%1,%2,%3}, [%4];"
                    : "=r"(v0), "=r"(v1), "=r"(v2), "=r"(v3) : "r"(addr));
                uint32_t b0[2] = {v0, v1}, b1[2] = {v2, v3};
#pragma unroll
                for (int mt = 0; mt < 4; mt++) {
                    mma_h16(acc_o[mt * 4 + np * 2 + 0], pa[mt], b0);
                    mma_h16(acc_o[mt * 4 + np * 2 + 1], pa[mt], b1);
                }
            }
        }
    }

    __syncthreads();

#pragma unroll
    for (int mt = 0; mt < 4; mt++)
#pragma unroll
        for (int hh = 0; hh < 2; hh++) {
            int rl = wm * 64 + mt * 16 + gr + hh * 8;
            float inv = 1.f / sm->sm_l[rl];
            int gq = qi * 128 + rl;
#pragma unroll
            for (int nt = 0; nt < 4; nt++) {
                int col = wn * 32 + nt * 8 + 2 * gc;
                *(uint32_t*)(AO + (size_t)(b * NN + gq) * DQ + h * DD + col) =
                    h2u(__floats2half2_rn(acc_o[mt * 4 + nt][hh * 2] * inv,
                                          acc_o[mt * 4 + nt][hh * 2 + 1] * inv));
            }
        }

    __syncthreads();
    if (tid == 0) { __threadfence(); atomicAdd(&g_cntFlash[b * 16 + qi], 1); }
}

// Wo tile GEMM with spin dependencies: out = AO @ WTo^T + FLA
__device__ void wo_part(char* smbuf, const __half* __restrict__ Ag,
                        const __half* __restrict__ Bt,
                        float* __restrict__ outp, int bid3)
{
    const int rt = bid3 >> 4;      // 0..31 : (b,qi), qi ascending
    const int ct = bid3 & 15;
    const int b  = rt & 1, qi = rt >> 1;

    const int tid  = threadIdx.x;

    if (tid == 0) {
        while (atomicAdd(&g_cntFlash[b * 16 + qi], 0) < 16) __nanosleep(256);
    }
    __syncthreads();
    __threadfence();

    uint32_t* smw = (uint32_t*)smbuf;
    uint32_t* Asb = smw;
    uint32_t* Bsb = smw + 4 * HSTGW;
    const uint32_t abase = (uint32_t)__cvta_generic_to_shared(Asb);
    const uint32_t bbase = (uint32_t)__cvta_generic_to_shared(Bsb);

    const int lane = tid & 31;
    const int wid  = tid >> 5;
    const int wm   = wid >> 2;
    const int wn   = wid & 3;
    const int gr   = lane >> 2;
    const int gc   = lane & 3;

    const int Kdim = DQ;           // 2048
    const int rowA0 = (b * NN + qi * 128);
    const int colB0 = ct * 128;
    const int niter = Kdim / 32;   // 64

    const int lrow  = lane & 15;
    const int lcolw = (lane >> 4) * 4;
    const uint32_t aoff = (uint32_t)(((wm * 64 + lrow) * HP + lcolw) * 4);
    const uint32_t boff = (uint32_t)(((wn * 32 + lrow) * HP + lcolw) * 4);

    const int r0 = tid >> 2,         s0 = (tid & 3);
    const int r1 = (tid + 256) >> 2, s1 = ((tid + 256) & 3);

#pragma unroll
    for (int s = 0; s < 3; s++) {
        int k0 = s * 32;
        uint32_t* As = Asb + s * HSTGW;
        uint32_t* Bs = Bsb + s * HSTGW;
        cp16(&As[r0 * HP + s0 * 4], Ag + (size_t)(rowA0 + r0) * Kdim + k0 + s0 * 8);
        cp16(&As[r1 * HP + s1 * 4], Ag + (size_t)(rowA0 + r1) * Kdim + k0 + s1 * 8);
        cp16(&Bs[r0 * HP + s0 * 4], Bt + (size_t)(colB0 + r0) * Kdim + k0 + s0 * 8);
        cp16(&Bs[r1 * HP + s1 * 4], Bt + (size_t)(colB0 + r1) * Kdim + k0 + s1 * 8);
        cp_commit();
    }

    float acc[16][4];
#pragma unroll
    for (int i = 0; i < 16; i++)
#pragma unroll
        for (int j = 0; j < 4; j++) acc[i][j] = 0.f;

    for (int i = 0; i < niter; i++) {
        cp_wait<2>();
        __syncthreads();
        if (i + 3 < niter) {
            int st = (i + 3) & 3;
            int k0 = (i + 3) * 32;
            uint32_t* As = Asb + st * HSTGW;
            uint32_t* Bs = Bsb + st * HSTGW;
            cp16(&As[r0 * HP + s0 * 4], Ag + (size_t)(rowA0 + r0) * Kdim + k0 + s0 * 8);
            cp16(&As[r1 * HP + s1 * 4], Ag + (size_t)(rowA0 + r1) * Kdim + k0 + s1 * 8);
            cp16(&Bs[r0 * HP + s0 * 4], Bt + (size_t)(colB0 + r0) * Kdim + k0 + s0 * 8);
            cp16(&Bs[r1 * HP + s1 * 4], Bt + (size_t)(colB0 + r1) * Kdim + k0 + s1 * 8);
        }
        cp_commit();

        const uint32_t ast = abase + (uint32_t)((i & 3) * HSTGW * 4);
        const uint32_t bst = bbase + (uint32_t)((i & 3) * HSTGW * 4);

#pragma unroll
        for (int ks = 0; ks < 2; ks++) {
            const int k2 = ks * 8;
            uint32_t a[4][4], bf[4][2];
#pragma unroll
            for (int mt = 0; mt < 4; mt++)
                ldsm4(a[mt][0], a[mt][1], a[mt][2], a[mt][3],
                      ast + aoff + (uint32_t)((mt * 16 * HP + k2) * 4));
#pragma unroll
            for (int p = 0; p < 2; p++) {
                uint32_t q0, q1, q2, q3;
                ldsm4(q0, q1, q2, q3, bst + boff + (uint32_t)((p * 16 * HP + k2) * 4));
                bf[2 * p][0] = q0;     bf[2 * p][1] = q2;
                bf[2 * p + 1][0] = q1; bf[2 * p + 1][1] = q3;
            }
#pragma unroll
            for (int mt = 0; mt < 4; mt++)
#pragma unroll
                for (int nt = 0; nt < 4; nt++)
                    mma_h16(acc[mt * 4 + nt], a[mt], bf[nt]);
        }
    }

    // wait for FLA contribution before the accumulate-epilogue
    if (tid == 0) {
        while (atomicAdd(&g_cntFla, 0) < NFLA) __nanosleep(256);
    }
    __syncthreads();
    __threadfence();

#pragma unroll
    for (int mt = 0; mt < 4; mt++) {
        int row = rowA0 + wm * 64 + mt * 16 + gr;
#pragma unroll
        for (int nt = 0; nt < 4; nt++) {
            int col = colB0 + wn * 32 + nt * 8 + gc * 2;
            const float* ac = acc[mt * 4 + nt];
            const float* f0 = g_FLA + (size_t)row * HIDD + col;
            const float* f1 = g_FLA + (size_t)(row + 8) * HIDD + col;
            float2 rv0 = make_float2(ac[0] + f0[0], ac[1] + f0[1]);
            float2 rv1 = make_float2(ac[2] + f1[0], ac[3] + f1[1]);
            *(float2*)(outp + (size_t)row * HIDD + col) = rv0;
            *(float2*)(outp + (size_t)(row + 8) * HIDD + col) = rv1;
        }
    }
}

__global__ __launch_bounds__(256, 1)
void fused_all_k(const __half* __restrict__ Q, const __half* __restrict__ K,
                 const __half* __restrict__ V, __half* __restrict__ AO,
                 const __half* __restrict__ WTo, float* __restrict__ out)
{
    extern __shared__ char smbuf[];
    const int bid = blockIdx.x;
    if (bid < NFLA)
        fla_part(smbuf, Q, K, V, bid);
    else if (bid < NFLA + NFLASH)
        flash_part(smbuf, Q, K, V, AO, bid - NFLA);
    else
        wo_part(smbuf, AO, WTo, out, bid - NFLA - NFLASH);
}

// ---------------- launch ---------------------------------------------------
extern "C" void kernel_launch(void* const* d_in, const int* in_sizes, int n_in,
                              void* d_out, int out_size)
{
    const float* hid = (const float*)d_in[0];
    const float* Wq  = (const float*)d_in[1];
    const float* Wk  = (const float*)d_in[2];
    const float* Wv  = (const float*)d_in[3];
    const float* Wo  = (const float*)d_in[4];
    float* outp = (float*)d_out;

    __half *Xh, *QKV, *AOh, *WTa, *WTo;
    cudaGetSymbolAddress((void**)&Xh,  g_Xh);
    cudaGetSymbolAddress((void**)&QKV, g_QKV);
    cudaGetSymbolAddress((void**)&AOh, g_AOh);
    cudaGetSymbolAddress((void**)&WTa, g_WTa);
    cudaGetSymbolAddress((void**)&WTo, g_WTo);

    cudaFuncSetAttribute((const void*)gemm_h, cudaFuncAttributeMaxDynamicSharedMemorySize, GEMM_SMEMH);
    cudaFuncSetAttribute((const void*)fused_all_k, cudaFuncAttributeMaxDynamicSharedMemorySize,
                         (int)sizeof(FlashSmemH));

    const float scale = 0.08838834764831845f;

    // reset dependency counters (fresh every call / graph replay)
    reset_k<<<1, 64>>>();

    // prepasses
    convh_k<<<(MQ * HIDD) / 4 / 256, 256>>>((const float4*)hid, (uint2*)Xh);
    transh_k<<<dim3(DQ / 32,  HIDD / 32), 256>>>(Wq, WTa,                        HIDD, DQ,  scale);
    transh_k<<<dim3(DKV / 32, HIDD / 32), 256>>>(Wk, WTa + (size_t)DQ * HIDD,    HIDD, DKV, 1.f);
    transh_k<<<dim3(DKV / 32, HIDD / 32), 256>>>(Wv, WTa + (size_t)(DQ + DKV) * HIDD, HIDD, DKV, 1.f);
    transh_k<<<dim3(HIDD / 32, DQ / 32),  256>>>(Wo, WTo, DQ, HIDD, 1.f);

    // fused QKV projection
    gemm_h<<<dim3(NQKV / 128, MQ / 128), 256, GEMM_SMEMH>>>(
        Xh, WTa, QKV, HIDD, NQKV, 1.f);

    const __half* Qh = QKV;
    const __half* Kh = QKV + DQ;
    const __half* Vh = QKV + DQ + DKV;

    // FLA + flash + dependency-spun Wo, one launch
    fused_all_k<<<NFLA + NFLASH + 512, 256, sizeof(FlashSmemH)>>>(
        Qh, Kh, Vh, AOh, WTo, outp);
}